// round 12
// baseline (speedup 1.0000x reference)
#include <cuda_runtime.h>
#include <cuda_bf16.h>
#include <math.h>
#include <stdint.h>

#define D_MODEL 2048
#define N_HEADS 16
#define D_CQ    1536
#define D_C     512
#define D_H     128
#define D_R     64
#define BSZ     4
#define SEQ     2048
#define NTOK    (BSZ*SEQ)
#define D_QK    (D_H + D_R)
#define LL long long

#define SW128(o) ((o) ^ (((o) >> 3) & 0x70))
#define SW64(o)  ((o) ^ (((o) >> 2) & 0x30))

#define N1 2176   // merged first-GEMM N: Wqd(1536) | Wkv(512) | Wkr(64) | pad(64)

typedef __nv_bfloat16 bf16;

// ---------------- scratch ----------------
__device__ float g_tmp12[(LL)NTOK * N1];
__device__ float g_qCR [(LL)NTOK * 3072];
__device__ float g_kvC [(LL)NTOK * 4096];
__device__ float g_krn [(LL)NTOK * D_R];
__device__ bf16 g_h_hi[(LL)NTOK * D_MODEL],      g_h_lo[(LL)NTOK * D_MODEL];
__device__ bf16 g_WdT_hi[(LL)N1 * D_MODEL],      g_WdT_lo[(LL)N1 * D_MODEL];
__device__ bf16 g_WqcrT_hi[(LL)3072 * D_CQ],     g_WqcrT_lo[(LL)3072 * D_CQ];
__device__ bf16 g_WkvcT_hi[(LL)4096 * D_C],      g_WkvcT_lo[(LL)4096 * D_C];
__device__ bf16 g_WoT_hi[(LL)2048 * 2048],       g_WoT_lo[(LL)2048 * 2048];
__device__ bf16 g_cQ_hi[(LL)NTOK * D_CQ],        g_cQ_lo[(LL)NTOK * D_CQ];
__device__ bf16 g_cKV_hi[(LL)NTOK * D_C],        g_cKV_lo[(LL)NTOK * D_C];
__device__ bf16 g_qf_hi[(LL)NTOK * N_HEADS*D_QK], g_qf_lo[(LL)NTOK * N_HEADS*D_QK];
__device__ bf16 g_kf_hi[(LL)NTOK * N_HEADS*D_QK], g_kf_lo[(LL)NTOK * N_HEADS*D_QK];
__device__ bf16 g_vCT_hi[(LL)2048 * NTOK],       g_vCT_lo[(LL)2048 * NTOK];
__device__ bf16 g_attn_hi[(LL)NTOK * 2048],      g_attn_lo[(LL)NTOK * 2048];
__device__ float g_bias1[N1];
__device__ float g_bias2[3072];
__device__ float g_bias3[4096];

// ---------------- helpers ----------------
__device__ __forceinline__ uint32_t smem_u32(const void* p) {
    uint32_t a;
    asm("{ .reg .u64 t; cvta.to.shared.u64 t, %1; cvt.u32.u64 %0, t; }" : "=r"(a) : "l"(p));
    return a;
}
#define CP16(d, s) asm volatile("cp.async.cg.shared.global [%0], [%1], 16;" :: "r"(d), "l"(s))
#define CP_COMMIT() asm volatile("cp.async.commit_group;" ::: "memory")
#define CP_WAIT1() asm volatile("cp.async.wait_group 1;" ::: "memory")
#define CP_WAIT0() asm volatile("cp.async.wait_group 0;" ::: "memory")

__device__ __forceinline__ void ldsm_x4(uint32_t addr, uint32_t& r0, uint32_t& r1,
                                        uint32_t& r2, uint32_t& r3) {
    asm volatile("ldmatrix.sync.aligned.m8n8.x4.shared.b16 {%0,%1,%2,%3}, [%4];"
                 : "=r"(r0), "=r"(r1), "=r"(r2), "=r"(r3) : "r"(addr));
}
__device__ __forceinline__ void mma_bf16(float* c, const uint32_t* a,
                                         uint32_t b0, uint32_t b1) {
    asm volatile(
        "mma.sync.aligned.m16n8k16.row.col.f32.bf16.bf16.f32 "
        "{%0,%1,%2,%3}, {%4,%5,%6,%7}, {%8,%9}, {%0,%1,%2,%3};"
        : "+f"(c[0]), "+f"(c[1]), "+f"(c[2]), "+f"(c[3])
        : "r"(a[0]), "r"(a[1]), "r"(a[2]), "r"(a[3]), "r"(b0), "r"(b1));
}
__device__ __forceinline__ void splitw(float v, bf16& hi, bf16& lo) {
    hi = __float2bfloat16(v);
    lo = __float2bfloat16(v - __bfloat162float(hi));
}
__device__ __forceinline__ void split2pack(float f0, float f1, uint32_t& hp, uint32_t& lp) {
    bf16 h0, l0, h1, l1;
    splitw(f0, h0, l0); splitw(f1, h1, l1);
    hp = ((uint32_t)__bfloat16_as_ushort(h1) << 16) | __bfloat16_as_ushort(h0);
    lp = ((uint32_t)__bfloat16_as_ushort(l1) << 16) | __bfloat16_as_ushort(l0);
}

// ============ bf16x3 GEMM: 256x128 tile, 512 threads, BK=64, 2-stage ============
template<int EPI, bool KCLIP>
__global__ __launch_bounds__(512, 1)
void gemm512(const bf16* __restrict__ Ahi, const bf16* __restrict__ Alo,
             const bf16* __restrict__ Bhi, const bf16* __restrict__ Blo,
             const float* __restrict__ bias,
             float* __restrict__ C, bf16* __restrict__ Chi, bf16* __restrict__ Clo,
             int K, int lda, int ldb, int ldc,
             LL soA, LL siA, LL soB, LL siB, LL soC, LL siC, int IC)
{
    int m0 = blockIdx.y * 256;
    int n0 = blockIdx.x * 128;

    int z = blockIdx.z;
    LL zo = z / IC, zi = z % IC;
    const bf16* Ah_b = Ahi + zo*soA + zi*siA;
    const bf16* Al_b = Alo + zo*soA + zi*siA;
    const bf16* Bh_b = Bhi + zo*soB + zi*siB;
    const bf16* Bl_b = Blo + zo*soB + zi*siB;

    int Keff = KCLIP ? (m0 + 256 < K ? m0 + 256 : K) : K;
    int KT = Keff >> 6;

    extern __shared__ char sm[];
    uint32_t sb = smem_u32(sm);

    int tid = threadIdx.x;
    int wid = tid >> 5, lane = tid & 31;
    int wm = (wid & 7) << 5;
    int wn = (wid >> 3) << 6;
    int g = lane >> 3, r = lane & 7;
    int aro = ((g & 1) << 3) + r, aco = (g >> 1) << 4;
    int bro = ((g >> 1) << 3) + r, bco = (g & 1) << 4;

    float acc[2][8][4];
    #pragma unroll
    for (int i = 0; i < 2; i++)
        #pragma unroll
        for (int j = 0; j < 8; j++)
            #pragma unroll
            for (int t = 0; t < 4; t++) acc[i][j][t] = 0.0f;

    #define LOAD_STG(s, k0) do {                                               \
        uint32_t st = sb + (uint32_t)(s) * 98304u;                             \
        _Pragma("unroll")                                                      \
        for (int i = 0; i < 4; i++) {                                          \
            int idx = tid + (i << 9);                                          \
            int row = idx >> 3, c = idx & 7;                                   \
            uint32_t d = st + SW128((uint32_t)((row << 7) + (c << 4)));        \
            LL go = (LL)(m0 + row) * lda + (k0) + (c << 3);                    \
            CP16(d,          Ah_b + go);                                       \
            CP16(d + 32768u, Al_b + go);                                       \
        }                                                                      \
        _Pragma("unroll")                                                      \
        for (int i = 0; i < 2; i++) {                                          \
            int idx = tid + (i << 9);                                          \
            int row = idx >> 3, c = idx & 7;                                   \
            uint32_t d = st + 65536u + SW128((uint32_t)((row << 7) + (c << 4)));\
            LL go = (LL)(n0 + row) * ldb + (k0) + (c << 3);                    \
            CP16(d,          Bh_b + go);                                       \
            CP16(d + 16384u, Bl_b + go);                                       \
        }                                                                      \
    } while (0)

    LOAD_STG(0, 0);
    CP_COMMIT();

    for (int kt = 0; kt < KT; kt++) {
        CP_WAIT0();
        __syncthreads();
        if (kt + 1 < KT) {
            LOAD_STG((kt + 1) & 1, (kt + 1) << 6);
            CP_COMMIT();
        }

        uint32_t aB = sb + (uint32_t)(kt & 1) * 98304u;
        uint32_t bB = aB + 65536u;

        #pragma unroll
        for (int ks = 0; ks < 4; ks++) {
            int kb = ks << 5;
            uint32_t ah[2][4], al[2][4];
            #pragma unroll
            for (int mf = 0; mf < 2; mf++) {
                uint32_t off = SW128((uint32_t)((wm + (mf << 4) + aro) * 128 + kb + aco));
                ldsm_x4(aB + off,          ah[mf][0], ah[mf][1], ah[mf][2], ah[mf][3]);
                ldsm_x4(aB + 32768u + off, al[mf][0], al[mf][1], al[mf][2], al[mf][3]);
            }
            #pragma unroll
            for (int ng = 0; ng < 4; ng++) {
                uint32_t off = SW128((uint32_t)((wn + (ng << 4) + bro) * 128 + kb + bco));
                uint32_t bh0, bh1, bh2, bh3, bl0, bl1, bl2, bl3;
                ldsm_x4(bB + off,          bh0, bh1, bh2, bh3);
                ldsm_x4(bB + 16384u + off, bl0, bl1, bl2, bl3);
                #pragma unroll
                for (int mf = 0; mf < 2; mf++) {
                    float* c0 = acc[mf][(ng << 1)];
                    float* c1 = acc[mf][(ng << 1) + 1];
                    mma_bf16(c0, ah[mf], bh0, bh1);
                    mma_bf16(c1, ah[mf], bh2, bh3);
                    mma_bf16(c0, ah[mf], bl0, bl1);
                    mma_bf16(c1, ah[mf], bl2, bl3);
                    mma_bf16(c0, al[mf], bh0, bh1);
                    mma_bf16(c1, al[mf], bh2, bh3);
                }
            }
        }
    }

    #pragma unroll
    for (int mf = 0; mf < 2; mf++) {
        int row = m0 + wm + (mf << 4) + (lane >> 2);
        #pragma unroll
        for (int nf = 0; nf < 8; nf++) {
            int col = n0 + wn + (nf << 3) + ((lane & 3) << 1);
            float* a = acc[mf][nf];
            if (EPI == 0) {
                float bx = bias[col], by = bias[col + 1];
                float* Cb = C + zo*soC + zi*siC;
                *(float2*)(Cb + (LL)row * ldc + col)       = make_float2(a[0] + bx, a[1] + by);
                *(float2*)(Cb + (LL)(row + 8) * ldc + col) = make_float2(a[2] + bx, a[3] + by);
            } else {
                bf16* Hb = Chi + zo*soC + zi*siC;
                bf16* Lb = Clo + zo*soC + zi*siC;
                uint32_t hp, lp;
                split2pack(a[0], a[1], hp, lp);
                *(uint32_t*)(Hb + (LL)row * ldc + col) = hp;
                *(uint32_t*)(Lb + (LL)row * ldc + col) = lp;
                split2pack(a[2], a[3], hp, lp);
                *(uint32_t*)(Hb + (LL)(row + 8) * ldc + col) = hp;
                *(uint32_t*)(Lb + (LL)(row + 8) * ldc + col) = lp;
            }
        }
    }
}

// ============ PV GEMM: A = fp32 w (converted in-kernel), B = bf16 splits ============
// 256x128 tile, 512 threads, BK=64, 2-stage. Keff = min(m0+256, K).
// A smem: fp32 [256][72-pitch] per stage (73728 B). B smem: hi/lo 16K+16K per stage.
__global__ __launch_bounds__(512, 1)
void pv_gemm(const float* __restrict__ A,
             const bf16* __restrict__ Bhi, const bf16* __restrict__ Blo,
             bf16* __restrict__ Chi, bf16* __restrict__ Clo,
             int K, int lda, int ldb, int ldc,
             LL soA, LL siA, LL soB, LL siB, LL soC, LL siC, int IC)
{
    int m0 = blockIdx.y * 256;
    int n0 = blockIdx.x * 128;

    int z = blockIdx.z;
    LL zo = z / IC, zi = z % IC;
    const float* A_b = A + zo*soA + zi*siA;
    const bf16* Bh_b = Bhi + zo*soB + zi*siB;
    const bf16* Bl_b = Blo + zo*soB + zi*siB;

    int Keff = (m0 + 256 < K) ? m0 + 256 : K;
    int KT = Keff >> 6;

    extern __shared__ char sm[];
    uint32_t sb = smem_u32(sm);
    // layout: A0 @0 (73728), A1 @73728, B0 @147456 (32768), B1 @180224

    int tid = threadIdx.x;
    int wid = tid >> 5, lane = tid & 31;
    int wm = (wid & 7) << 5;
    int wn = (wid >> 3) << 6;
    int g = lane >> 3, r = lane & 7;
    int bro = ((g >> 1) << 3) + r, bco = (g & 1) << 4;
    int arow = (lane >> 2);          // 0..7 within 16-row fragment
    int acol = (lane & 3) << 1;      // 0,2,4,6

    float acc[2][8][4];
    #pragma unroll
    for (int i = 0; i < 2; i++)
        #pragma unroll
        for (int j = 0; j < 8; j++)
            #pragma unroll
            for (int t = 0; t < 4; t++) acc[i][j][t] = 0.0f;

    #define PV_LOAD(s, k0) do {                                                \
        uint32_t stA = sb + (uint32_t)(s) * 73728u;                            \
        _Pragma("unroll")                                                      \
        for (int i = 0; i < 8; i++) {                                          \
            int idx = tid + (i << 9);                                          \
            int row = idx >> 4, cc = idx & 15;                                 \
            uint32_t d = stA + (uint32_t)(row * 288 + (cc << 4));              \
            CP16(d, A_b + (LL)(m0 + row) * lda + (k0) + (cc << 2));            \
        }                                                                      \
        uint32_t stB = sb + 147456u + (uint32_t)(s) * 32768u;                  \
        _Pragma("unroll")                                                      \
        for (int i = 0; i < 2; i++) {                                          \
            int idx = tid + (i << 9);                                          \
            int row = idx >> 3, c = idx & 7;                                   \
            uint32_t d = stB + SW128((uint32_t)((row << 7) + (c << 4)));       \
            LL go = (LL)(n0 + row) * ldb + (k0) + (c << 3);                    \
            CP16(d,          Bh_b + go);                                       \
            CP16(d + 16384u, Bl_b + go);                                       \
        }                                                                      \
    } while (0)

    PV_LOAD(0, 0);
    CP_COMMIT();

    for (int kt = 0; kt < KT; kt++) {
        CP_WAIT0();
        __syncthreads();
        if (kt + 1 < KT) {
            PV_LOAD((kt + 1) & 1, (kt + 1) << 6);
            CP_COMMIT();
        }

        const float* As = (const float*)(sm + (size_t)(kt & 1) * 73728u);
        uint32_t bB = sb + 147456u + (uint32_t)(kt & 1) * 32768u;

        #pragma unroll
        for (int ks = 0; ks < 4; ks++) {
            int kb = ks << 5;          // B byte offset (16 bf16)
            int kc = (ks << 4) + acol; // A float col
            uint32_t ah[2][4], al[2][4];
            #pragma unroll
            for (int mf = 0; mf < 2; mf++) {
                int r0 = wm + (mf << 4) + arow;
                float2 p0 = *(const float2*)(As + r0 * 72 + kc);
                float2 p1 = *(const float2*)(As + (r0 + 8) * 72 + kc);
                float2 p2 = *(const float2*)(As + r0 * 72 + kc + 8);
                float2 p3 = *(const float2*)(As + (r0 + 8) * 72 + kc + 8);
                split2pack(p0.x, p0.y, ah[mf][0], al[mf][0]);
                split2pack(p1.x, p1.y, ah[mf][1], al[mf][1]);
                split2pack(p2.x, p2.y, ah[mf][2], al[mf][2]);
                split2pack(p3.x, p3.y, ah[mf][3], al[mf][3]);
            }
            #pragma unroll
            for (int ng = 0; ng < 4; ng++) {
                uint32_t off = SW128((uint32_t)((wn + (ng << 4) + bro) * 128 + kb + bco));
                uint32_t bh0, bh1, bh2, bh3, bl0, bl1, bl2, bl3;
                ldsm_x4(bB + off,          bh0, bh1, bh2, bh3);
                ldsm_x4(bB + 16384u + off, bl0, bl1, bl2, bl3);
                #pragma unroll
                for (int mf = 0; mf < 2; mf++) {
                    float* c0 = acc[mf][(ng << 1)];
                    float* c1 = acc[mf][(ng << 1) + 1];
                    mma_bf16(c0, ah[mf], bh0, bh1);
                    mma_bf16(c1, ah[mf], bh2, bh3);
                    mma_bf16(c0, ah[mf], bl0, bl1);
                    mma_bf16(c1, ah[mf], bl2, bl3);
                    mma_bf16(c0, al[mf], bh0, bh1);
                    mma_bf16(c1, al[mf], bh2, bh3);
                }
            }
        }
    }

    #pragma unroll
    for (int mf = 0; mf < 2; mf++) {
        int row = m0 + wm + (mf << 4) + (lane >> 2);
        #pragma unroll
        for (int nf = 0; nf < 8; nf++) {
            int col = n0 + wn + (nf << 3) + ((lane & 3) << 1);
            float* a = acc[mf][nf];
            bf16* Hb = Chi + zo*soC + zi*siC;
            bf16* Lb = Clo + zo*soC + zi*siC;
            uint32_t hp, lp;
            split2pack(a[0], a[1], hp, lp);
            *(uint32_t*)(Hb + (LL)row * ldc + col) = hp;
            *(uint32_t*)(Lb + (LL)row * ldc + col) = lp;
            split2pack(a[2], a[3], hp, lp);
            *(uint32_t*)(Hb + (LL)(row + 8) * ldc + col) = hp;
            *(uint32_t*)(Lb + (LL)(row + 8) * ldc + col) = lp;
        }
    }
}

// ============ score GEMM: bf16x3, 128x128, BK=32, 3-stage, 2 CTAs/SM, causal ============
__global__ __launch_bounds__(256, 2)
void score_gemm(const bf16* __restrict__ Ahi, const bf16* __restrict__ Alo,
                const bf16* __restrict__ Bhi, const bf16* __restrict__ Blo,
                float* __restrict__ W)
{
    int m0 = blockIdx.y * 128;
    int n0 = blockIdx.x * 128;
    int z = blockIdx.z;
    float* Wb = W + (LL)z * SEQ * SEQ;

    int tid = threadIdx.x;

    if (n0 > m0) {
        float4 zz = make_float4(0.f, 0.f, 0.f, 0.f);
        #pragma unroll
        for (int i = 0; i < 16; i++) {
            int idx = tid + (i << 8);
            int row = idx >> 5, c4 = (idx & 31) << 2;
            *(float4*)(Wb + (LL)(m0 + row) * SEQ + n0 + c4) = zz;
        }
        return;
    }

    int b = z >> 4, hh = z & 15;
    const LL lda = (LL)N_HEADS * D_QK;
    LL abase = (LL)b * SEQ * lda + (LL)hh * D_QK;
    const bf16* Ah_b = Ahi + abase;
    const bf16* Al_b = Alo + abase;
    const bf16* Bh_b = Bhi + abase;
    const bf16* Bl_b = Blo + abase;

    extern __shared__ char sm[];
    uint32_t sb = smem_u32(sm);

    int wid = tid >> 5, lane = tid & 31;
    int wm = (wid & 3) << 5;
    int wn = (wid >> 2) << 6;
    int g = lane >> 3, r = lane & 7;
    int aro = ((g & 1) << 3) + r, aco = (g >> 1) << 4;
    int bro = ((g >> 1) << 3) + r, bco = (g & 1) << 4;

    float acc[2][8][4];
    #pragma unroll
    for (int i = 0; i < 2; i++)
        #pragma unroll
        for (int j = 0; j < 8; j++)
            #pragma unroll
            for (int t = 0; t < 4; t++) acc[i][j][t] = 0.0f;

    #define SLOAD(s, k0) do {                                                  \
        uint32_t st = sb + (uint32_t)(s) * 32768u;                             \
        _Pragma("unroll")                                                      \
        for (int i = 0; i < 2; i++) {                                          \
            int idx = tid + (i << 8);                                          \
            int row = idx >> 2, c = (idx & 3) << 4;                            \
            uint32_t sw = SW64((uint32_t)((row << 6) + c));                    \
            LL goA = (LL)(m0 + row) * lda + (k0) + ((idx & 3) << 3);           \
            LL goB = (LL)(n0 + row) * lda + (k0) + ((idx & 3) << 3);           \
            CP16(st + sw,           Ah_b + goA);                               \
            CP16(st + 8192u  + sw,  Al_b + goA);                               \
            CP16(st + 16384u + sw,  Bh_b + goB);                               \
            CP16(st + 24576u + sw,  Bl_b + goB);                               \
        }                                                                      \
    } while (0)

    const int KT = D_QK / 32;   // 6
    SLOAD(0, 0);  CP_COMMIT();
    SLOAD(1, 32); CP_COMMIT();

    int cs = 0, ls = 2;
    for (int kt = 0; kt < KT; kt++) {
        CP_WAIT1();
        __syncthreads();
        if (kt + 2 < KT) {
            SLOAD(ls, (kt + 2) << 5);
        }
        CP_COMMIT();
        ls++; if (ls == 3) ls = 0;

        uint32_t aB = sb + (uint32_t)cs * 32768u;
        uint32_t bB = aB + 16384u;

        #pragma unroll
        for (int ks = 0; ks < 2; ks++) {
            int kb = ks << 5;
            uint32_t ah[2][4], al[2][4];
            #pragma unroll
            for (int mf = 0; mf < 2; mf++) {
                uint32_t off = SW64((uint32_t)((wm + (mf << 4) + aro) * 64 + kb + aco));
                ldsm_x4(aB + off,         ah[mf][0], ah[mf][1], ah[mf][2], ah[mf][3]);
                ldsm_x4(aB + 8192u + off, al[mf][0], al[mf][1], al[mf][2], al[mf][3]);
            }
            #pragma unroll
            for (int ng = 0; ng < 4; ng++) {
                uint32_t off = SW64((uint32_t)((wn + (ng << 4) + bro) * 64 + kb + bco));
                uint32_t bh0, bh1, bh2, bh3, bl0, bl1, bl2, bl3;
                ldsm_x4(bB + off,         bh0, bh1, bh2, bh3);
                ldsm_x4(bB + 8192u + off, bl0, bl1, bl2, bl3);
                #pragma unroll
                for (int mf = 0; mf < 2; mf++) {
                    float* c0 = acc[mf][(ng << 1)];
                    float* c1 = acc[mf][(ng << 1) + 1];
                    mma_bf16(c0, ah[mf], bh0, bh1);
                    mma_bf16(c1, ah[mf], bh2, bh3);
                    mma_bf16(c0, ah[mf], bl0, bl1);
                    mma_bf16(c1, ah[mf], bl2, bl3);
                    mma_bf16(c0, al[mf], bh0, bh1);
                    mma_bf16(c1, al[mf], bh2, bh3);
                }
            }
        }
        cs++; if (cs == 3) cs = 0;
    }

    #pragma unroll
    for (int mf = 0; mf < 2; mf++) {
        int row = m0 + wm + (mf << 4) + (lane >> 2);
        #pragma unroll
        for (int nf = 0; nf < 8; nf++) {
            int col = n0 + wn + (nf << 3) + ((lane & 3) << 1);
            float* a = acc[mf][nf];
            *(float2*)(Wb + (LL)row * SEQ + col)       = make_float2(a[0], a[1]);
            *(float2*)(Wb + (LL)(row + 8) * SEQ + col) = make_float2(a[2], a[3]);
        }
    }
}

// ---------------- split kernels ----------------
__global__ __launch_bounds__(256)
void split_rm(const float* __restrict__ x, bf16* __restrict__ hi, bf16* __restrict__ lo)
{
    LL base = ((LL)blockIdx.x * 256 + threadIdx.x) * 4;
    float4 v = *(const float4*)(x + base);
    bf16 h[4], l[4];
    splitw(v.x, h[0], l[0]); splitw(v.y, h[1], l[1]);
    splitw(v.z, h[2], l[2]); splitw(v.w, h[3], l[3]);
    *(uint2*)(hi + base) = *(uint2*)h;
    *(uint2*)(lo + base) = *(uint2*)l;
}

__global__ __launch_bounds__(256)
void split_tr(const float* __restrict__ x, int ldx,
              bf16* __restrict__ hi, bf16* __restrict__ lo, int R, int C)
{
    __shared__ float s[32][33];
    int tx = threadIdx.x & 31, ty = threadIdx.x >> 5;
    int r0 = blockIdx.y * 32, c0 = blockIdx.x * 32;
    #pragma unroll
    for (int j = 0; j < 4; j++)
        s[ty + 8*j][tx] = x[(LL)(r0 + ty + 8*j) * ldx + c0 + tx];
    __syncthreads();
    #pragma unroll
    for (int j = 0; j < 4; j++) {
        float v = s[tx][ty + 8*j];
        bf16 h, l; splitw(v, h, l);
        LL o = (LL)(c0 + ty + 8*j) * R + r0 + tx;
        hi[o] = h; lo[o] = l;
    }
}

__global__ __launch_bounds__(256)
void zfill(bf16* __restrict__ p, LL n)
{
    LL i = ((LL)blockIdx.x * 256 + threadIdx.x) * 2;
    if (i < n) *(uint32_t*)(p + i) = 0u;
}

__global__ __launch_bounds__(256)
void biascat(const float* __restrict__ bqd, const float* __restrict__ bkv,
             const float* __restrict__ bkr,
             const float* __restrict__ bqc, const float* __restrict__ bqr,
             const float* __restrict__ bkc, const float* __restrict__ bvc,
             float* __restrict__ b1, float* __restrict__ b2, float* __restrict__ b3)
{
    int i = blockIdx.x * 256 + threadIdx.x;
    if (i < N1) {
        float v = 0.0f;
        if (i < 1536) v = bqd[i];
        else if (i < 2048) v = bkv[i - 1536];
        else if (i < 2112) v = bkr[i - 2048];
        b1[i] = v;
    }
    if (i < 2048) b2[i] = bqc[i]; else if (i < 3072) b2[i] = bqr[i - 2048];
    if (i < 2048) b3[i] = bkc[i]; else if (i < 4096) b3[i] = bvc[i - 2048];
}

__global__ __launch_bounds__(256)
void rmsnorm_slice(const float* __restrict__ x, int ldx, int off,
                   const float* __restrict__ g, float* __restrict__ y, int dim)
{
    LL xb = (LL)blockIdx.x * ldx + off;
    LL yb = (LL)blockIdx.x * dim;
    int tid = threadIdx.x;
    float s = 0.0f;
    for (int i = tid; i < dim; i += 256) { float v = x[xb + i]; s += v * v; }
    __shared__ float red[256];
    red[tid] = s; __syncthreads();
    for (int st = 128; st > 0; st >>= 1) {
        if (tid < st) red[tid] += red[tid + st];
        __syncthreads();
    }
    float rs = rsqrtf(red[0] / (float)dim + 1e-6f);
    for (int i = tid; i < dim; i += 256)
        y[yb + i] = x[xb + i] * rs * g[i];
}

__global__ __launch_bounds__(256)
void rmsnorm_split(const float* __restrict__ x, int ldx, int off,
                   const float* __restrict__ g,
                   bf16* __restrict__ yh, bf16* __restrict__ yl, int dim)
{
    LL xb = (LL)blockIdx.x * ldx + off;
    LL yb = (LL)blockIdx.x * dim;
    int tid = threadIdx.x;
    float s = 0.0f;
    for (int i = tid; i < dim; i += 256) { float v = x[xb + i]; s += v * v; }
    __shared__ float red[256];
    red[tid] = s; __syncthreads();
    for (int st = 128; st > 0; st >>= 1) {
        if (tid < st) red[tid] += red[tid + st];
        __syncthreads();
    }
    float rs = rsqrtf(red[0] / (float)dim + 1e-6f);
    for (int i = tid; i < dim; i += 256) {
        float v = x[xb + i] * rs * g[i];
        bf16 h, l; splitw(v, h, l);
        yh[yb + i] = h; yl[yb + i] = l;
    }
}

// ---------------- pack with RoPE -> bf16 splits (q pre-scaled) ----------------
__global__ __launch_bounds__(256)
void pack_split(const float* __restrict__ qCR, const float* __restrict__ kvC,
                const float* __restrict__ krn, const float* __restrict__ freqs,
                bf16* __restrict__ qfh, bf16* __restrict__ qfl,
                bf16* __restrict__ kfh, bf16* __restrict__ kfl, float scale)
{
    int bs = blockIdx.x;
    int s  = bs & (SEQ - 1);
    LL qfb = (LL)bs * N_HEADS * D_QK;
    int tid = threadIdx.x;

    __shared__ float krs[D_R];
    if (tid < 32) {
        int i = tid;
        float a = krn[(LL)bs*D_R + 2*i];
        float b = krn[(LL)bs*D_R + 2*i + 1];
        float c  = freqs[(LL)s*D_R + 2*i];
        float sn = freqs[(LL)s*D_R + 2*i + 1];
        krs[2*i]   = a*c - b*sn;
        krs[2*i+1] = a*sn + b*c;
    }
    __syncthreads();

    for (int idx = tid; idx < N_HEADS*D_H; idx += 256) {
        int h = idx >> 7, d = idx & 127;
        float v = qCR[(LL)bs*3072 + idx] * scale;
        bf16 hh, ll; splitw(v, hh, ll);
        qfh[qfb + h*D_QK + d] = hh; qfl[qfb + h*D_QK + d] = ll;
    }
    for (int idx = tid; idx < N_HEADS*(D_R/2); idx += 256) {
        int h = idx >> 5, i = idx & 31;
        float a = qCR[(LL)bs*3072 + 2048 + h*D_R + 2*i];
        float b = qCR[(LL)bs*3072 + 2048 + h*D_R + 2*i + 1];
        float c  = freqs[(LL)s*D_R + 2*i];
        float sn = freqs[(LL)s*D_R + 2*i + 1];
        float v0 = (a*c - b*sn) * scale, v1 = (a*sn + b*c) * scale;
        bf16 hh, ll;
        splitw(v0, hh, ll);
        qfh[qfb + h*D_QK + D_H + 2*i] = hh;   qfl[qfb + h*D_QK + D_H + 2*i] = ll;
        splitw(v1, hh, ll);
        qfh[qfb + h*D_QK + D_H + 2*i+1] = hh; qfl[qfb + h*D_QK + D_H + 2*i+1] = ll;
    }
    for (int idx = tid; idx < N_HEADS*D_R; idx += 256) {
        int h = idx >> 6, d = idx & 63;
        bf16 hh, ll; splitw(krs[d], hh, ll);
        kfh[qfb + h*D_QK + d] = hh; kfl[qfb + h*D_QK + d] = ll;
    }
    for (int idx = tid; idx < N_HEADS*D_H; idx += 256) {
        int h = idx >> 7, d = idx & 127;
        float v = kvC[(LL)bs*4096 + idx];
        bf16 hh, ll; splitw(v, hh, ll);
        kfh[qfb + h*D_QK + D_R + d] = hh; kfl[qfb + h*D_QK + D_R + d] = ll;
    }
}

// ---------------- causal softmax (fp32 only, writes k < kLim) ----------------
__global__ __launch_bounds__(256)
void softmax_kernel(float* __restrict__ w)
{
    LL row = blockIdx.x;
    int q = (int)(row & (SEQ - 1));
    float* base = w + row * (LL)SEQ;
    int tid = threadIdx.x;

    float vals[8];
    float mx = -INFINITY;
    #pragma unroll
    for (int it = 0; it < 8; it++) {
        int k = tid + it * 256;
        float v = -INFINITY;
        if (k <= q) v = base[k];
        vals[it] = v;
        mx = fmaxf(mx, v);
    }
    __shared__ float red[256];
    red[tid] = mx; __syncthreads();
    for (int st = 128; st > 0; st >>= 1) {
        if (tid < st) red[tid] = fmaxf(red[tid], red[tid + st]);
        __syncthreads();
    }
    mx = red[0]; __syncthreads();

    float sum = 0.0f;
    #pragma unroll
    for (int it = 0; it < 8; it++) {
        float e = (vals[it] == -INFINITY) ? 0.0f : __expf(vals[it] - mx);
        vals[it] = e;
        sum += e;
    }
    red[tid] = sum; __syncthreads();
    for (int st = 128; st > 0; st >>= 1) {
        if (tid < st) red[tid] += red[tid + st];
        __syncthreads();
    }
    float inv = 1.0f / red[0];

    int kLim = ((q >> 8) + 1) << 8;   // PV reads k < m0+256 = kLim; beyond pre-zeroed
    #pragma unroll
    for (int it = 0; it < 8; it++) {
        int k = tid + it * 256;
        if (k < kLim) base[k] = vals[it] * inv;
    }
}

// ---------------- host ----------------
#define SYMF(name) ({ void* p_; cudaGetSymbolAddress(&p_, name); (float*)p_; })
#define SYMB(name) ({ void* p_; cudaGetSymbolAddress(&p_, name); (bf16*)p_; })

#define G512_SMEM  196608
#define SCORE_SMEM 98304
#define PV_SMEM    212992

extern "C" void kernel_launch(void* const* d_in, const int* in_sizes, int n_in,
                              void* d_out, int out_size)
{
    (void)in_sizes; (void)n_in; (void)out_size;
    const float* h       = (const float*)d_in[0];
    const float* freqs   = (const float*)d_in[1];
    const float* Wq_down = (const float*)d_in[3];
    const float* bq_down = (const float*)d_in[4];
    const float* gq_norm = (const float*)d_in[5];
    const float* Wqc     = (const float*)d_in[6];
    const float* bqc     = (const float*)d_in[7];
    const float* Wqr     = (const float*)d_in[8];
    const float* bqr     = (const float*)d_in[9];
    const float* Wkr     = (const float*)d_in[10];
    const float* bkr     = (const float*)d_in[11];
    const float* gkr     = (const float*)d_in[12];
    const float* Wkv     = (const float*)d_in[13];
    const float* bkv     = (const float*)d_in[14];
    const float* gkv     = (const float*)d_in[15];
    const float* Wkc     = (const float*)d_in[16];
    const float* bkc     = (const float*)d_in[17];
    const float* Wvc     = (const float*)d_in[18];
    const float* bvc     = (const float*)d_in[19];
    const float* Wo      = (const float*)d_in[20];
    const float* bo      = (const float*)d_in[21];

    float* out_h = (float*)d_out;
    float* w     = out_h + (LL)NTOK * D_MODEL;

    float* tmp12 = SYMF(g_tmp12);
    float* qCR = SYMF(g_qCR);
    float* kvC = SYMF(g_kvC);
    float* krn = SYMF(g_krn);
    float* b1 = SYMF(g_bias1); float* b2 = SYMF(g_bias2); float* b3 = SYMF(g_bias3);

    bf16 *h_hi = SYMB(g_h_hi), *h_lo = SYMB(g_h_lo);
    bf16 *WdT_hi = SYMB(g_WdT_hi), *WdT_lo = SYMB(g_WdT_lo);
    bf16 *WqcrT_hi = SYMB(g_WqcrT_hi), *WqcrT_lo = SYMB(g_WqcrT_lo);
    bf16 *WkvcT_hi = SYMB(g_WkvcT_hi), *WkvcT_lo = SYMB(g_WkvcT_lo);
    bf16 *WoT_hi  = SYMB(g_WoT_hi),  *WoT_lo  = SYMB(g_WoT_lo);
    bf16 *cQ_hi = SYMB(g_cQ_hi), *cQ_lo = SYMB(g_cQ_lo);
    bf16 *cKV_hi = SYMB(g_cKV_hi), *cKV_lo = SYMB(g_cKV_lo);
    bf16 *qf_hi = SYMB(g_qf_hi), *qf_lo = SYMB(g_qf_lo);
    bf16 *kf_hi = SYMB(g_kf_hi), *kf_lo = SYMB(g_kf_lo);
    bf16 *vCT_hi = SYMB(g_vCT_hi), *vCT_lo = SYMB(g_vCT_lo);
    bf16 *attn_hi = SYMB(g_attn_hi), *attn_lo = SYMB(g_attn_lo);

    cudaFuncSetAttribute((const void*)gemm512<0,false>, cudaFuncAttributeMaxDynamicSharedMemorySize, G512_SMEM);
    cudaFuncSetAttribute((const void*)pv_gemm,          cudaFuncAttributeMaxDynamicSharedMemorySize, PV_SMEM);
    cudaFuncSetAttribute(score_gemm, cudaFuncAttributeMaxDynamicSharedMemorySize, SCORE_SMEM);

    // prep
    biascat<<<(N1 + 255)/256 > 16 ? (N1+255)/256 : 16, 256>>>(
        bq_down, bkv, bkr, bqc, bqr, bkc, bvc, b1, b2, b3);
    split_rm<<<(LL)NTOK*D_MODEL/1024, 256>>>(h, h_hi, h_lo);
    split_tr<<<dim3(D_CQ/32, D_MODEL/32), 256>>>(Wq_down, D_CQ, WdT_hi, WdT_lo, D_MODEL, D_CQ);
    split_tr<<<dim3(D_C/32, D_MODEL/32), 256>>>(Wkv, D_C,
        WdT_hi + (LL)D_CQ*D_MODEL, WdT_lo + (LL)D_CQ*D_MODEL, D_MODEL, D_C);
    split_tr<<<dim3(D_R/32, D_MODEL/32), 256>>>(Wkr, D_R,
        WdT_hi + (LL)2048*D_MODEL, WdT_lo + (LL)2048*D_MODEL, D_MODEL, D_R);
    zfill<<<(64*D_MODEL/2 + 255)/256, 256>>>(WdT_hi + (LL)2112*D_MODEL, (LL)64*D_MODEL);
    zfill<<<(64*D_MODEL/2 + 255)/256, 256>>>(WdT_lo + (LL)2112*D_MODEL, (LL)64*D_MODEL);

    // merged: tmp12 = h @ [Wq_down | Wkv | Wkr | 0] + bias   (N=2176)
    gemm512<0,false><<<dim3(N1/128, NTOK/256), 512, G512_SMEM>>>(
        h_hi, h_lo, WdT_hi, WdT_lo, b1, tmp12, nullptr, nullptr,
        D_MODEL, D_MODEL, D_MODEL, N1, 0,0,0,0,0,0,1);

    // remaining weight splits
    split_tr<<<dim3(2048/32, D_CQ/32), 256>>>(Wqc, 2048, WqcrT_hi, WqcrT_lo, D_CQ, 2048);
    split_tr<<<dim3(1024/32, D_CQ/32), 256>>>(Wqr, 1024,
        WqcrT_hi + (LL)2048*D_CQ, WqcrT_lo + (LL)2048*D_CQ, D_CQ, 1024);
    split_tr<<<dim3(2048/32, D_C/32), 256>>>(Wkc, 2048, WkvcT_hi, WkvcT_lo, D_C, 2048);
    split_tr<<<dim3(2048/32, D_C/32), 256>>>(Wvc, 2048,
        WkvcT_hi + (LL)2048*D_C, WkvcT_lo + (LL)2048*D_C, D_C, 2048);
    split_tr<<<dim3(2048/32, 2048/32), 256>>>(Wo, 2048, WoT_hi, WoT_lo, 2048, 2048);

    // norms
    rmsnorm_split<<<NTOK, 256>>>(tmp12, N1, 0,    gq_norm, cQ_hi, cQ_lo, D_CQ);
    rmsnorm_split<<<NTOK, 256>>>(tmp12, N1, D_CQ, gkv,     cKV_hi, cKV_lo, D_C);
    rmsnorm_slice<<<NTOK, 256>>>(tmp12, N1, 2048, gkr, krn, D_R);

    // merged: qCR = cQ @ [Wqc | Wqr] + [bqc | bqr]   (N=3072)
    gemm512<0,false><<<dim3(3072/128, NTOK/256), 512, G512_SMEM>>>(
        cQ_hi, cQ_lo, WqcrT_hi, WqcrT_lo, b2, qCR, nullptr, nullptr,
        D_CQ, D_CQ, D_CQ, 3072, 0,0,0,0,0,0,1);

    // merged: kvC = cKV @ [Wkc | Wvc] + [bkc | bvc]   (N=4096)
    gemm512<0,false><<<dim3(4096/128, NTOK/256), 512, G512_SMEM>>>(
        cKV_hi, cKV_lo, WkvcT_hi, WkvcT_lo, b3, kvC, nullptr, nullptr,
        D_C, D_C, D_C, 4096, 0,0,0,0,0,0,1);

    // vC^T splits
    split_tr<<<dim3(2048/32, NTOK/32), 256>>>(kvC + 2048, 4096, vCT_hi, vCT_lo, NTOK, 2048);

    // pack + RoPE (q pre-scaled)
    pack_split<<<NTOK, 256>>>(qCR, kvC, krn, freqs, qf_hi, qf_lo, kf_hi, kf_lo,
                              1.0f / sqrtf((float)D_QK));

    // scores = q k^T (causal; upper tiles zero-fill w)
    score_gemm<<<dim3(SEQ/128, SEQ/128, BSZ*N_HEADS), 256, SCORE_SMEM>>>(
        qf_hi, qf_lo, kf_hi, kf_lo, w);

    // softmax (fp32 only)
    softmax_kernel<<<(LL)BSZ*N_HEADS*SEQ, 256>>>(w);

    // PV: attn = w(fp32, split in-kernel) @ vC, K clipped, bf16-split output
    {
        LL soW = (LL)N_HEADS * SEQ * SEQ, siW = (LL)SEQ * SEQ;
        LL soB = 2048;
        LL siB = (LL)D_H * NTOK;
        LL soC = (LL)SEQ * 2048, siC = D_H;
        pv_gemm<<<dim3(D_H/128, SEQ/256, BSZ*N_HEADS), 512, PV_SMEM>>>(
            w, vCT_hi, vCT_lo, attn_hi, attn_lo,
            SEQ, SEQ, NTOK, 2048,
            soW, siW, soB, siB, soC, siC, N_HEADS);
    }

    // h_out = attn @ Wo + bo
    gemm512<0,false><<<dim3(2048/128, NTOK/256), 512, G512_SMEM>>>(
        attn_hi, attn_lo, WoT_hi, WoT_lo, bo, out_h, nullptr, nullptr,
        2048, 2048, 2048, 2048, 0,0,0,0,0,0,1);
}

// round 13
// speedup vs baseline: 1.0103x; 1.0103x over previous
#include <cuda_runtime.h>
#include <cuda_bf16.h>
#include <math.h>
#include <stdint.h>

#define D_MODEL 2048
#define N_HEADS 16
#define D_CQ    1536
#define D_C     512
#define D_H     128
#define D_R     64
#define BSZ     4
#define SEQ     2048
#define NTOK    (BSZ*SEQ)
#define D_QK    (D_H + D_R)
#define LL long long

#define SW128(o) ((o) ^ (((o) >> 3) & 0x70))
#define SW64(o)  ((o) ^ (((o) >> 2) & 0x30))

#define N1 2176   // merged first-GEMM N: Wqd(1536) | Wkv(512) | Wkr(64) | pad(64)

typedef __nv_bfloat16 bf16;

// ---------------- scratch ----------------
__device__ float g_tmp12[(LL)NTOK * N1];
__device__ float g_qCR [(LL)NTOK * 3072];
__device__ float g_kvC [(LL)NTOK * 4096];
__device__ float g_krn [(LL)NTOK * D_R];
__device__ bf16 g_h_hi[(LL)NTOK * D_MODEL],      g_h_lo[(LL)NTOK * D_MODEL];
__device__ bf16 g_WdT_hi[(LL)N1 * D_MODEL],      g_WdT_lo[(LL)N1 * D_MODEL];
__device__ bf16 g_WqcrT_hi[(LL)3072 * D_CQ],     g_WqcrT_lo[(LL)3072 * D_CQ];
__device__ bf16 g_WkvcT_hi[(LL)4096 * D_C],      g_WkvcT_lo[(LL)4096 * D_C];
__device__ bf16 g_WoT_hi[(LL)2048 * 2048],       g_WoT_lo[(LL)2048 * 2048];
__device__ bf16 g_cQ_hi[(LL)NTOK * D_CQ],        g_cQ_lo[(LL)NTOK * D_CQ];
__device__ bf16 g_cKV_hi[(LL)NTOK * D_C],        g_cKV_lo[(LL)NTOK * D_C];
__device__ bf16 g_qf_hi[(LL)NTOK * N_HEADS*D_QK], g_qf_lo[(LL)NTOK * N_HEADS*D_QK];
__device__ bf16 g_kf_hi[(LL)NTOK * N_HEADS*D_QK], g_kf_lo[(LL)NTOK * N_HEADS*D_QK];
__device__ bf16 g_vCT_hi[(LL)2048 * NTOK],       g_vCT_lo[(LL)2048 * NTOK];
__device__ bf16 g_w_hi[(LL)BSZ*N_HEADS*SEQ*SEQ], g_w_lo[(LL)BSZ*N_HEADS*SEQ*SEQ];
__device__ bf16 g_attn_hi[(LL)NTOK * 2048],      g_attn_lo[(LL)NTOK * 2048];
__device__ float g_bias1[N1];
__device__ float g_bias2[3072];
__device__ float g_bias3[4096];

// ---------------- helpers ----------------
__device__ __forceinline__ uint32_t smem_u32(const void* p) {
    uint32_t a;
    asm("{ .reg .u64 t; cvta.to.shared.u64 t, %1; cvt.u32.u64 %0, t; }" : "=r"(a) : "l"(p));
    return a;
}
#define CP16(d, s) asm volatile("cp.async.cg.shared.global [%0], [%1], 16;" :: "r"(d), "l"(s))
#define CP_COMMIT() asm volatile("cp.async.commit_group;" ::: "memory")
#define CP_WAIT1() asm volatile("cp.async.wait_group 1;" ::: "memory")
#define CP_WAIT0() asm volatile("cp.async.wait_group 0;" ::: "memory")

__device__ __forceinline__ void ldsm_x4(uint32_t addr, uint32_t& r0, uint32_t& r1,
                                        uint32_t& r2, uint32_t& r3) {
    asm volatile("ldmatrix.sync.aligned.m8n8.x4.shared.b16 {%0,%1,%2,%3}, [%4];"
                 : "=r"(r0), "=r"(r1), "=r"(r2), "=r"(r3) : "r"(addr));
}
__device__ __forceinline__ void mma_bf16(float* c, const uint32_t* a,
                                         uint32_t b0, uint32_t b1) {
    asm volatile(
        "mma.sync.aligned.m16n8k16.row.col.f32.bf16.bf16.f32 "
        "{%0,%1,%2,%3}, {%4,%5,%6,%7}, {%8,%9}, {%0,%1,%2,%3};"
        : "+f"(c[0]), "+f"(c[1]), "+f"(c[2]), "+f"(c[3])
        : "r"(a[0]), "r"(a[1]), "r"(a[2]), "r"(a[3]), "r"(b0), "r"(b1));
}
__device__ __forceinline__ void splitw(float v, bf16& hi, bf16& lo) {
    hi = __float2bfloat16(v);
    lo = __float2bfloat16(v - __bfloat162float(hi));
}
__device__ __forceinline__ void split2pack(float f0, float f1, uint32_t& hp, uint32_t& lp) {
    bf16 h0, l0, h1, l1;
    splitw(f0, h0, l0); splitw(f1, h1, l1);
    hp = ((uint32_t)__bfloat16_as_ushort(h1) << 16) | __bfloat16_as_ushort(h0);
    lp = ((uint32_t)__bfloat16_as_ushort(l1) << 16) | __bfloat16_as_ushort(l0);
}

// ============ bf16x3 GEMM: 256x128 tile, 512 threads, BK=64, 2-stage ============
// EPI: 0=fp32+bias, 2=bf16 splits.
template<int EPI>
__global__ __launch_bounds__(512, 1)
void gemm512(const bf16* __restrict__ Ahi, const bf16* __restrict__ Alo,
             const bf16* __restrict__ Bhi, const bf16* __restrict__ Blo,
             const float* __restrict__ bias,
             float* __restrict__ C, bf16* __restrict__ Chi, bf16* __restrict__ Clo,
             int K, int lda, int ldb, int ldc,
             LL soA, LL siA, LL soB, LL siB, LL soC, LL siC, int IC)
{
    int m0 = blockIdx.y * 256;
    int n0 = blockIdx.x * 128;

    int z = blockIdx.z;
    LL zo = z / IC, zi = z % IC;
    const bf16* Ah_b = Ahi + zo*soA + zi*siA;
    const bf16* Al_b = Alo + zo*soA + zi*siA;
    const bf16* Bh_b = Bhi + zo*soB + zi*siB;
    const bf16* Bl_b = Blo + zo*soB + zi*siB;

    int KT = K >> 6;

    extern __shared__ char sm[];
    uint32_t sb = smem_u32(sm);

    int tid = threadIdx.x;
    int wid = tid >> 5, lane = tid & 31;
    int wm = (wid & 7) << 5;
    int wn = (wid >> 3) << 6;
    int g = lane >> 3, r = lane & 7;
    int aro = ((g & 1) << 3) + r, aco = (g >> 1) << 4;
    int bro = ((g >> 1) << 3) + r, bco = (g & 1) << 4;

    float acc[2][8][4];
    #pragma unroll
    for (int i = 0; i < 2; i++)
        #pragma unroll
        for (int j = 0; j < 8; j++)
            #pragma unroll
            for (int t = 0; t < 4; t++) acc[i][j][t] = 0.0f;

    #define LOAD_STG(s, k0) do {                                               \
        uint32_t st = sb + (uint32_t)(s) * 98304u;                             \
        _Pragma("unroll")                                                      \
        for (int i = 0; i < 4; i++) {                                          \
            int idx = tid + (i << 9);                                          \
            int row = idx >> 3, c = idx & 7;                                   \
            uint32_t d = st + SW128((uint32_t)((row << 7) + (c << 4)));        \
            LL go = (LL)(m0 + row) * lda + (k0) + (c << 3);                    \
            CP16(d,          Ah_b + go);                                       \
            CP16(d + 32768u, Al_b + go);                                       \
        }                                                                      \
        _Pragma("unroll")                                                      \
        for (int i = 0; i < 2; i++) {                                          \
            int idx = tid + (i << 9);                                          \
            int row = idx >> 3, c = idx & 7;                                   \
            uint32_t d = st + 65536u + SW128((uint32_t)((row << 7) + (c << 4)));\
            LL go = (LL)(n0 + row) * ldb + (k0) + (c << 3);                    \
            CP16(d,          Bh_b + go);                                       \
            CP16(d + 16384u, Bl_b + go);                                       \
        }                                                                      \
    } while (0)

    LOAD_STG(0, 0);
    CP_COMMIT();

    for (int kt = 0; kt < KT; kt++) {
        CP_WAIT0();
        __syncthreads();
        if (kt + 1 < KT) {
            LOAD_STG((kt + 1) & 1, (kt + 1) << 6);
            CP_COMMIT();
        }

        uint32_t aB = sb + (uint32_t)(kt & 1) * 98304u;
        uint32_t bB = aB + 65536u;

        #pragma unroll
        for (int ks = 0; ks < 4; ks++) {
            int kb = ks << 5;
            uint32_t ah[2][4], al[2][4];
            #pragma unroll
            for (int mf = 0; mf < 2; mf++) {
                uint32_t off = SW128((uint32_t)((wm + (mf << 4) + aro) * 128 + kb + aco));
                ldsm_x4(aB + off,          ah[mf][0], ah[mf][1], ah[mf][2], ah[mf][3]);
                ldsm_x4(aB + 32768u + off, al[mf][0], al[mf][1], al[mf][2], al[mf][3]);
            }
            #pragma unroll
            for (int ng = 0; ng < 4; ng++) {
                uint32_t off = SW128((uint32_t)((wn + (ng << 4) + bro) * 128 + kb + bco));
                uint32_t bh0, bh1, bh2, bh3, bl0, bl1, bl2, bl3;
                ldsm_x4(bB + off,          bh0, bh1, bh2, bh3);
                ldsm_x4(bB + 16384u + off, bl0, bl1, bl2, bl3);
                #pragma unroll
                for (int mf = 0; mf < 2; mf++) {
                    float* c0 = acc[mf][(ng << 1)];
                    float* c1 = acc[mf][(ng << 1) + 1];
                    mma_bf16(c0, ah[mf], bh0, bh1);
                    mma_bf16(c1, ah[mf], bh2, bh3);
                    mma_bf16(c0, ah[mf], bl0, bl1);
                    mma_bf16(c1, ah[mf], bl2, bl3);
                    mma_bf16(c0, al[mf], bh0, bh1);
                    mma_bf16(c1, al[mf], bh2, bh3);
                }
            }
        }
    }

    #pragma unroll
    for (int mf = 0; mf < 2; mf++) {
        int row = m0 + wm + (mf << 4) + (lane >> 2);
        #pragma unroll
        for (int nf = 0; nf < 8; nf++) {
            int col = n0 + wn + (nf << 3) + ((lane & 3) << 1);
            float* a = acc[mf][nf];
            if (EPI == 0) {
                float bx = bias[col], by = bias[col + 1];
                float* Cb = C + zo*soC + zi*siC;
                *(float2*)(Cb + (LL)row * ldc + col)       = make_float2(a[0] + bx, a[1] + by);
                *(float2*)(Cb + (LL)(row + 8) * ldc + col) = make_float2(a[2] + bx, a[3] + by);
            } else {
                bf16* Hb = Chi + zo*soC + zi*siC;
                bf16* Lb = Clo + zo*soC + zi*siC;
                uint32_t hp, lp;
                split2pack(a[0], a[1], hp, lp);
                *(uint32_t*)(Hb + (LL)row * ldc + col) = hp;
                *(uint32_t*)(Lb + (LL)row * ldc + col) = lp;
                split2pack(a[2], a[3], hp, lp);
                *(uint32_t*)(Hb + (LL)(row + 8) * ldc + col) = hp;
                *(uint32_t*)(Lb + (LL)(row + 8) * ldc + col) = lp;
            }
        }
    }
}

// ============ attn128: bf16x3, 128x128, BK=32, 3-stage, 2 CTAs/SM ============
// Shared by score (CAUSAL=1: skip/zero upper tiles, A=B=qf/kf, fp32 out) and
// PV (KCLIP=1: Keff=min(m0+128,K), A=w splits, B=vCT splits, bf16-split out).
template<bool CAUSAL, bool KCLIP, int EPI>   // EPI: 1=fp32, 2=bf16 splits
__global__ __launch_bounds__(256, 2)
void attn128(const bf16* __restrict__ Ahi, const bf16* __restrict__ Alo,
             const bf16* __restrict__ Bhi, const bf16* __restrict__ Blo,
             float* __restrict__ C, bf16* __restrict__ Chi, bf16* __restrict__ Clo,
             int K, int lda, int ldb, int ldc,
             LL soA, LL siA, LL soB, LL siB, LL soC, LL siC, int IC)
{
    int m0 = blockIdx.y * 128;
    int n0 = blockIdx.x * 128;
    int z = blockIdx.z;
    LL zo = z / IC, zi = z % IC;
    int tid = threadIdx.x;

    if (CAUSAL && n0 > m0) {
        float* Wb = C + zo*soC + zi*siC;
        float4 zz = make_float4(0.f, 0.f, 0.f, 0.f);
        #pragma unroll
        for (int i = 0; i < 16; i++) {
            int idx = tid + (i << 8);
            int row = idx >> 5, c4 = (idx & 31) << 2;
            *(float4*)(Wb + (LL)(m0 + row) * ldc + n0 + c4) = zz;
        }
        return;
    }

    const bf16* Ah_b = Ahi + zo*soA + zi*siA;
    const bf16* Al_b = Alo + zo*soA + zi*siA;
    const bf16* Bh_b = Bhi + zo*soB + zi*siB;
    const bf16* Bl_b = Blo + zo*soB + zi*siB;

    int Keff = KCLIP ? (m0 + 128 < K ? m0 + 128 : K) : K;
    int KT = Keff >> 5;

    extern __shared__ char sm[];
    uint32_t sb = smem_u32(sm);

    int wid = tid >> 5, lane = tid & 31;
    int wm = (wid & 3) << 5;
    int wn = (wid >> 2) << 6;
    int g = lane >> 3, r = lane & 7;
    int aro = ((g & 1) << 3) + r, aco = (g >> 1) << 4;
    int bro = ((g >> 1) << 3) + r, bco = (g & 1) << 4;

    float acc[2][8][4];
    #pragma unroll
    for (int i = 0; i < 2; i++)
        #pragma unroll
        for (int j = 0; j < 8; j++)
            #pragma unroll
            for (int t = 0; t < 4; t++) acc[i][j][t] = 0.0f;

    #define SLOAD(s, k0) do {                                                  \
        uint32_t st = sb + (uint32_t)(s) * 32768u;                             \
        _Pragma("unroll")                                                      \
        for (int i = 0; i < 2; i++) {                                          \
            int idx = tid + (i << 8);                                          \
            int row = idx >> 2, c = (idx & 3) << 4;                            \
            uint32_t sw = SW64((uint32_t)((row << 6) + c));                    \
            LL goA = (LL)(m0 + row) * lda + (k0) + ((idx & 3) << 3);           \
            LL goB = (LL)(n0 + row) * ldb + (k0) + ((idx & 3) << 3);           \
            CP16(st + sw,           Ah_b + goA);                               \
            CP16(st + 8192u  + sw,  Al_b + goA);                               \
            CP16(st + 16384u + sw,  Bh_b + goB);                               \
            CP16(st + 24576u + sw,  Bl_b + goB);                               \
        }                                                                      \
    } while (0)

    SLOAD(0, 0);  CP_COMMIT();
    SLOAD(1, 32); CP_COMMIT();

    int cs = 0, ls = 2;
    for (int kt = 0; kt < KT; kt++) {
        CP_WAIT1();
        __syncthreads();
        if (kt + 2 < KT) {
            SLOAD(ls, (kt + 2) << 5);
        }
        CP_COMMIT();
        ls++; if (ls == 3) ls = 0;

        uint32_t aB = sb + (uint32_t)cs * 32768u;
        uint32_t bB = aB + 16384u;

        #pragma unroll
        for (int ks = 0; ks < 2; ks++) {
            int kb = ks << 5;
            uint32_t ah[2][4], al[2][4];
            #pragma unroll
            for (int mf = 0; mf < 2; mf++) {
                uint32_t off = SW64((uint32_t)((wm + (mf << 4) + aro) * 64 + kb + aco));
                ldsm_x4(aB + off,         ah[mf][0], ah[mf][1], ah[mf][2], ah[mf][3]);
                ldsm_x4(aB + 8192u + off, al[mf][0], al[mf][1], al[mf][2], al[mf][3]);
            }
            #pragma unroll
            for (int ng = 0; ng < 4; ng++) {
                uint32_t off = SW64((uint32_t)((wn + (ng << 4) + bro) * 64 + kb + bco));
                uint32_t bh0, bh1, bh2, bh3, bl0, bl1, bl2, bl3;
                ldsm_x4(bB + off,         bh0, bh1, bh2, bh3);
                ldsm_x4(bB + 8192u + off, bl0, bl1, bl2, bl3);
                #pragma unroll
                for (int mf = 0; mf < 2; mf++) {
                    float* c0 = acc[mf][(ng << 1)];
                    float* c1 = acc[mf][(ng << 1) + 1];
                    mma_bf16(c0, ah[mf], bh0, bh1);
                    mma_bf16(c1, ah[mf], bh2, bh3);
                    mma_bf16(c0, ah[mf], bl0, bl1);
                    mma_bf16(c1, ah[mf], bl2, bl3);
                    mma_bf16(c0, al[mf], bh0, bh1);
                    mma_bf16(c1, al[mf], bh2, bh3);
                }
            }
        }
        cs++; if (cs == 3) cs = 0;
    }

    #pragma unroll
    for (int mf = 0; mf < 2; mf++) {
        int row = m0 + wm + (mf << 4) + (lane >> 2);
        #pragma unroll
        for (int nf = 0; nf < 8; nf++) {
            int col = n0 + wn + (nf << 3) + ((lane & 3) << 1);
            float* a = acc[mf][nf];
            if (EPI == 1) {
                float* Cb = C + zo*soC + zi*siC;
                *(float2*)(Cb + (LL)row * ldc + col)       = make_float2(a[0], a[1]);
                *(float2*)(Cb + (LL)(row + 8) * ldc + col) = make_float2(a[2], a[3]);
            } else {
                bf16* Hb = Chi + zo*soC + zi*siC;
                bf16* Lb = Clo + zo*soC + zi*siC;
                uint32_t hp, lp;
                split2pack(a[0], a[1], hp, lp);
                *(uint32_t*)(Hb + (LL)row * ldc + col) = hp;
                *(uint32_t*)(Lb + (LL)row * ldc + col) = lp;
                split2pack(a[2], a[3], hp, lp);
                *(uint32_t*)(Hb + (LL)(row + 8) * ldc + col) = hp;
                *(uint32_t*)(Lb + (LL)(row + 8) * ldc + col) = lp;
            }
        }
    }
}

// ---------------- split kernels ----------------
__global__ __launch_bounds__(256)
void split_rm(const float* __restrict__ x, bf16* __restrict__ hi, bf16* __restrict__ lo)
{
    LL base = ((LL)blockIdx.x * 256 + threadIdx.x) * 4;
    float4 v = *(const float4*)(x + base);
    bf16 h[4], l[4];
    splitw(v.x, h[0], l[0]); splitw(v.y, h[1], l[1]);
    splitw(v.z, h[2], l[2]); splitw(v.w, h[3], l[3]);
    *(uint2*)(hi + base) = *(uint2*)h;
    *(uint2*)(lo + base) = *(uint2*)l;
}

__global__ __launch_bounds__(256)
void split_tr(const float* __restrict__ x, int ldx,
              bf16* __restrict__ hi, bf16* __restrict__ lo, int R, int C)
{
    __shared__ float s[32][33];
    int tx = threadIdx.x & 31, ty = threadIdx.x >> 5;
    int r0 = blockIdx.y * 32, c0 = blockIdx.x * 32;
    #pragma unroll
    for (int j = 0; j < 4; j++)
        s[ty + 8*j][tx] = x[(LL)(r0 + ty + 8*j) * ldx + c0 + tx];
    __syncthreads();
    #pragma unroll
    for (int j = 0; j < 4; j++) {
        float v = s[tx][ty + 8*j];
        bf16 h, l; splitw(v, h, l);
        LL o = (LL)(c0 + ty + 8*j) * R + r0 + tx;
        hi[o] = h; lo[o] = l;
    }
}

__global__ __launch_bounds__(256)
void zfill(bf16* __restrict__ p, LL n)
{
    LL i = ((LL)blockIdx.x * 256 + threadIdx.x) * 2;
    if (i < n) *(uint32_t*)(p + i) = 0u;
}

__global__ __launch_bounds__(256)
void biascat(const float* __restrict__ bqd, const float* __restrict__ bkv,
             const float* __restrict__ bkr,
             const float* __restrict__ bqc, const float* __restrict__ bqr,
             const float* __restrict__ bkc, const float* __restrict__ bvc,
             float* __restrict__ b1, float* __restrict__ b2, float* __restrict__ b3)
{
    int i = blockIdx.x * 256 + threadIdx.x;
    if (i < N1) {
        float v = 0.0f;
        if (i < 1536) v = bqd[i];
        else if (i < 2048) v = bkv[i - 1536];
        else if (i < 2112) v = bkr[i - 2048];
        b1[i] = v;
    }
    if (i < 2048) b2[i] = bqc[i]; else if (i < 3072) b2[i] = bqr[i - 2048];
    if (i < 2048) b3[i] = bkc[i]; else if (i < 4096) b3[i] = bvc[i - 2048];
}

__global__ __launch_bounds__(256)
void rmsnorm_slice(const float* __restrict__ x, int ldx, int off,
                   const float* __restrict__ g, float* __restrict__ y, int dim)
{
    LL xb = (LL)blockIdx.x * ldx + off;
    LL yb = (LL)blockIdx.x * dim;
    int tid = threadIdx.x;
    float s = 0.0f;
    for (int i = tid; i < dim; i += 256) { float v = x[xb + i]; s += v * v; }
    __shared__ float red[256];
    red[tid] = s; __syncthreads();
    for (int st = 128; st > 0; st >>= 1) {
        if (tid < st) red[tid] += red[tid + st];
        __syncthreads();
    }
    float rs = rsqrtf(red[0] / (float)dim + 1e-6f);
    for (int i = tid; i < dim; i += 256)
        y[yb + i] = x[xb + i] * rs * g[i];
}

__global__ __launch_bounds__(256)
void rmsnorm_split(const float* __restrict__ x, int ldx, int off,
                   const float* __restrict__ g,
                   bf16* __restrict__ yh, bf16* __restrict__ yl, int dim)
{
    LL xb = (LL)blockIdx.x * ldx + off;
    LL yb = (LL)blockIdx.x * dim;
    int tid = threadIdx.x;
    float s = 0.0f;
    for (int i = tid; i < dim; i += 256) { float v = x[xb + i]; s += v * v; }
    __shared__ float red[256];
    red[tid] = s; __syncthreads();
    for (int st = 128; st > 0; st >>= 1) {
        if (tid < st) red[tid] += red[tid + st];
        __syncthreads();
    }
    float rs = rsqrtf(red[0] / (float)dim + 1e-6f);
    for (int i = tid; i < dim; i += 256) {
        float v = x[xb + i] * rs * g[i];
        bf16 h, l; splitw(v, h, l);
        yh[yb + i] = h; yl[yb + i] = l;
    }
}

// ---------------- pack with RoPE -> bf16 splits (q pre-scaled) ----------------
__global__ __launch_bounds__(256)
void pack_split(const float* __restrict__ qCR, const float* __restrict__ kvC,
                const float* __restrict__ krn, const float* __restrict__ freqs,
                bf16* __restrict__ qfh, bf16* __restrict__ qfl,
                bf16* __restrict__ kfh, bf16* __restrict__ kfl, float scale)
{
    int bs = blockIdx.x;
    int s  = bs & (SEQ - 1);
    LL qfb = (LL)bs * N_HEADS * D_QK;
    int tid = threadIdx.x;

    __shared__ float krs[D_R];
    if (tid < 32) {
        int i = tid;
        float a = krn[(LL)bs*D_R + 2*i];
        float b = krn[(LL)bs*D_R + 2*i + 1];
        float c  = freqs[(LL)s*D_R + 2*i];
        float sn = freqs[(LL)s*D_R + 2*i + 1];
        krs[2*i]   = a*c - b*sn;
        krs[2*i+1] = a*sn + b*c;
    }
    __syncthreads();

    for (int idx = tid; idx < N_HEADS*D_H; idx += 256) {
        int h = idx >> 7, d = idx & 127;
        float v = qCR[(LL)bs*3072 + idx] * scale;
        bf16 hh, ll; splitw(v, hh, ll);
        qfh[qfb + h*D_QK + d] = hh; qfl[qfb + h*D_QK + d] = ll;
    }
    for (int idx = tid; idx < N_HEADS*(D_R/2); idx += 256) {
        int h = idx >> 5, i = idx & 31;
        float a = qCR[(LL)bs*3072 + 2048 + h*D_R + 2*i];
        float b = qCR[(LL)bs*3072 + 2048 + h*D_R + 2*i + 1];
        float c  = freqs[(LL)s*D_R + 2*i];
        float sn = freqs[(LL)s*D_R + 2*i + 1];
        float v0 = (a*c - b*sn) * scale, v1 = (a*sn + b*c) * scale;
        bf16 hh, ll;
        splitw(v0, hh, ll);
        qfh[qfb + h*D_QK + D_H + 2*i] = hh;   qfl[qfb + h*D_QK + D_H + 2*i] = ll;
        splitw(v1, hh, ll);
        qfh[qfb + h*D_QK + D_H + 2*i+1] = hh; qfl[qfb + h*D_QK + D_H + 2*i+1] = ll;
    }
    for (int idx = tid; idx < N_HEADS*D_R; idx += 256) {
        int h = idx >> 6, d = idx & 63;
        bf16 hh, ll; splitw(krs[d], hh, ll);
        kfh[qfb + h*D_QK + d] = hh; kfl[qfb + h*D_QK + d] = ll;
    }
    for (int idx = tid; idx < N_HEADS*D_H; idx += 256) {
        int h = idx >> 7, d = idx & 127;
        float v = kvC[(LL)bs*4096 + idx];
        bf16 hh, ll; splitw(v, hh, ll);
        kfh[qfb + h*D_QK + D_R + d] = hh; kfl[qfb + h*D_QK + D_R + d] = ll;
    }
}

// ---------------- causal softmax + bf16 split emission (k < kLim only) ----------------
__global__ __launch_bounds__(256)
void softmax_kernel(float* __restrict__ w, bf16* __restrict__ wh, bf16* __restrict__ wl)
{
    LL row = blockIdx.x;
    int q = (int)(row & (SEQ - 1));
    float* base = w + row * (LL)SEQ;
    bf16* bh = wh + row * (LL)SEQ;
    bf16* bl = wl + row * (LL)SEQ;
    int tid = threadIdx.x;

    float vals[8];
    float mx = -INFINITY;
    #pragma unroll
    for (int it = 0; it < 8; it++) {
        int k = tid + it * 256;
        float v = -INFINITY;
        if (k <= q) v = base[k];
        vals[it] = v;
        mx = fmaxf(mx, v);
    }
    __shared__ float red[256];
    red[tid] = mx; __syncthreads();
    for (int st = 128; st > 0; st >>= 1) {
        if (tid < st) red[tid] = fmaxf(red[tid], red[tid + st]);
        __syncthreads();
    }
    mx = red[0]; __syncthreads();

    float sum = 0.0f;
    #pragma unroll
    for (int it = 0; it < 8; it++) {
        float e = (vals[it] == -INFINITY) ? 0.0f : __expf(vals[it] - mx);
        vals[it] = e;
        sum += e;
    }
    red[tid] = sum; __syncthreads();
    for (int st = 128; st > 0; st >>= 1) {
        if (tid < st) red[tid] += red[tid + st];
        __syncthreads();
    }
    float inv = 1.0f / red[0];

    int kLim = ((q >> 7) + 1) << 7;   // PV (128-tile) reads k < m0+128 = kLim
    #pragma unroll
    for (int it = 0; it < 8; it++) {
        int k = tid + it * 256;
        if (k < kLim) {
            float p = vals[it] * inv;
            base[k] = p;
            bf16 h, l; splitw(p, h, l);
            bh[k] = h; bl[k] = l;
        }
    }
}

// ---------------- host ----------------
#define SYMF(name) ({ void* p_; cudaGetSymbolAddress(&p_, name); (float*)p_; })
#define SYMB(name) ({ void* p_; cudaGetSymbolAddress(&p_, name); (bf16*)p_; })

#define G512_SMEM  196608
#define A128_SMEM  98304

extern "C" void kernel_launch(void* const* d_in, const int* in_sizes, int n_in,
                              void* d_out, int out_size)
{
    (void)in_sizes; (void)n_in; (void)out_size;
    const float* h       = (const float*)d_in[0];
    const float* freqs   = (const float*)d_in[1];
    const float* Wq_down = (const float*)d_in[3];
    const float* bq_down = (const float*)d_in[4];
    const float* gq_norm = (const float*)d_in[5];
    const float* Wqc     = (const float*)d_in[6];
    const float* bqc     = (const float*)d_in[7];
    const float* Wqr     = (const float*)d_in[8];
    const float* bqr     = (const float*)d_in[9];
    const float* Wkr     = (const float*)d_in[10];
    const float* bkr     = (const float*)d_in[11];
    const float* gkr     = (const float*)d_in[12];
    const float* Wkv     = (const float*)d_in[13];
    const float* bkv     = (const float*)d_in[14];
    const float* gkv     = (const float*)d_in[15];
    const float* Wkc     = (const float*)d_in[16];
    const float* bkc     = (const float*)d_in[17];
    const float* Wvc     = (const float*)d_in[18];
    const float* bvc     = (const float*)d_in[19];
    const float* Wo      = (const float*)d_in[20];
    const float* bo      = (const float*)d_in[21];

    float* out_h = (float*)d_out;
    float* w     = out_h + (LL)NTOK * D_MODEL;

    float* tmp12 = SYMF(g_tmp12);
    float* qCR = SYMF(g_qCR);
    float* kvC = SYMF(g_kvC);
    float* krn = SYMF(g_krn);
    float* b1 = SYMF(g_bias1); float* b2 = SYMF(g_bias2); float* b3 = SYMF(g_bias3);

    bf16 *h_hi = SYMB(g_h_hi), *h_lo = SYMB(g_h_lo);
    bf16 *WdT_hi = SYMB(g_WdT_hi), *WdT_lo = SYMB(g_WdT_lo);
    bf16 *WqcrT_hi = SYMB(g_WqcrT_hi), *WqcrT_lo = SYMB(g_WqcrT_lo);
    bf16 *WkvcT_hi = SYMB(g_WkvcT_hi), *WkvcT_lo = SYMB(g_WkvcT_lo);
    bf16 *WoT_hi  = SYMB(g_WoT_hi),  *WoT_lo  = SYMB(g_WoT_lo);
    bf16 *cQ_hi = SYMB(g_cQ_hi), *cQ_lo = SYMB(g_cQ_lo);
    bf16 *cKV_hi = SYMB(g_cKV_hi), *cKV_lo = SYMB(g_cKV_lo);
    bf16 *qf_hi = SYMB(g_qf_hi), *qf_lo = SYMB(g_qf_lo);
    bf16 *kf_hi = SYMB(g_kf_hi), *kf_lo = SYMB(g_kf_lo);
    bf16 *vCT_hi = SYMB(g_vCT_hi), *vCT_lo = SYMB(g_vCT_lo);
    bf16 *w_hi = SYMB(g_w_hi), *w_lo = SYMB(g_w_lo);
    bf16 *attn_hi = SYMB(g_attn_hi), *attn_lo = SYMB(g_attn_lo);

    cudaFuncSetAttribute((const void*)gemm512<0>, cudaFuncAttributeMaxDynamicSharedMemorySize, G512_SMEM);
    cudaFuncSetAttribute((const void*)attn128<true,false,1>,  cudaFuncAttributeMaxDynamicSharedMemorySize, A128_SMEM);
    cudaFuncSetAttribute((const void*)attn128<false,true,2>,  cudaFuncAttributeMaxDynamicSharedMemorySize, A128_SMEM);

    // prep
    biascat<<<(N1 + 255)/256 > 16 ? (N1+255)/256 : 16, 256>>>(
        bq_down, bkv, bkr, bqc, bqr, bkc, bvc, b1, b2, b3);
    split_rm<<<(LL)NTOK*D_MODEL/1024, 256>>>(h, h_hi, h_lo);
    split_tr<<<dim3(D_CQ/32, D_MODEL/32), 256>>>(Wq_down, D_CQ, WdT_hi, WdT_lo, D_MODEL, D_CQ);
    split_tr<<<dim3(D_C/32, D_MODEL/32), 256>>>(Wkv, D_C,
        WdT_hi + (LL)D_CQ*D_MODEL, WdT_lo + (LL)D_CQ*D_MODEL, D_MODEL, D_C);
    split_tr<<<dim3(D_R/32, D_MODEL/32), 256>>>(Wkr, D_R,
        WdT_hi + (LL)2048*D_MODEL, WdT_lo + (LL)2048*D_MODEL, D_MODEL, D_R);
    zfill<<<(64*D_MODEL/2 + 255)/256, 256>>>(WdT_hi + (LL)2112*D_MODEL, (LL)64*D_MODEL);
    zfill<<<(64*D_MODEL/2 + 255)/256, 256>>>(WdT_lo + (LL)2112*D_MODEL, (LL)64*D_MODEL);

    // merged: tmp12 = h @ [Wq_down | Wkv | Wkr | 0] + bias   (N=2176)
    gemm512<0><<<dim3(N1/128, NTOK/256), 512, G512_SMEM>>>(
        h_hi, h_lo, WdT_hi, WdT_lo, b1, tmp12, nullptr, nullptr,
        D_MODEL, D_MODEL, D_MODEL, N1, 0,0,0,0,0,0,1);

    // remaining weight splits
    split_tr<<<dim3(2048/32, D_CQ/32), 256>>>(Wqc, 2048, WqcrT_hi, WqcrT_lo, D_CQ, 2048);
    split_tr<<<dim3(1024/32, D_CQ/32), 256>>>(Wqr, 1024,
        WqcrT_hi + (LL)2048*D_CQ, WqcrT_lo + (LL)2048*D_CQ, D_CQ, 1024);
    split_tr<<<dim3(2048/32, D_C/32), 256>>>(Wkc, 2048, WkvcT_hi, WkvcT_lo, D_C, 2048);
    split_tr<<<dim3(2048/32, D_C/32), 256>>>(Wvc, 2048,
        WkvcT_hi + (LL)2048*D_C, WkvcT_lo + (LL)2048*D_C, D_C, 2048);
    split_tr<<<dim3(2048/32, 2048/32), 256>>>(Wo, 2048, WoT_hi, WoT_lo, 2048, 2048);

    // norms
    rmsnorm_split<<<NTOK, 256>>>(tmp12, N1, 0,    gq_norm, cQ_hi, cQ_lo, D_CQ);
    rmsnorm_split<<<NTOK, 256>>>(tmp12, N1, D_CQ, gkv,     cKV_hi, cKV_lo, D_C);
    rmsnorm_slice<<<NTOK, 256>>>(tmp12, N1, 2048, gkr, krn, D_R);

    // merged: qCR = cQ @ [Wqc | Wqr] + [bqc | bqr]   (N=3072)
    gemm512<0><<<dim3(3072/128, NTOK/256), 512, G512_SMEM>>>(
        cQ_hi, cQ_lo, WqcrT_hi, WqcrT_lo, b2, qCR, nullptr, nullptr,
        D_CQ, D_CQ, D_CQ, 3072, 0,0,0,0,0,0,1);

    // merged: kvC = cKV @ [Wkc | Wvc] + [bkc | bvc]   (N=4096)
    gemm512<0><<<dim3(4096/128, NTOK/256), 512, G512_SMEM>>>(
        cKV_hi, cKV_lo, WkvcT_hi, WkvcT_lo, b3, kvC, nullptr, nullptr,
        D_C, D_C, D_C, 4096, 0,0,0,0,0,0,1);

    // vC^T splits
    split_tr<<<dim3(2048/32, NTOK/32), 256>>>(kvC + 2048, 4096, vCT_hi, vCT_lo, NTOK, 2048);

    // pack + RoPE (q pre-scaled)
    pack_split<<<NTOK, 256>>>(qCR, kvC, krn, freqs, qf_hi, qf_lo, kf_hi, kf_lo,
                              1.0f / sqrtf((float)D_QK));

    // scores = q k^T (causal; upper tiles zero-fill w)
    {
        LL soQK = (LL)SEQ * N_HEADS * D_QK, siQK = D_QK;
        LL soW  = (LL)N_HEADS * SEQ * SEQ,  siW  = (LL)SEQ * SEQ;
        attn128<true,false,1><<<dim3(SEQ/128, SEQ/128, BSZ*N_HEADS), 256, A128_SMEM>>>(
            qf_hi, qf_lo, kf_hi, kf_lo, w, nullptr, nullptr,
            D_QK, N_HEADS*D_QK, N_HEADS*D_QK, SEQ,
            soQK, siQK, soQK, siQK, soW, siW, N_HEADS);
    }

    // softmax (fp32 + bf16 splits, k < kLim at 128-granularity)
    softmax_kernel<<<(LL)BSZ*N_HEADS*SEQ, 256>>>(w, w_hi, w_lo);

    // PV: attn = w @ vC, 128-row tiles, K clipped at m0+128, bf16-split out
    {
        LL soW = (LL)N_HEADS * SEQ * SEQ, siW = (LL)SEQ * SEQ;
        LL soB = 2048;
        LL siB = (LL)D_H * NTOK;
        LL soC = (LL)SEQ * 2048, siC = D_H;
        attn128<false,true,2><<<dim3(D_H/128, SEQ/128, BSZ*N_HEADS), 256, A128_SMEM>>>(
            w_hi, w_lo, vCT_hi, vCT_lo, nullptr, attn_hi, attn_lo,
            SEQ, SEQ, NTOK, 2048,
            soW, siW, soB, siB, soC, siC, N_HEADS);
    }

    // h_out = attn @ Wo + bo
    gemm512<0><<<dim3(2048/128, NTOK/256), 512, G512_SMEM>>>(
        attn_hi, attn_lo, WoT_hi, WoT_lo, bo, out_h, nullptr, nullptr,
        2048, 2048, 2048, 2048, 0,0,0,0,0,0,1);
}

// round 14
// speedup vs baseline: 1.0462x; 1.0355x over previous
#include <cuda_runtime.h>
#include <cuda_bf16.h>
#include <math.h>
#include <stdint.h>

#define D_MODEL 2048
#define N_HEADS 16
#define D_CQ    1536
#define D_C     512
#define D_H     128
#define D_R     64
#define BSZ     4
#define SEQ     2048
#define NTOK    (BSZ*SEQ)
#define D_QK    (D_H + D_R)
#define LL long long

#define SW128(o) ((o) ^ (((o) >> 3) & 0x70))
#define SW64(o)  ((o) ^ (((o) >> 2) & 0x30))

#define N1 2176   // merged first-GEMM N: Wqd(1536) | Wkv(512) | Wkr(64) | pad(64)

typedef __nv_bfloat16 bf16;

// ---------------- scratch ----------------
__device__ float g_tmp12[(LL)NTOK * N1];
__device__ float g_qCR [(LL)NTOK * 3072];
__device__ float g_kvC [(LL)NTOK * 4096];
__device__ float g_krn [(LL)NTOK * D_R];
__device__ bf16 g_h_hi[(LL)NTOK * D_MODEL],      g_h_lo[(LL)NTOK * D_MODEL];
__device__ bf16 g_WdT_hi[(LL)N1 * D_MODEL],      g_WdT_lo[(LL)N1 * D_MODEL];
__device__ bf16 g_WqcrT_hi[(LL)3072 * D_CQ],     g_WqcrT_lo[(LL)3072 * D_CQ];
__device__ bf16 g_WkvcT_hi[(LL)4096 * D_C],      g_WkvcT_lo[(LL)4096 * D_C];
__device__ bf16 g_WoT_hi[(LL)2048 * 2048],       g_WoT_lo[(LL)2048 * 2048];
__device__ bf16 g_cQ_hi[(LL)NTOK * D_CQ],        g_cQ_lo[(LL)NTOK * D_CQ];
__device__ bf16 g_cKV_hi[(LL)NTOK * D_C],        g_cKV_lo[(LL)NTOK * D_C];
__device__ bf16 g_qf_hi[(LL)NTOK * N_HEADS*D_QK], g_qf_lo[(LL)NTOK * N_HEADS*D_QK];
__device__ bf16 g_kf_hi[(LL)NTOK * N_HEADS*D_QK], g_kf_lo[(LL)NTOK * N_HEADS*D_QK];
__device__ bf16 g_vCT_hi[(LL)2048 * NTOK],       g_vCT_lo[(LL)2048 * NTOK];
__device__ bf16 g_w_hi[(LL)BSZ*N_HEADS*SEQ*SEQ], g_w_lo[(LL)BSZ*N_HEADS*SEQ*SEQ];
__device__ bf16 g_attn_hi[(LL)NTOK * 2048],      g_attn_lo[(LL)NTOK * 2048];
__device__ float g_bias1[N1];
__device__ float g_bias2[3072];
__device__ float g_bias3[4096];

// ---------------- helpers ----------------
__device__ __forceinline__ uint32_t smem_u32(const void* p) {
    uint32_t a;
    asm("{ .reg .u64 t; cvta.to.shared.u64 t, %1; cvt.u32.u64 %0, t; }" : "=r"(a) : "l"(p));
    return a;
}
#define CP16(d, s) asm volatile("cp.async.cg.shared.global [%0], [%1], 16;" :: "r"(d), "l"(s))
#define CP_COMMIT() asm volatile("cp.async.commit_group;" ::: "memory")
#define CP_WAIT1() asm volatile("cp.async.wait_group 1;" ::: "memory")
#define CP_WAIT0() asm volatile("cp.async.wait_group 0;" ::: "memory")

__device__ __forceinline__ void ldsm_x4(uint32_t addr, uint32_t& r0, uint32_t& r1,
                                        uint32_t& r2, uint32_t& r3) {
    asm volatile("ldmatrix.sync.aligned.m8n8.x4.shared.b16 {%0,%1,%2,%3}, [%4];"
                 : "=r"(r0), "=r"(r1), "=r"(r2), "=r"(r3) : "r"(addr));
}
__device__ __forceinline__ void mma_bf16(float* c, const uint32_t* a,
                                         uint32_t b0, uint32_t b1) {
    asm volatile(
        "mma.sync.aligned.m16n8k16.row.col.f32.bf16.bf16.f32 "
        "{%0,%1,%2,%3}, {%4,%5,%6,%7}, {%8,%9}, {%0,%1,%2,%3};"
        : "+f"(c[0]), "+f"(c[1]), "+f"(c[2]), "+f"(c[3])
        : "r"(a[0]), "r"(a[1]), "r"(a[2]), "r"(a[3]), "r"(b0), "r"(b1));
}
__device__ __forceinline__ void splitw(float v, bf16& hi, bf16& lo) {
    hi = __float2bfloat16(v);
    lo = __float2bfloat16(v - __bfloat162float(hi));
}
__device__ __forceinline__ void split2pack(float f0, float f1, uint32_t& hp, uint32_t& lp) {
    bf16 h0, l0, h1, l1;
    splitw(f0, h0, l0); splitw(f1, h1, l1);
    hp = ((uint32_t)__bfloat16_as_ushort(h1) << 16) | __bfloat16_as_ushort(h0);
    lp = ((uint32_t)__bfloat16_as_ushort(l1) << 16) | __bfloat16_as_ushort(l0);
}

// ============ gemm512 device body: 256x128 tile, 512 threads, BK=64, 2-stage ============
__device__ __forceinline__
void gemm512_body(const bf16* __restrict__ Ah_b, const bf16* __restrict__ Al_b,
                  const bf16* __restrict__ Bh_b, const bf16* __restrict__ Bl_b,
                  const float* __restrict__ bias, float* __restrict__ Cb,
                  bf16* __restrict__ Hb, bf16* __restrict__ Lb,
                  int m0, int n0, int K, int lda, int ldb, int ldc, int epi)
{
    int KT = K >> 6;

    extern __shared__ char sm[];
    uint32_t sb = smem_u32(sm);

    int tid = threadIdx.x;
    int wid = tid >> 5, lane = tid & 31;
    int wm = (wid & 7) << 5;
    int wn = (wid >> 3) << 6;
    int g = lane >> 3, r = lane & 7;
    int aro = ((g & 1) << 3) + r, aco = (g >> 1) << 4;
    int bro = ((g >> 1) << 3) + r, bco = (g & 1) << 4;

    float acc[2][8][4];
    #pragma unroll
    for (int i = 0; i < 2; i++)
        #pragma unroll
        for (int j = 0; j < 8; j++)
            #pragma unroll
            for (int t = 0; t < 4; t++) acc[i][j][t] = 0.0f;

    #define LOAD_STG(s, k0) do {                                               \
        uint32_t st = sb + (uint32_t)(s) * 98304u;                             \
        _Pragma("unroll")                                                      \
        for (int i = 0; i < 4; i++) {                                          \
            int idx = tid + (i << 9);                                          \
            int row = idx >> 3, c = idx & 7;                                   \
            uint32_t d = st + SW128((uint32_t)((row << 7) + (c << 4)));        \
            LL go = (LL)(m0 + row) * lda + (k0) + (c << 3);                    \
            CP16(d,          Ah_b + go);                                       \
            CP16(d + 32768u, Al_b + go);                                       \
        }                                                                      \
        _Pragma("unroll")                                                      \
        for (int i = 0; i < 2; i++) {                                          \
            int idx = tid + (i << 9);                                          \
            int row = idx >> 3, c = idx & 7;                                   \
            uint32_t d = st + 65536u + SW128((uint32_t)((row << 7) + (c << 4)));\
            LL go = (LL)(n0 + row) * ldb + (k0) + (c << 3);                    \
            CP16(d,          Bh_b + go);                                       \
            CP16(d + 16384u, Bl_b + go);                                       \
        }                                                                      \
    } while (0)

    LOAD_STG(0, 0);
    CP_COMMIT();

    for (int kt = 0; kt < KT; kt++) {
        CP_WAIT0();
        __syncthreads();
        if (kt + 1 < KT) {
            LOAD_STG((kt + 1) & 1, (kt + 1) << 6);
            CP_COMMIT();
        }

        uint32_t aB = sb + (uint32_t)(kt & 1) * 98304u;
        uint32_t bB = aB + 65536u;

        #pragma unroll
        for (int ks = 0; ks < 4; ks++) {
            int kb = ks << 5;
            uint32_t ah[2][4], al[2][4];
            #pragma unroll
            for (int mf = 0; mf < 2; mf++) {
                uint32_t off = SW128((uint32_t)((wm + (mf << 4) + aro) * 128 + kb + aco));
                ldsm_x4(aB + off,          ah[mf][0], ah[mf][1], ah[mf][2], ah[mf][3]);
                ldsm_x4(aB + 32768u + off, al[mf][0], al[mf][1], al[mf][2], al[mf][3]);
            }
            #pragma unroll
            for (int ng = 0; ng < 4; ng++) {
                uint32_t off = SW128((uint32_t)((wn + (ng << 4) + bro) * 128 + kb + bco));
                uint32_t bh0, bh1, bh2, bh3, bl0, bl1, bl2, bl3;
                ldsm_x4(bB + off,          bh0, bh1, bh2, bh3);
                ldsm_x4(bB + 16384u + off, bl0, bl1, bl2, bl3);
                #pragma unroll
                for (int mf = 0; mf < 2; mf++) {
                    float* c0 = acc[mf][(ng << 1)];
                    float* c1 = acc[mf][(ng << 1) + 1];
                    mma_bf16(c0, ah[mf], bh0, bh1);
                    mma_bf16(c1, ah[mf], bh2, bh3);
                    mma_bf16(c0, ah[mf], bl0, bl1);
                    mma_bf16(c1, ah[mf], bl2, bl3);
                    mma_bf16(c0, al[mf], bh0, bh1);
                    mma_bf16(c1, al[mf], bh2, bh3);
                }
            }
        }
    }

    #pragma unroll
    for (int mf = 0; mf < 2; mf++) {
        int row = m0 + wm + (mf << 4) + (lane >> 2);
        #pragma unroll
        for (int nf = 0; nf < 8; nf++) {
            int col = n0 + wn + (nf << 3) + ((lane & 3) << 1);
            float* a = acc[mf][nf];
            if (epi == 0) {
                float bx = bias[col], by = bias[col + 1];
                *(float2*)(Cb + (LL)row * ldc + col)       = make_float2(a[0] + bx, a[1] + by);
                *(float2*)(Cb + (LL)(row + 8) * ldc + col) = make_float2(a[2] + bx, a[3] + by);
            } else {
                uint32_t hp, lp;
                split2pack(a[0], a[1], hp, lp);
                *(uint32_t*)(Hb + (LL)row * ldc + col) = hp;
                *(uint32_t*)(Lb + (LL)row * ldc + col) = lp;
                split2pack(a[2], a[3], hp, lp);
                *(uint32_t*)(Hb + (LL)(row + 8) * ldc + col) = hp;
                *(uint32_t*)(Lb + (LL)(row + 8) * ldc + col) = lp;
            }
        }
    }
}

// single GEMM wrapper (EPI 0 = fp32+bias, 2 = bf16 splits)
template<int EPI>
__global__ __launch_bounds__(512, 1)
void gemm512(const bf16* __restrict__ Ahi, const bf16* __restrict__ Alo,
             const bf16* __restrict__ Bhi, const bf16* __restrict__ Blo,
             const float* __restrict__ bias,
             float* __restrict__ C, bf16* __restrict__ Chi, bf16* __restrict__ Clo,
             int K, int lda, int ldb, int ldc)
{
    gemm512_body(Ahi, Alo, Bhi, Blo, bias, C, Chi, Clo,
                 blockIdx.y * 256, blockIdx.x * 128, K, lda, ldb, ldc, EPI);
}

// dual GEMM: column strips [0,NX1) -> GEMM 1, [NX1, NX1+NX2) -> GEMM 2
__global__ __launch_bounds__(512, 1)
void gemm512dual(const bf16* A1h, const bf16* A1l, const bf16* B1h, const bf16* B1l,
                 const float* b1, float* C1, int K1, int ldc1, int NX1,
                 const bf16* A2h, const bf16* A2l, const bf16* B2h, const bf16* B2l,
                 const float* b2, float* C2, int K2, int ldc2)
{
    int xc = blockIdx.x;
    if (xc < NX1) {
        gemm512_body(A1h, A1l, B1h, B1l, b1, C1, nullptr, nullptr,
                     blockIdx.y * 256, xc * 128, K1, K1, K1, ldc1, 0);
    } else {
        gemm512_body(A2h, A2l, B2h, B2l, b2, C2, nullptr, nullptr,
                     blockIdx.y * 256, (xc - NX1) * 128, K2, K2, K2, ldc2, 0);
    }
}

// ============ attn128: bf16x3, 128x128, BK=32, 3-stage, 2 CTAs/SM ============
template<bool CAUSAL, bool KCLIP, int EPI>   // EPI: 1=fp32, 2=bf16 splits
__global__ __launch_bounds__(256, 2)
void attn128(const bf16* __restrict__ Ahi, const bf16* __restrict__ Alo,
             const bf16* __restrict__ Bhi, const bf16* __restrict__ Blo,
             float* __restrict__ C, bf16* __restrict__ Chi, bf16* __restrict__ Clo,
             int K, int lda, int ldb, int ldc,
             LL soA, LL siA, LL soB, LL siB, LL soC, LL siC, int IC)
{
    int m0 = blockIdx.y * 128;
    int n0 = blockIdx.x * 128;
    int z = blockIdx.z;
    LL zo = z / IC, zi = z % IC;
    int tid = threadIdx.x;

    if (CAUSAL && n0 > m0) {
        float* Wb = C + zo*soC + zi*siC;
        float4 zz = make_float4(0.f, 0.f, 0.f, 0.f);
        #pragma unroll
        for (int i = 0; i < 16; i++) {
            int idx = tid + (i << 8);
            int row = idx >> 5, c4 = (idx & 31) << 2;
            *(float4*)(Wb + (LL)(m0 + row) * ldc + n0 + c4) = zz;
        }
        return;
    }

    const bf16* Ah_b = Ahi + zo*soA + zi*siA;
    const bf16* Al_b = Alo + zo*soA + zi*siA;
    const bf16* Bh_b = Bhi + zo*soB + zi*siB;
    const bf16* Bl_b = Blo + zo*soB + zi*siB;

    int Keff = KCLIP ? (m0 + 128 < K ? m0 + 128 : K) : K;
    int KT = Keff >> 5;

    extern __shared__ char sm[];
    uint32_t sb = smem_u32(sm);

    int wid = tid >> 5, lane = tid & 31;
    int wm = (wid & 3) << 5;
    int wn = (wid >> 2) << 6;
    int g = lane >> 3, r = lane & 7;
    int aro = ((g & 1) << 3) + r, aco = (g >> 1) << 4;
    int bro = ((g >> 1) << 3) + r, bco = (g & 1) << 4;

    float acc[2][8][4];
    #pragma unroll
    for (int i = 0; i < 2; i++)
        #pragma unroll
        for (int j = 0; j < 8; j++)
            #pragma unroll
            for (int t = 0; t < 4; t++) acc[i][j][t] = 0.0f;

    #define SLOAD(s, k0) do {                                                  \
        uint32_t st = sb + (uint32_t)(s) * 32768u;                             \
        _Pragma("unroll")                                                      \
        for (int i = 0; i < 2; i++) {                                          \
            int idx = tid + (i << 8);                                          \
            int row = idx >> 2, c = (idx & 3) << 4;                            \
            uint32_t sw = SW64((uint32_t)((row << 6) + c));                    \
            LL goA = (LL)(m0 + row) * lda + (k0) + ((idx & 3) << 3);           \
            LL goB = (LL)(n0 + row) * ldb + (k0) + ((idx & 3) << 3);           \
            CP16(st + sw,           Ah_b + goA);                               \
            CP16(st + 8192u  + sw,  Al_b + goA);                               \
            CP16(st + 16384u + sw,  Bh_b + goB);                               \
            CP16(st + 24576u + sw,  Bl_b + goB);                               \
        }                                                                      \
    } while (0)

    SLOAD(0, 0);  CP_COMMIT();
    SLOAD(1, 32); CP_COMMIT();

    int cs = 0, ls = 2;
    for (int kt = 0; kt < KT; kt++) {
        CP_WAIT1();
        __syncthreads();
        if (kt + 2 < KT) {
            SLOAD(ls, (kt + 2) << 5);
        }
        CP_COMMIT();
        ls++; if (ls == 3) ls = 0;

        uint32_t aB = sb + (uint32_t)cs * 32768u;
        uint32_t bB = aB + 16384u;

        #pragma unroll
        for (int ks = 0; ks < 2; ks++) {
            int kb = ks << 5;
            uint32_t ah[2][4], al[2][4];
            #pragma unroll
            for (int mf = 0; mf < 2; mf++) {
                uint32_t off = SW64((uint32_t)((wm + (mf << 4) + aro) * 64 + kb + aco));
                ldsm_x4(aB + off,         ah[mf][0], ah[mf][1], ah[mf][2], ah[mf][3]);
                ldsm_x4(aB + 8192u + off, al[mf][0], al[mf][1], al[mf][2], al[mf][3]);
            }
            #pragma unroll
            for (int ng = 0; ng < 4; ng++) {
                uint32_t off = SW64((uint32_t)((wn + (ng << 4) + bro) * 64 + kb + bco));
                uint32_t bh0, bh1, bh2, bh3, bl0, bl1, bl2, bl3;
                ldsm_x4(bB + off,         bh0, bh1, bh2, bh3);
                ldsm_x4(bB + 8192u + off, bl0, bl1, bl2, bl3);
                #pragma unroll
                for (int mf = 0; mf < 2; mf++) {
                    float* c0 = acc[mf][(ng << 1)];
                    float* c1 = acc[mf][(ng << 1) + 1];
                    mma_bf16(c0, ah[mf], bh0, bh1);
                    mma_bf16(c1, ah[mf], bh2, bh3);
                    mma_bf16(c0, ah[mf], bl0, bl1);
                    mma_bf16(c1, ah[mf], bl2, bl3);
                    mma_bf16(c0, al[mf], bh0, bh1);
                    mma_bf16(c1, al[mf], bh2, bh3);
                }
            }
        }
        cs++; if (cs == 3) cs = 0;
    }

    #pragma unroll
    for (int mf = 0; mf < 2; mf++) {
        int row = m0 + wm + (mf << 4) + (lane >> 2);
        #pragma unroll
        for (int nf = 0; nf < 8; nf++) {
            int col = n0 + wn + (nf << 3) + ((lane & 3) << 1);
            float* a = acc[mf][nf];
            if (EPI == 1) {
                float* Cb = C + zo*soC + zi*siC;
                *(float2*)(Cb + (LL)row * ldc + col)       = make_float2(a[0], a[1]);
                *(float2*)(Cb + (LL)(row + 8) * ldc + col) = make_float2(a[2], a[3]);
            } else {
                bf16* Hb = Chi + zo*soC + zi*siC;
                bf16* Lb = Clo + zo*soC + zi*siC;
                uint32_t hp, lp;
                split2pack(a[0], a[1], hp, lp);
                *(uint32_t*)(Hb + (LL)row * ldc + col) = hp;
                *(uint32_t*)(Lb + (LL)row * ldc + col) = lp;
                split2pack(a[2], a[3], hp, lp);
                *(uint32_t*)(Hb + (LL)(row + 8) * ldc + col) = hp;
                *(uint32_t*)(Lb + (LL)(row + 8) * ldc + col) = lp;
            }
        }
    }
}

// ---------------- split kernels ----------------
__global__ __launch_bounds__(256)
void split_rm(const float* __restrict__ x, bf16* __restrict__ hi, bf16* __restrict__ lo)
{
    LL base = ((LL)blockIdx.x * 256 + threadIdx.x) * 4;
    float4 v = *(const float4*)(x + base);
    bf16 h[4], l[4];
    splitw(v.x, h[0], l[0]); splitw(v.y, h[1], l[1]);
    splitw(v.z, h[2], l[2]); splitw(v.w, h[3], l[3]);
    *(uint2*)(hi + base) = *(uint2*)h;
    *(uint2*)(lo + base) = *(uint2*)l;
}

__global__ __launch_bounds__(256)
void split_tr(const float* __restrict__ x, int ldx,
              bf16* __restrict__ hi, bf16* __restrict__ lo, int R, int C)
{
    __shared__ float s[32][33];
    int tx = threadIdx.x & 31, ty = threadIdx.x >> 5;
    int r0 = blockIdx.y * 32, c0 = blockIdx.x * 32;
    #pragma unroll
    for (int j = 0; j < 4; j++)
        s[ty + 8*j][tx] = x[(LL)(r0 + ty + 8*j) * ldx + c0 + tx];
    __syncthreads();
    #pragma unroll
    for (int j = 0; j < 4; j++) {
        float v = s[tx][ty + 8*j];
        bf16 h, l; splitw(v, h, l);
        LL o = (LL)(c0 + ty + 8*j) * R + r0 + tx;
        hi[o] = h; lo[o] = l;
    }
}

__global__ __launch_bounds__(256)
void zfill(bf16* __restrict__ p, LL n)
{
    LL i = ((LL)blockIdx.x * 256 + threadIdx.x) * 2;
    if (i < n) *(uint32_t*)(p + i) = 0u;
}

__global__ __launch_bounds__(256)
void biascat(const float* __restrict__ bqd, const float* __restrict__ bkv,
             const float* __restrict__ bkr,
             const float* __restrict__ bqc, const float* __restrict__ bqr,
             const float* __restrict__ bkc, const float* __restrict__ bvc,
             float* __restrict__ b1, float* __restrict__ b2, float* __restrict__ b3)
{
    int i = blockIdx.x * 256 + threadIdx.x;
    if (i < N1) {
        float v = 0.0f;
        if (i < 1536) v = bqd[i];
        else if (i < 2048) v = bkv[i - 1536];
        else if (i < 2112) v = bkr[i - 2048];
        b1[i] = v;
    }
    if (i < 2048) b2[i] = bqc[i]; else if (i < 3072) b2[i] = bqr[i - 2048];
    if (i < 2048) b3[i] = bkc[i]; else if (i < 4096) b3[i] = bvc[i - 2048];
}

// ---------------- fused rmsnorm over all three slices of tmp12 ----------------
__global__ __launch_bounds__(256)
void rmsnorm_all(const float* __restrict__ x,
                 const float* __restrict__ gq, const float* __restrict__ gkv,
                 const float* __restrict__ gkr,
                 bf16* __restrict__ cQh, bf16* __restrict__ cQl,
                 bf16* __restrict__ cKVh, bf16* __restrict__ cKVl,
                 float* __restrict__ krn)
{
    LL xb = (LL)blockIdx.x * N1;
    int tid = threadIdx.x;
    __shared__ float red[256];

    // slice 1: cQ [0, 1536)
    float s = 0.0f;
    #pragma unroll
    for (int i = 0; i < 6; i++) { float v = x[xb + tid + (i << 8)]; s += v * v; }
    red[tid] = s; __syncthreads();
    for (int st = 128; st > 0; st >>= 1) {
        if (tid < st) red[tid] += red[tid + st];
        __syncthreads();
    }
    float rs = rsqrtf(red[0] / (float)D_CQ + 1e-6f);
    LL yb = (LL)blockIdx.x * D_CQ;
    #pragma unroll
    for (int i = 0; i < 6; i++) {
        int idx = tid + (i << 8);
        float v = x[xb + idx] * rs * gq[idx];
        bf16 h, l; splitw(v, h, l);
        cQh[yb + idx] = h; cQl[yb + idx] = l;
    }
    __syncthreads();

    // slice 2: cKV [1536, 2048)
    s = 0.0f;
    #pragma unroll
    for (int i = 0; i < 2; i++) { float v = x[xb + 1536 + tid + (i << 8)]; s += v * v; }
    red[tid] = s; __syncthreads();
    for (int st = 128; st > 0; st >>= 1) {
        if (tid < st) red[tid] += red[tid + st];
        __syncthreads();
    }
    rs = rsqrtf(red[0] / (float)D_C + 1e-6f);
    yb = (LL)blockIdx.x * D_C;
    #pragma unroll
    for (int i = 0; i < 2; i++) {
        int idx = tid + (i << 8);
        float v = x[xb + 1536 + idx] * rs * gkv[idx];
        bf16 h, l; splitw(v, h, l);
        cKVh[yb + idx] = h; cKVl[yb + idx] = l;
    }
    __syncthreads();

    // slice 3: kr [2048, 2112)
    float v3 = (tid < D_R) ? x[xb + 2048 + tid] : 0.0f;
    red[tid] = v3 * v3; __syncthreads();
    for (int st = 128; st > 0; st >>= 1) {
        if (tid < st) red[tid] += red[tid + st];
        __syncthreads();
    }
    rs = rsqrtf(red[0] / (float)D_R + 1e-6f);
    if (tid < D_R)
        krn[(LL)blockIdx.x * D_R + tid] = v3 * rs * gkr[tid];
}

// ---------------- pack with RoPE -> bf16 splits (q pre-scaled) ----------------
__global__ __launch_bounds__(256)
void pack_split(const float* __restrict__ qCR, const float* __restrict__ kvC,
                const float* __restrict__ krn, const float* __restrict__ freqs,
                bf16* __restrict__ qfh, bf16* __restrict__ qfl,
                bf16* __restrict__ kfh, bf16* __restrict__ kfl, float scale)
{
    int bs = blockIdx.x;
    int s  = bs & (SEQ - 1);
    LL qfb = (LL)bs * N_HEADS * D_QK;
    int tid = threadIdx.x;

    __shared__ float krs[D_R];
    if (tid < 32) {
        int i = tid;
        float a = krn[(LL)bs*D_R + 2*i];
        float b = krn[(LL)bs*D_R + 2*i + 1];
        float c  = freqs[(LL)s*D_R + 2*i];
        float sn = freqs[(LL)s*D_R + 2*i + 1];
        krs[2*i]   = a*c - b*sn;
        krs[2*i+1] = a*sn + b*c;
    }
    __syncthreads();

    for (int idx = tid; idx < N_HEADS*D_H; idx += 256) {
        int h = idx >> 7, d = idx & 127;
        float v = qCR[(LL)bs*3072 + idx] * scale;
        bf16 hh, ll; splitw(v, hh, ll);
        qfh[qfb + h*D_QK + d] = hh; qfl[qfb + h*D_QK + d] = ll;
    }
    for (int idx = tid; idx < N_HEADS*(D_R/2); idx += 256) {
        int h = idx >> 5, i = idx & 31;
        float a = qCR[(LL)bs*3072 + 2048 + h*D_R + 2*i];
        float b = qCR[(LL)bs*3072 + 2048 + h*D_R + 2*i + 1];
        float c  = freqs[(LL)s*D_R + 2*i];
        float sn = freqs[(LL)s*D_R + 2*i + 1];
        float v0 = (a*c - b*sn) * scale, v1 = (a*sn + b*c) * scale;
        bf16 hh, ll;
        splitw(v0, hh, ll);
        qfh[qfb + h*D_QK + D_H + 2*i] = hh;   qfl[qfb + h*D_QK + D_H + 2*i] = ll;
        splitw(v1, hh, ll);
        qfh[qfb + h*D_QK + D_H + 2*i+1] = hh; qfl[qfb + h*D_QK + D_H + 2*i+1] = ll;
    }
    for (int idx = tid; idx < N_HEADS*D_R; idx += 256) {
        int h = idx >> 6, d = idx & 63;
        bf16 hh, ll; splitw(krs[d], hh, ll);
        kfh[qfb + h*D_QK + d] = hh; kfl[qfb + h*D_QK + d] = ll;
    }
    for (int idx = tid; idx < N_HEADS*D_H; idx += 256) {
        int h = idx >> 7, d = idx & 127;
        float v = kvC[(LL)bs*4096 + idx];
        bf16 hh, ll; splitw(v, hh, ll);
        kfh[qfb + h*D_QK + D_R + d] = hh; kfl[qfb + h*D_QK + D_R + d] = ll;
    }
}

// ---------------- causal softmax + bf16 split emission (k < kLim only) ----------------
__global__ __launch_bounds__(256)
void softmax_kernel(float* __restrict__ w, bf16* __restrict__ wh, bf16* __restrict__ wl)
{
    LL row = blockIdx.x;
    int q = (int)(row & (SEQ - 1));
    float* base = w + row * (LL)SEQ;
    bf16* bh = wh + row * (LL)SEQ;
    bf16* bl = wl + row * (LL)SEQ;
    int tid = threadIdx.x;

    float vals[8];
    float mx = -INFINITY;
    #pragma unroll
    for (int it = 0; it < 8; it++) {
        int k = tid + it * 256;
        float v = -INFINITY;
        if (k <= q) v = base[k];
        vals[it] = v;
        mx = fmaxf(mx, v);
    }
    __shared__ float red[256];
    red[tid] = mx; __syncthreads();
    for (int st = 128; st > 0; st >>= 1) {
        if (tid < st) red[tid] = fmaxf(red[tid], red[tid + st]);
        __syncthreads();
    }
    mx = red[0]; __syncthreads();

    float sum = 0.0f;
    #pragma unroll
    for (int it = 0; it < 8; it++) {
        float e = (vals[it] == -INFINITY) ? 0.0f : __expf(vals[it] - mx);
        vals[it] = e;
        sum += e;
    }
    red[tid] = sum; __syncthreads();
    for (int st = 128; st > 0; st >>= 1) {
        if (tid < st) red[tid] += red[tid + st];
        __syncthreads();
    }
    float inv = 1.0f / red[0];

    int kLim = ((q >> 7) + 1) << 7;
    #pragma unroll
    for (int it = 0; it < 8; it++) {
        int k = tid + it * 256;
        if (k < kLim) {
            float p = vals[it] * inv;
            base[k] = p;
            bf16 h, l; splitw(p, h, l);
            bh[k] = h; bl[k] = l;
        }
    }
}

// ---------------- host ----------------
#define SYMF(name) ({ void* p_; cudaGetSymbolAddress(&p_, name); (float*)p_; })
#define SYMB(name) ({ void* p_; cudaGetSymbolAddress(&p_, name); (bf16*)p_; })

#define G512_SMEM  196608
#define A128_SMEM  98304

extern "C" void kernel_launch(void* const* d_in, const int* in_sizes, int n_in,
                              void* d_out, int out_size)
{
    (void)in_sizes; (void)n_in; (void)out_size;
    const float* h       = (const float*)d_in[0];
    const float* freqs   = (const float*)d_in[1];
    const float* Wq_down = (const float*)d_in[3];
    const float* bq_down = (const float*)d_in[4];
    const float* gq_norm = (const float*)d_in[5];
    const float* Wqc     = (const float*)d_in[6];
    const float* bqc     = (const float*)d_in[7];
    const float* Wqr     = (const float*)d_in[8];
    const float* bqr     = (const float*)d_in[9];
    const float* Wkr     = (const float*)d_in[10];
    const float* bkr     = (const float*)d_in[11];
    const float* gkr     = (const float*)d_in[12];
    const float* Wkv     = (const float*)d_in[13];
    const float* bkv     = (const float*)d_in[14];
    const float* gkv     = (const float*)d_in[15];
    const float* Wkc     = (const float*)d_in[16];
    const float* bkc     = (const float*)d_in[17];
    const float* Wvc     = (const float*)d_in[18];
    const float* bvc     = (const float*)d_in[19];
    const float* Wo      = (const float*)d_in[20];
    const float* bo      = (const float*)d_in[21];

    float* out_h = (float*)d_out;
    float* w     = out_h + (LL)NTOK * D_MODEL;

    float* tmp12 = SYMF(g_tmp12);
    float* qCR = SYMF(g_qCR);
    float* kvC = SYMF(g_kvC);
    float* krn = SYMF(g_krn);
    float* b1 = SYMF(g_bias1); float* b2 = SYMF(g_bias2); float* b3 = SYMF(g_bias3);

    bf16 *h_hi = SYMB(g_h_hi), *h_lo = SYMB(g_h_lo);
    bf16 *WdT_hi = SYMB(g_WdT_hi), *WdT_lo = SYMB(g_WdT_lo);
    bf16 *WqcrT_hi = SYMB(g_WqcrT_hi), *WqcrT_lo = SYMB(g_WqcrT_lo);
    bf16 *WkvcT_hi = SYMB(g_WkvcT_hi), *WkvcT_lo = SYMB(g_WkvcT_lo);
    bf16 *WoT_hi  = SYMB(g_WoT_hi),  *WoT_lo  = SYMB(g_WoT_lo);
    bf16 *cQ_hi = SYMB(g_cQ_hi), *cQ_lo = SYMB(g_cQ_lo);
    bf16 *cKV_hi = SYMB(g_cKV_hi), *cKV_lo = SYMB(g_cKV_lo);
    bf16 *qf_hi = SYMB(g_qf_hi), *qf_lo = SYMB(g_qf_lo);
    bf16 *kf_hi = SYMB(g_kf_hi), *kf_lo = SYMB(g_kf_lo);
    bf16 *vCT_hi = SYMB(g_vCT_hi), *vCT_lo = SYMB(g_vCT_lo);
    bf16 *w_hi = SYMB(g_w_hi), *w_lo = SYMB(g_w_lo);
    bf16 *attn_hi = SYMB(g_attn_hi), *attn_lo = SYMB(g_attn_lo);

    cudaFuncSetAttribute((const void*)gemm512<0>,  cudaFuncAttributeMaxDynamicSharedMemorySize, G512_SMEM);
    cudaFuncSetAttribute((const void*)gemm512dual, cudaFuncAttributeMaxDynamicSharedMemorySize, G512_SMEM);
    cudaFuncSetAttribute((const void*)attn128<true,false,1>, cudaFuncAttributeMaxDynamicSharedMemorySize, A128_SMEM);
    cudaFuncSetAttribute((const void*)attn128<false,true,2>, cudaFuncAttributeMaxDynamicSharedMemorySize, A128_SMEM);

    // prep
    biascat<<<(N1 + 255)/256 > 16 ? (N1+255)/256 : 16, 256>>>(
        bq_down, bkv, bkr, bqc, bqr, bkc, bvc, b1, b2, b3);
    split_rm<<<(LL)NTOK*D_MODEL/1024, 256>>>(h, h_hi, h_lo);
    split_tr<<<dim3(D_CQ/32, D_MODEL/32), 256>>>(Wq_down, D_CQ, WdT_hi, WdT_lo, D_MODEL, D_CQ);
    split_tr<<<dim3(D_C/32, D_MODEL/32), 256>>>(Wkv, D_C,
        WdT_hi + (LL)D_CQ*D_MODEL, WdT_lo + (LL)D_CQ*D_MODEL, D_MODEL, D_C);
    split_tr<<<dim3(D_R/32, D_MODEL/32), 256>>>(Wkr, D_R,
        WdT_hi + (LL)2048*D_MODEL, WdT_lo + (LL)2048*D_MODEL, D_MODEL, D_R);
    zfill<<<(64*D_MODEL/2 + 255)/256, 256>>>(WdT_hi + (LL)2112*D_MODEL, (LL)64*D_MODEL);
    zfill<<<(64*D_MODEL/2 + 255)/256, 256>>>(WdT_lo + (LL)2112*D_MODEL, (LL)64*D_MODEL);

    // merged: tmp12 = h @ [Wq_down | Wkv | Wkr | 0] + bias   (N=2176)
    gemm512<0><<<dim3(N1/128, NTOK/256), 512, G512_SMEM>>>(
        h_hi, h_lo, WdT_hi, WdT_lo, b1, tmp12, nullptr, nullptr,
        D_MODEL, D_MODEL, D_MODEL, N1);

    // remaining weight splits
    split_tr<<<dim3(2048/32, D_CQ/32), 256>>>(Wqc, 2048, WqcrT_hi, WqcrT_lo, D_CQ, 2048);
    split_tr<<<dim3(1024/32, D_CQ/32), 256>>>(Wqr, 1024,
        WqcrT_hi + (LL)2048*D_CQ, WqcrT_lo + (LL)2048*D_CQ, D_CQ, 1024);
    split_tr<<<dim3(2048/32, D_C/32), 256>>>(Wkc, 2048, WkvcT_hi, WkvcT_lo, D_C, 2048);
    split_tr<<<dim3(2048/32, D_C/32), 256>>>(Wvc, 2048,
        WkvcT_hi + (LL)2048*D_C, WkvcT_lo + (LL)2048*D_C, D_C, 2048);
    split_tr<<<dim3(2048/32, 2048/32), 256>>>(Wo, 2048, WoT_hi, WoT_lo, 2048, 2048);

    // fused norms (cQ, cKV, kr) in one launch
    rmsnorm_all<<<NTOK, 256>>>(tmp12, gq_norm, gkv, gkr,
                               cQ_hi, cQ_lo, cKV_hi, cKV_lo, krn);

    // dual projection: qCR (N=3072, K=1536) + kvC (N=4096, K=512) in one launch
    gemm512dual<<<dim3(3072/128 + 4096/128, NTOK/256), 512, G512_SMEM>>>(
        cQ_hi, cQ_lo, WqcrT_hi, WqcrT_lo, b2, qCR, D_CQ, 3072, 3072/128,
        cKV_hi, cKV_lo, WkvcT_hi, WkvcT_lo, b3, kvC, D_C, 4096);

    // vC^T splits
    split_tr<<<dim3(2048/32, NTOK/32), 256>>>(kvC + 2048, 4096, vCT_hi, vCT_lo, NTOK, 2048);

    // pack + RoPE (q pre-scaled)
    pack_split<<<NTOK, 256>>>(qCR, kvC, krn, freqs, qf_hi, qf_lo, kf_hi, kf_lo,
                              1.0f / sqrtf((float)D_QK));

    // scores = q k^T (causal; upper tiles zero-fill w)
    {
        LL soQK = (LL)SEQ * N_HEADS * D_QK, siQK = D_QK;
        LL soW  = (LL)N_HEADS * SEQ * SEQ,  siW  = (LL)SEQ * SEQ;
        attn128<true,false,1><<<dim3(SEQ/128, SEQ/128, BSZ*N_HEADS), 256, A128_SMEM>>>(
            qf_hi, qf_lo, kf_hi, kf_lo, w, nullptr, nullptr,
            D_QK, N_HEADS*D_QK, N_HEADS*D_QK, SEQ,
            soQK, siQK, soQK, siQK, soW, siW, N_HEADS);
    }

    // softmax (fp32 + bf16 splits, k < kLim at 128-granularity)
    softmax_kernel<<<(LL)BSZ*N_HEADS*SEQ, 256>>>(w, w_hi, w_lo);

    // PV: attn = w @ vC, 128-row tiles, K clipped at m0+128, bf16-split out
    {
        LL soW = (LL)N_HEADS * SEQ * SEQ, siW = (LL)SEQ * SEQ;
        LL soB = 2048;
        LL siB = (LL)D_H * NTOK;
        LL soC = (LL)SEQ * 2048, siC = D_H;
        attn128<false,true,2><<<dim3(D_H/128, SEQ/128, BSZ*N_HEADS), 256, A128_SMEM>>>(
            w_hi, w_lo, vCT_hi, vCT_lo, nullptr, attn_hi, attn_lo,
            SEQ, SEQ, NTOK, 2048,
            soW, siW, soB, siB, soC, siC, N_HEADS);
    }

    // h_out = attn @ Wo + bo
    gemm512<0><<<dim3(2048/128, NTOK/256), 512, G512_SMEM>>>(
        attn_hi, attn_lo, WoT_hi, WoT_lo, bo, out_h, nullptr, nullptr,
        2048, 2048, 2048, 2048);
}

// round 15
// speedup vs baseline: 1.0568x; 1.0102x over previous
#include <cuda_runtime.h>
#include <cuda_bf16.h>
#include <math.h>
#include <stdint.h>

#define D_MODEL 2048
#define N_HEADS 16
#define D_CQ    1536
#define D_C     512
#define D_H     128
#define D_R     64
#define BSZ     4
#define SEQ     2048
#define NTOK    (BSZ*SEQ)
#define D_QK    (D_H + D_R)
#define LL long long

#define SW128(o) ((o) ^ (((o) >> 3) & 0x70))
#define SW64(o)  ((o) ^ (((o) >> 2) & 0x30))

#define N1 2176   // merged first-GEMM N: Wqd(1536) | Wkv(512) | Wkr(64) | pad(64)

typedef __nv_bfloat16 bf16;

// ---------------- scratch ----------------
__device__ float g_tmp12[(LL)NTOK * N1];
__device__ float g_qCR [(LL)NTOK * 3072];
__device__ float g_kvC [(LL)NTOK * 4096];
__device__ float g_krn [(LL)NTOK * D_R];
__device__ bf16 g_h_hi[(LL)NTOK * D_MODEL],      g_h_lo[(LL)NTOK * D_MODEL];
__device__ bf16 g_WdT_hi[(LL)N1 * D_MODEL],      g_WdT_lo[(LL)N1 * D_MODEL];
__device__ bf16 g_WqcrT_hi[(LL)3072 * D_CQ],     g_WqcrT_lo[(LL)3072 * D_CQ];
__device__ bf16 g_WkvcT_hi[(LL)4096 * D_C],      g_WkvcT_lo[(LL)4096 * D_C];
__device__ bf16 g_WoT_hi[(LL)2048 * 2048],       g_WoT_lo[(LL)2048 * 2048];
__device__ bf16 g_cQ_hi[(LL)NTOK * D_CQ],        g_cQ_lo[(LL)NTOK * D_CQ];
__device__ bf16 g_cKV_hi[(LL)NTOK * D_C],        g_cKV_lo[(LL)NTOK * D_C];
__device__ bf16 g_qf_hi[(LL)NTOK * N_HEADS*D_QK], g_qf_lo[(LL)NTOK * N_HEADS*D_QK];
__device__ bf16 g_kf_hi[(LL)NTOK * N_HEADS*D_QK], g_kf_lo[(LL)NTOK * N_HEADS*D_QK];
__device__ bf16 g_vCT_hi[(LL)2048 * NTOK],       g_vCT_lo[(LL)2048 * NTOK];
__device__ bf16 g_w_hi[(LL)BSZ*N_HEADS*SEQ*SEQ], g_w_lo[(LL)BSZ*N_HEADS*SEQ*SEQ];
__device__ bf16 g_attn_hi[(LL)NTOK * 2048],      g_attn_lo[(LL)NTOK * 2048];
__device__ float g_bias1[N1];
__device__ float g_bias2[3072];
__device__ float g_bias3[4096];

// ---------------- helpers ----------------
__device__ __forceinline__ uint32_t smem_u32(const void* p) {
    uint32_t a;
    asm("{ .reg .u64 t; cvta.to.shared.u64 t, %1; cvt.u32.u64 %0, t; }" : "=r"(a) : "l"(p));
    return a;
}
#define CP16(d, s) asm volatile("cp.async.cg.shared.global [%0], [%1], 16;" :: "r"(d), "l"(s))
#define CP_COMMIT() asm volatile("cp.async.commit_group;" ::: "memory")
#define CP_WAIT1() asm volatile("cp.async.wait_group 1;" ::: "memory")
#define CP_WAIT0() asm volatile("cp.async.wait_group 0;" ::: "memory")

__device__ __forceinline__ void ldsm_x4(uint32_t addr, uint32_t& r0, uint32_t& r1,
                                        uint32_t& r2, uint32_t& r3) {
    asm volatile("ldmatrix.sync.aligned.m8n8.x4.shared.b16 {%0,%1,%2,%3}, [%4];"
                 : "=r"(r0), "=r"(r1), "=r"(r2), "=r"(r3) : "r"(addr));
}
__device__ __forceinline__ void mma_bf16(float* c, const uint32_t* a,
                                         uint32_t b0, uint32_t b1) {
    asm volatile(
        "mma.sync.aligned.m16n8k16.row.col.f32.bf16.bf16.f32 "
        "{%0,%1,%2,%3}, {%4,%5,%6,%7}, {%8,%9}, {%0,%1,%2,%3};"
        : "+f"(c[0]), "+f"(c[1]), "+f"(c[2]), "+f"(c[3])
        : "r"(a[0]), "r"(a[1]), "r"(a[2]), "r"(a[3]), "r"(b0), "r"(b1));
}
__device__ __forceinline__ void splitw(float v, bf16& hi, bf16& lo) {
    hi = __float2bfloat16(v);
    lo = __float2bfloat16(v - __bfloat162float(hi));
}
__device__ __forceinline__ void split2pack(float f0, float f1, uint32_t& hp, uint32_t& lp) {
    bf16 h0, l0, h1, l1;
    splitw(f0, h0, l0); splitw(f1, h1, l1);
    hp = ((uint32_t)__bfloat16_as_ushort(h1) << 16) | __bfloat16_as_ushort(h0);
    lp = ((uint32_t)__bfloat16_as_ushort(l1) << 16) | __bfloat16_as_ushort(l0);
}

// ============ gemm512 body: 256x128 tile, 512 threads, BK=64, 2-stage ============
__device__ __forceinline__
void gemm512_body(const bf16* __restrict__ Ah_b, const bf16* __restrict__ Al_b,
                  const bf16* __restrict__ Bh_b, const bf16* __restrict__ Bl_b,
                  const float* __restrict__ bias, float* __restrict__ Cb,
                  int m0, int n0, int K, int lda, int ldb, int ldc)
{
    int KT = K >> 6;

    extern __shared__ char sm[];
    uint32_t sb = smem_u32(sm);

    int tid = threadIdx.x;
    int wid = tid >> 5, lane = tid & 31;
    int wm = (wid & 7) << 5;
    int wn = (wid >> 3) << 6;
    int g = lane >> 3, r = lane & 7;
    int aro = ((g & 1) << 3) + r, aco = (g >> 1) << 4;
    int bro = ((g >> 1) << 3) + r, bco = (g & 1) << 4;

    float acc[2][8][4];
    #pragma unroll
    for (int i = 0; i < 2; i++)
        #pragma unroll
        for (int j = 0; j < 8; j++)
            #pragma unroll
            for (int t = 0; t < 4; t++) acc[i][j][t] = 0.0f;

    #define LOAD_STG(s, k0) do {                                               \
        uint32_t st = sb + (uint32_t)(s) * 98304u;                             \
        _Pragma("unroll")                                                      \
        for (int i = 0; i < 4; i++) {                                          \
            int idx = tid + (i << 9);                                          \
            int row = idx >> 3, c = idx & 7;                                   \
            uint32_t d = st + SW128((uint32_t)((row << 7) + (c << 4)));        \
            LL go = (LL)(m0 + row) * lda + (k0) + (c << 3);                    \
            CP16(d,          Ah_b + go);                                       \
            CP16(d + 32768u, Al_b + go);                                       \
        }                                                                      \
        _Pragma("unroll")                                                      \
        for (int i = 0; i < 2; i++) {                                          \
            int idx = tid + (i << 9);                                          \
            int row = idx >> 3, c = idx & 7;                                   \
            uint32_t d = st + 65536u + SW128((uint32_t)((row << 7) + (c << 4)));\
            LL go = (LL)(n0 + row) * ldb + (k0) + (c << 3);                    \
            CP16(d,          Bh_b + go);                                       \
            CP16(d + 16384u, Bl_b + go);                                       \
        }                                                                      \
    } while (0)

    LOAD_STG(0, 0);
    CP_COMMIT();

    for (int kt = 0; kt < KT; kt++) {
        CP_WAIT0();
        __syncthreads();
        if (kt + 1 < KT) {
            LOAD_STG((kt + 1) & 1, (kt + 1) << 6);
            CP_COMMIT();
        }

        uint32_t aB = sb + (uint32_t)(kt & 1) * 98304u;
        uint32_t bB = aB + 65536u;

        #pragma unroll
        for (int ks = 0; ks < 4; ks++) {
            int kb = ks << 5;
            uint32_t ah[2][4], al[2][4];
            #pragma unroll
            for (int mf = 0; mf < 2; mf++) {
                uint32_t off = SW128((uint32_t)((wm + (mf << 4) + aro) * 128 + kb + aco));
                ldsm_x4(aB + off,          ah[mf][0], ah[mf][1], ah[mf][2], ah[mf][3]);
                ldsm_x4(aB + 32768u + off, al[mf][0], al[mf][1], al[mf][2], al[mf][3]);
            }
            #pragma unroll
            for (int ng = 0; ng < 4; ng++) {
                uint32_t off = SW128((uint32_t)((wn + (ng << 4) + bro) * 128 + kb + bco));
                uint32_t bh0, bh1, bh2, bh3, bl0, bl1, bl2, bl3;
                ldsm_x4(bB + off,          bh0, bh1, bh2, bh3);
                ldsm_x4(bB + 16384u + off, bl0, bl1, bl2, bl3);
                #pragma unroll
                for (int mf = 0; mf < 2; mf++) {
                    float* c0 = acc[mf][(ng << 1)];
                    float* c1 = acc[mf][(ng << 1) + 1];
                    mma_bf16(c0, ah[mf], bh0, bh1);
                    mma_bf16(c1, ah[mf], bh2, bh3);
                    mma_bf16(c0, ah[mf], bl0, bl1);
                    mma_bf16(c1, ah[mf], bl2, bl3);
                    mma_bf16(c0, al[mf], bh0, bh1);
                    mma_bf16(c1, al[mf], bh2, bh3);
                }
            }
        }
    }

    #pragma unroll
    for (int mf = 0; mf < 2; mf++) {
        int row = m0 + wm + (mf << 4) + (lane >> 2);
        #pragma unroll
        for (int nf = 0; nf < 8; nf++) {
            int col = n0 + wn + (nf << 3) + ((lane & 3) << 1);
            float* a = acc[mf][nf];
            float bx = bias[col], by = bias[col + 1];
            *(float2*)(Cb + (LL)row * ldc + col)       = make_float2(a[0] + bx, a[1] + by);
            *(float2*)(Cb + (LL)(row + 8) * ldc + col) = make_float2(a[2] + bx, a[3] + by);
        }
    }
}

__global__ __launch_bounds__(512, 1)
void gemm512f(const bf16* __restrict__ Ahi, const bf16* __restrict__ Alo,
              const bf16* __restrict__ Bhi, const bf16* __restrict__ Blo,
              const float* __restrict__ bias, float* __restrict__ C,
              int K, int lda, int ldb, int ldc)
{
    gemm512_body(Ahi, Alo, Bhi, Blo, bias, C,
                 blockIdx.y * 256, blockIdx.x * 128, K, lda, ldb, ldc);
}

__global__ __launch_bounds__(512, 1)
void gemm512dual(const bf16* A1h, const bf16* A1l, const bf16* B1h, const bf16* B1l,
                 const float* b1, float* C1, int K1, int ldc1, int NX1,
                 const bf16* A2h, const bf16* A2l, const bf16* B2h, const bf16* B2l,
                 const float* b2, float* C2, int K2, int ldc2)
{
    int xc = blockIdx.x;
    if (xc < NX1) {
        gemm512_body(A1h, A1l, B1h, B1l, b1, C1,
                     blockIdx.y * 256, xc * 128, K1, K1, K1, ldc1);
    } else {
        gemm512_body(A2h, A2l, B2h, B2l, b2, C2,
                     blockIdx.y * 256, (xc - NX1) * 128, K2, K2, K2, ldc2);
    }
}

// ============ attn128: bf16x3, 128x128, BK=32, 3-stage, 2 CTAs/SM ============
template<bool CAUSAL, bool KCLIP, int EPI>   // EPI: 1=fp32, 2=bf16 splits
__global__ __launch_bounds__(256, 2)
void attn128(const bf16* __restrict__ Ahi, const bf16* __restrict__ Alo,
             const bf16* __restrict__ Bhi, const bf16* __restrict__ Blo,
             float* __restrict__ C, bf16* __restrict__ Chi, bf16* __restrict__ Clo,
             int K, int lda, int ldb, int ldc,
             LL soA, LL siA, LL soB, LL siB, LL soC, LL siC, int IC)
{
    int m0 = blockIdx.y * 128;
    int n0 = blockIdx.x * 128;
    int z = blockIdx.z;
    LL zo = z / IC, zi = z % IC;
    int tid = threadIdx.x;

    if (CAUSAL && n0 > m0) {
        float* Wb = C + zo*soC + zi*siC;
        float4 zz = make_float4(0.f, 0.f, 0.f, 0.f);
        #pragma unroll
        for (int i = 0; i < 16; i++) {
            int idx = tid + (i << 8);
            int row = idx >> 5, c4 = (idx & 31) << 2;
            *(float4*)(Wb + (LL)(m0 + row) * ldc + n0 + c4) = zz;
        }
        return;
    }

    const bf16* Ah_b = Ahi + zo*soA + zi*siA;
    const bf16* Al_b = Alo + zo*soA + zi*siA;
    const bf16* Bh_b = Bhi + zo*soB + zi*siB;
    const bf16* Bl_b = Blo + zo*soB + zi*siB;

    int Keff = KCLIP ? (m0 + 128 < K ? m0 + 128 : K) : K;
    int KT = Keff >> 5;

    extern __shared__ char sm[];
    uint32_t sb = smem_u32(sm);

    int wid = tid >> 5, lane = tid & 31;
    int wm = (wid & 3) << 5;
    int wn = (wid >> 2) << 6;
    int g = lane >> 3, r = lane & 7;
    int aro = ((g & 1) << 3) + r, aco = (g >> 1) << 4;
    int bro = ((g >> 1) << 3) + r, bco = (g & 1) << 4;

    float acc[2][8][4];
    #pragma unroll
    for (int i = 0; i < 2; i++)
        #pragma unroll
        for (int j = 0; j < 8; j++)
            #pragma unroll
            for (int t = 0; t < 4; t++) acc[i][j][t] = 0.0f;

    #define SLOAD(s, k0) do {                                                  \
        uint32_t st = sb + (uint32_t)(s) * 32768u;                             \
        _Pragma("unroll")                                                      \
        for (int i = 0; i < 2; i++) {                                          \
            int idx = tid + (i << 8);                                          \
            int row = idx >> 2, c = (idx & 3) << 4;                            \
            uint32_t sw = SW64((uint32_t)((row << 6) + c));                    \
            LL goA = (LL)(m0 + row) * lda + (k0) + ((idx & 3) << 3);           \
            LL goB = (LL)(n0 + row) * ldb + (k0) + ((idx & 3) << 3);           \
            CP16(st + sw,           Ah_b + goA);                               \
            CP16(st + 8192u  + sw,  Al_b + goA);                               \
            CP16(st + 16384u + sw,  Bh_b + goB);                               \
            CP16(st + 24576u + sw,  Bl_b + goB);                               \
        }                                                                      \
    } while (0)

    SLOAD(0, 0);  CP_COMMIT();
    SLOAD(1, 32); CP_COMMIT();

    int cs = 0, ls = 2;
    for (int kt = 0; kt < KT; kt++) {
        CP_WAIT1();
        __syncthreads();
        if (kt + 2 < KT) {
            SLOAD(ls, (kt + 2) << 5);
        }
        CP_COMMIT();
        ls++; if (ls == 3) ls = 0;

        uint32_t aB = sb + (uint32_t)cs * 32768u;
        uint32_t bB = aB + 16384u;

        #pragma unroll
        for (int ks = 0; ks < 2; ks++) {
            int kb = ks << 5;
            uint32_t ah[2][4], al[2][4];
            #pragma unroll
            for (int mf = 0; mf < 2; mf++) {
                uint32_t off = SW64((uint32_t)((wm + (mf << 4) + aro) * 64 + kb + aco));
                ldsm_x4(aB + off,         ah[mf][0], ah[mf][1], ah[mf][2], ah[mf][3]);
                ldsm_x4(aB + 8192u + off, al[mf][0], al[mf][1], al[mf][2], al[mf][3]);
            }
            #pragma unroll
            for (int ng = 0; ng < 4; ng++) {
                uint32_t off = SW64((uint32_t)((wn + (ng << 4) + bro) * 64 + kb + bco));
                uint32_t bh0, bh1, bh2, bh3, bl0, bl1, bl2, bl3;
                ldsm_x4(bB + off,         bh0, bh1, bh2, bh3);
                ldsm_x4(bB + 8192u + off, bl0, bl1, bl2, bl3);
                #pragma unroll
                for (int mf = 0; mf < 2; mf++) {
                    float* c0 = acc[mf][(ng << 1)];
                    float* c1 = acc[mf][(ng << 1) + 1];
                    mma_bf16(c0, ah[mf], bh0, bh1);
                    mma_bf16(c1, ah[mf], bh2, bh3);
                    mma_bf16(c0, ah[mf], bl0, bl1);
                    mma_bf16(c1, ah[mf], bl2, bl3);
                    mma_bf16(c0, al[mf], bh0, bh1);
                    mma_bf16(c1, al[mf], bh2, bh3);
                }
            }
        }
        cs++; if (cs == 3) cs = 0;
    }

    #pragma unroll
    for (int mf = 0; mf < 2; mf++) {
        int row = m0 + wm + (mf << 4) + (lane >> 2);
        #pragma unroll
        for (int nf = 0; nf < 8; nf++) {
            int col = n0 + wn + (nf << 3) + ((lane & 3) << 1);
            float* a = acc[mf][nf];
            if (EPI == 1) {
                float* Cb = C + zo*soC + zi*siC;
                *(float2*)(Cb + (LL)row * ldc + col)       = make_float2(a[0], a[1]);
                *(float2*)(Cb + (LL)(row + 8) * ldc + col) = make_float2(a[2], a[3]);
            } else {
                bf16* Hb = Chi + zo*soC + zi*siC;
                bf16* Lb = Clo + zo*soC + zi*siC;
                uint32_t hp, lp;
                split2pack(a[0], a[1], hp, lp);
                *(uint32_t*)(Hb + (LL)row * ldc + col) = hp;
                *(uint32_t*)(Lb + (LL)row * ldc + col) = lp;
                split2pack(a[2], a[3], hp, lp);
                *(uint32_t*)(Hb + (LL)(row + 8) * ldc + col) = hp;
                *(uint32_t*)(Lb + (LL)(row + 8) * ldc + col) = lp;
            }
        }
    }
}

// ---------------- fat-kernel device bodies ----------------
__device__ __forceinline__
void split_rm_body(const float* __restrict__ x, bf16* __restrict__ hi,
                   bf16* __restrict__ lo, int blk)
{
    LL base = ((LL)blk * 256 + threadIdx.x) * 4;
    float4 v = *(const float4*)(x + base);
    bf16 h[4], l[4];
    splitw(v.x, h[0], l[0]); splitw(v.y, h[1], l[1]);
    splitw(v.z, h[2], l[2]); splitw(v.w, h[3], l[3]);
    *(uint2*)(hi + base) = *(uint2*)h;
    *(uint2*)(lo + base) = *(uint2*)l;
}

__device__ __forceinline__
void split_tr_body(const float* __restrict__ x, int ldx,
                   bf16* __restrict__ hi, bf16* __restrict__ lo,
                   int R, int bx, int by)
{
    __shared__ float s[32][33];
    int tx = threadIdx.x & 31, ty = threadIdx.x >> 5;
    int r0 = by * 32, c0 = bx * 32;
    #pragma unroll
    for (int j = 0; j < 4; j++)
        s[ty + 8*j][tx] = x[(LL)(r0 + ty + 8*j) * ldx + c0 + tx];
    __syncthreads();
    #pragma unroll
    for (int j = 0; j < 4; j++) {
        float v = s[tx][ty + 8*j];
        bf16 h, l; splitw(v, h, l);
        LL o = (LL)(c0 + ty + 8*j) * R + r0 + tx;
        hi[o] = h; lo[o] = l;
    }
    __syncthreads();
}

__device__ __forceinline__
void zfill_body(bf16* __restrict__ p, int blk)
{
    LL i = ((LL)blk * 256 + threadIdx.x) * 2;
    *(uint32_t*)(p + i) = 0u;
}

__device__ __forceinline__
void biascat_body(const float* bqd, const float* bkv, const float* bkr,
                  const float* bqc, const float* bqr,
                  const float* bkc, const float* bvc,
                  float* b1, float* b2, float* b3, int blk)
{
    int i = blk * 256 + threadIdx.x;
    if (i < N1) {
        float v = 0.0f;
        if (i < 1536) v = bqd[i];
        else if (i < 2048) v = bkv[i - 1536];
        else if (i < 2112) v = bkr[i - 2048];
        b1[i] = v;
    }
    if (i < 2048) b2[i] = bqc[i]; else if (i < 3072) b2[i] = bqr[i - 2048];
    if (i < 2048) b3[i] = bkc[i]; else if (i < 4096) b3[i] = bvc[i - 2048];
}

// block-count constants for prep_all dispatch
#define NB_RM   16384               // split h
#define NB_WQD  (48*64)             // 3072
#define NB_WKV  (16*64)             // 1024
#define NB_WKR  (2*64)              // 128
#define NB_ZF   256                 // per zfill array (64*2048 bf16 / 512)
#define NB_BIAS 16
#define NB_WQC  (64*48)             // 3072
#define NB_WQR  (32*48)             // 1536
#define NB_WKC  (64*16)             // 1024
#define NB_WVC  (64*16)             // 1024
#define NB_WO   (64*64)             // 4096
#define PREP_TOTAL (NB_RM+NB_WQD+NB_WKV+NB_WKR+2*NB_ZF+NB_BIAS+NB_WQC+NB_WQR+NB_WKC+NB_WVC+NB_WO)

__global__ __launch_bounds__(256)
void prep_all(const float* h, const float* Wqd, const float* Wkv, const float* Wkr,
              const float* Wqc, const float* Wqr, const float* Wkc, const float* Wvc,
              const float* Wo,
              const float* bqd, const float* bkv, const float* bkr,
              const float* bqc, const float* bqr, const float* bkc, const float* bvc,
              bf16* h_hi, bf16* h_lo, bf16* WdT_hi, bf16* WdT_lo,
              bf16* WqcrT_hi, bf16* WqcrT_lo, bf16* WkvcT_hi, bf16* WkvcT_lo,
              bf16* WoT_hi, bf16* WoT_lo,
              float* b1, float* b2, float* b3)
{
    int b = blockIdx.x;
    if (b < NB_RM) { split_rm_body(h, h_hi, h_lo, b); return; }
    b -= NB_RM;
    if (b < NB_WQD) { split_tr_body(Wqd, D_CQ, WdT_hi, WdT_lo, D_MODEL, b % 48, b / 48); return; }
    b -= NB_WQD;
    if (b < NB_WKV) {
        split_tr_body(Wkv, D_C, WdT_hi + (LL)D_CQ*D_MODEL, WdT_lo + (LL)D_CQ*D_MODEL,
                      D_MODEL, b % 16, b / 16);
        return;
    }
    b -= NB_WKV;
    if (b < NB_WKR) {
        split_tr_body(Wkr, D_R, WdT_hi + (LL)2048*D_MODEL, WdT_lo + (LL)2048*D_MODEL,
                      D_MODEL, b % 2, b / 2);
        return;
    }
    b -= NB_WKR;
    if (b < NB_ZF) { zfill_body(WdT_hi + (LL)2112*D_MODEL, b); return; }
    b -= NB_ZF;
    if (b < NB_ZF) { zfill_body(WdT_lo + (LL)2112*D_MODEL, b); return; }
    b -= NB_ZF;
    if (b < NB_BIAS) { biascat_body(bqd, bkv, bkr, bqc, bqr, bkc, bvc, b1, b2, b3, b); return; }
    b -= NB_BIAS;
    if (b < NB_WQC) { split_tr_body(Wqc, 2048, WqcrT_hi, WqcrT_lo, D_CQ, b % 64, b / 64); return; }
    b -= NB_WQC;
    if (b < NB_WQR) {
        split_tr_body(Wqr, 1024, WqcrT_hi + (LL)2048*D_CQ, WqcrT_lo + (LL)2048*D_CQ,
                      D_CQ, b % 32, b / 32);
        return;
    }
    b -= NB_WQR;
    if (b < NB_WKC) { split_tr_body(Wkc, 2048, WkvcT_hi, WkvcT_lo, D_C, b % 64, b / 64); return; }
    b -= NB_WKC;
    if (b < NB_WVC) {
        split_tr_body(Wvc, 2048, WkvcT_hi + (LL)2048*D_C, WkvcT_lo + (LL)2048*D_C,
                      D_C, b % 64, b / 64);
        return;
    }
    b -= NB_WVC;
    split_tr_body(Wo, 2048, WoT_hi, WoT_lo, 2048, b % 64, b / 64);
}

// ---------------- fused rmsnorm over all three slices of tmp12 ----------------
__global__ __launch_bounds__(256)
void rmsnorm_all(const float* __restrict__ x,
                 const float* __restrict__ gq, const float* __restrict__ gkv,
                 const float* __restrict__ gkr,
                 bf16* __restrict__ cQh, bf16* __restrict__ cQl,
                 bf16* __restrict__ cKVh, bf16* __restrict__ cKVl,
                 float* __restrict__ krn)
{
    LL xb = (LL)blockIdx.x * N1;
    int tid = threadIdx.x;
    __shared__ float red[256];

    float s = 0.0f;
    #pragma unroll
    for (int i = 0; i < 6; i++) { float v = x[xb + tid + (i << 8)]; s += v * v; }
    red[tid] = s; __syncthreads();
    for (int st = 128; st > 0; st >>= 1) {
        if (tid < st) red[tid] += red[tid + st];
        __syncthreads();
    }
    float rs = rsqrtf(red[0] / (float)D_CQ + 1e-6f);
    LL yb = (LL)blockIdx.x * D_CQ;
    #pragma unroll
    for (int i = 0; i < 6; i++) {
        int idx = tid + (i << 8);
        float v = x[xb + idx] * rs * gq[idx];
        bf16 h, l; splitw(v, h, l);
        cQh[yb + idx] = h; cQl[yb + idx] = l;
    }
    __syncthreads();

    s = 0.0f;
    #pragma unroll
    for (int i = 0; i < 2; i++) { float v = x[xb + 1536 + tid + (i << 8)]; s += v * v; }
    red[tid] = s; __syncthreads();
    for (int st = 128; st > 0; st >>= 1) {
        if (tid < st) red[tid] += red[tid + st];
        __syncthreads();
    }
    rs = rsqrtf(red[0] / (float)D_C + 1e-6f);
    yb = (LL)blockIdx.x * D_C;
    #pragma unroll
    for (int i = 0; i < 2; i++) {
        int idx = tid + (i << 8);
        float v = x[xb + 1536 + idx] * rs * gkv[idx];
        bf16 h, l; splitw(v, h, l);
        cKVh[yb + idx] = h; cKVl[yb + idx] = l;
    }
    __syncthreads();

    float v3 = (tid < D_R) ? x[xb + 2048 + tid] : 0.0f;
    red[tid] = v3 * v3; __syncthreads();
    for (int st = 128; st > 0; st >>= 1) {
        if (tid < st) red[tid] += red[tid + st];
        __syncthreads();
    }
    rs = rsqrtf(red[0] / (float)D_R + 1e-6f);
    if (tid < D_R)
        krn[(LL)blockIdx.x * D_R + tid] = v3 * rs * gkr[tid];
}

// ---------------- pack body (RoPE -> bf16 splits, q pre-scaled) ----------------
__device__ __forceinline__
void pack_body(const float* __restrict__ qCR, const float* __restrict__ kvC,
               const float* __restrict__ krn, const float* __restrict__ freqs,
               bf16* __restrict__ qfh, bf16* __restrict__ qfl,
               bf16* __restrict__ kfh, bf16* __restrict__ kfl, float scale, int bs)
{
    int s  = bs & (SEQ - 1);
    LL qfb = (LL)bs * N_HEADS * D_QK;
    int tid = threadIdx.x;

    __shared__ float krs[D_R];
    if (tid < 32) {
        int i = tid;
        float a = krn[(LL)bs*D_R + 2*i];
        float b = krn[(LL)bs*D_R + 2*i + 1];
        float c  = freqs[(LL)s*D_R + 2*i];
        float sn = freqs[(LL)s*D_R + 2*i + 1];
        krs[2*i]   = a*c - b*sn;
        krs[2*i+1] = a*sn + b*c;
    }
    __syncthreads();

    for (int idx = tid; idx < N_HEADS*D_H; idx += 256) {
        int h = idx >> 7, d = idx & 127;
        float v = qCR[(LL)bs*3072 + idx] * scale;
        bf16 hh, ll; splitw(v, hh, ll);
        qfh[qfb + h*D_QK + d] = hh; qfl[qfb + h*D_QK + d] = ll;
    }
    for (int idx = tid; idx < N_HEADS*(D_R/2); idx += 256) {
        int h = idx >> 5, i = idx & 31;
        float a = qCR[(LL)bs*3072 + 2048 + h*D_R + 2*i];
        float b = qCR[(LL)bs*3072 + 2048 + h*D_R + 2*i + 1];
        float c  = freqs[(LL)s*D_R + 2*i];
        float sn = freqs[(LL)s*D_R + 2*i + 1];
        float v0 = (a*c - b*sn) * scale, v1 = (a*sn + b*c) * scale;
        bf16 hh, ll;
        splitw(v0, hh, ll);
        qfh[qfb + h*D_QK + D_H + 2*i] = hh;   qfl[qfb + h*D_QK + D_H + 2*i] = ll;
        splitw(v1, hh, ll);
        qfh[qfb + h*D_QK + D_H + 2*i+1] = hh; qfl[qfb + h*D_QK + D_H + 2*i+1] = ll;
    }
    for (int idx = tid; idx < N_HEADS*D_R; idx += 256) {
        int h = idx >> 6, d = idx & 63;
        bf16 hh, ll; splitw(krs[d], hh, ll);
        kfh[qfb + h*D_QK + d] = hh; kfl[qfb + h*D_QK + d] = ll;
    }
    for (int idx = tid; idx < N_HEADS*D_H; idx += 256) {
        int h = idx >> 7, d = idx & 127;
        float v = kvC[(LL)bs*4096 + idx];
        bf16 hh, ll; splitw(v, hh, ll);
        kfh[qfb + h*D_QK + D_R + d] = hh; kfl[qfb + h*D_QK + D_R + d] = ll;
    }
}

// post_all: vCT split (64 x 256 tiles = 16384 blocks) + pack (8192 blocks)
#define NB_VCT (64*256)
__global__ __launch_bounds__(256)
void post_all(const float* kvC, bf16* vCT_hi, bf16* vCT_lo,
              const float* qCR, const float* krn, const float* freqs,
              bf16* qfh, bf16* qfl, bf16* kfh, bf16* kfl, float scale)
{
    int b = blockIdx.x;
    if (b < NB_VCT) {
        split_tr_body(kvC + 2048, 4096, vCT_hi, vCT_lo, NTOK, b % 64, b / 64);
        return;
    }
    b -= NB_VCT;
    pack_body(qCR, kvC, krn, freqs, qfh, qfl, kfh, kfl, scale, b);
}

// ---------------- causal softmax + bf16 split emission (k < kLim only) ----------------
__global__ __launch_bounds__(256)
void softmax_kernel(float* __restrict__ w, bf16* __restrict__ wh, bf16* __restrict__ wl)
{
    LL row = blockIdx.x;
    int q = (int)(row & (SEQ - 1));
    float* base = w + row * (LL)SEQ;
    bf16* bh = wh + row * (LL)SEQ;
    bf16* bl = wl + row * (LL)SEQ;
    int tid = threadIdx.x;

    float vals[8];
    float mx = -INFINITY;
    #pragma unroll
    for (int it = 0; it < 8; it++) {
        int k = tid + it * 256;
        float v = -INFINITY;
        if (k <= q) v = base[k];
        vals[it] = v;
        mx = fmaxf(mx, v);
    }
    __shared__ float red[256];
    red[tid] = mx; __syncthreads();
    for (int st = 128; st > 0; st >>= 1) {
        if (tid < st) red[tid] = fmaxf(red[tid], red[tid + st]);
        __syncthreads();
    }
    mx = red[0]; __syncthreads();

    float sum = 0.0f;
    #pragma unroll
    for (int it = 0; it < 8; it++) {
        float e = (vals[it] == -INFINITY) ? 0.0f : __expf(vals[it] - mx);
        vals[it] = e;
        sum += e;
    }
    red[tid] = sum; __syncthreads();
    for (int st = 128; st > 0; st >>= 1) {
        if (tid < st) red[tid] += red[tid + st];
        __syncthreads();
    }
    float inv = 1.0f / red[0];

    int kLim = ((q >> 7) + 1) << 7;
    #pragma unroll
    for (int it = 0; it < 8; it++) {
        int k = tid + it * 256;
        if (k < kLim) {
            float p = vals[it] * inv;
            base[k] = p;
            bf16 h, l; splitw(p, h, l);
            bh[k] = h; bl[k] = l;
        }
    }
}

// ---------------- host ----------------
#define SYMF(name) ({ void* p_; cudaGetSymbolAddress(&p_, name); (float*)p_; })
#define SYMB(name) ({ void* p_; cudaGetSymbolAddress(&p_, name); (bf16*)p_; })

#define G512_SMEM  196608
#define A128_SMEM  98304

extern "C" void kernel_launch(void* const* d_in, const int* in_sizes, int n_in,
                              void* d_out, int out_size)
{
    (void)in_sizes; (void)n_in; (void)out_size;
    const float* h       = (const float*)d_in[0];
    const float* freqs   = (const float*)d_in[1];
    const float* Wq_down = (const float*)d_in[3];
    const float* bq_down = (const float*)d_in[4];
    const float* gq_norm = (const float*)d_in[5];
    const float* Wqc     = (const float*)d_in[6];
    const float* bqc     = (const float*)d_in[7];
    const float* Wqr     = (const float*)d_in[8];
    const float* bqr     = (const float*)d_in[9];
    const float* Wkr     = (const float*)d_in[10];
    const float* bkr     = (const float*)d_in[11];
    const float* gkr     = (const float*)d_in[12];
    const float* Wkv     = (const float*)d_in[13];
    const float* bkv     = (const float*)d_in[14];
    const float* gkv     = (const float*)d_in[15];
    const float* Wkc     = (const float*)d_in[16];
    const float* bkc     = (const float*)d_in[17];
    const float* Wvc     = (const float*)d_in[18];
    const float* bvc     = (const float*)d_in[19];
    const float* Wo      = (const float*)d_in[20];
    const float* bo      = (const float*)d_in[21];

    float* out_h = (float*)d_out;
    float* w     = out_h + (LL)NTOK * D_MODEL;

    float* tmp12 = SYMF(g_tmp12);
    float* qCR = SYMF(g_qCR);
    float* kvC = SYMF(g_kvC);
    float* krn = SYMF(g_krn);
    float* b1 = SYMF(g_bias1); float* b2 = SYMF(g_bias2); float* b3 = SYMF(g_bias3);

    bf16 *h_hi = SYMB(g_h_hi), *h_lo = SYMB(g_h_lo);
    bf16 *WdT_hi = SYMB(g_WdT_hi), *WdT_lo = SYMB(g_WdT_lo);
    bf16 *WqcrT_hi = SYMB(g_WqcrT_hi), *WqcrT_lo = SYMB(g_WqcrT_lo);
    bf16 *WkvcT_hi = SYMB(g_WkvcT_hi), *WkvcT_lo = SYMB(g_WkvcT_lo);
    bf16 *WoT_hi  = SYMB(g_WoT_hi),  *WoT_lo  = SYMB(g_WoT_lo);
    bf16 *cQ_hi = SYMB(g_cQ_hi), *cQ_lo = SYMB(g_cQ_lo);
    bf16 *cKV_hi = SYMB(g_cKV_hi), *cKV_lo = SYMB(g_cKV_lo);
    bf16 *qf_hi = SYMB(g_qf_hi), *qf_lo = SYMB(g_qf_lo);
    bf16 *kf_hi = SYMB(g_kf_hi), *kf_lo = SYMB(g_kf_lo);
    bf16 *vCT_hi = SYMB(g_vCT_hi), *vCT_lo = SYMB(g_vCT_lo);
    bf16 *w_hi = SYMB(g_w_hi), *w_lo = SYMB(g_w_lo);
    bf16 *attn_hi = SYMB(g_attn_hi), *attn_lo = SYMB(g_attn_lo);

    cudaFuncSetAttribute((const void*)gemm512f,    cudaFuncAttributeMaxDynamicSharedMemorySize, G512_SMEM);
    cudaFuncSetAttribute((const void*)gemm512dual, cudaFuncAttributeMaxDynamicSharedMemorySize, G512_SMEM);
    cudaFuncSetAttribute((const void*)attn128<true,false,1>, cudaFuncAttributeMaxDynamicSharedMemorySize, A128_SMEM);
    cudaFuncSetAttribute((const void*)attn128<false,true,2>, cudaFuncAttributeMaxDynamicSharedMemorySize, A128_SMEM);

    // 1) all input-derived prep in ONE launch
    prep_all<<<PREP_TOTAL, 256>>>(
        h, Wq_down, Wkv, Wkr, Wqc, Wqr, Wkc, Wvc, Wo,
        bq_down, bkv, bkr, bqc, bqr, bkc, bvc,
        h_hi, h_lo, WdT_hi, WdT_lo, WqcrT_hi, WqcrT_lo, WkvcT_hi, WkvcT_lo,
        WoT_hi, WoT_lo, b1, b2, b3);

    // 2) merged first GEMM: tmp12 = h @ [Wq_down | Wkv | Wkr | 0] + bias
    gemm512f<<<dim3(N1/128, NTOK/256), 512, G512_SMEM>>>(
        h_hi, h_lo, WdT_hi, WdT_lo, b1, tmp12, D_MODEL, D_MODEL, D_MODEL, N1);

    // 3) fused norms
    rmsnorm_all<<<NTOK, 256>>>(tmp12, gq_norm, gkv, gkr,
                               cQ_hi, cQ_lo, cKV_hi, cKV_lo, krn);

    // 4) dual projection: qCR (N=3072) + kvC (N=4096)
    gemm512dual<<<dim3(3072/128 + 4096/128, NTOK/256), 512, G512_SMEM>>>(
        cQ_hi, cQ_lo, WqcrT_hi, WqcrT_lo, b2, qCR, D_CQ, 3072, 3072/128,
        cKV_hi, cKV_lo, WkvcT_hi, WkvcT_lo, b3, kvC, D_C, 4096);

    // 5) vCT split + pack in ONE launch
    post_all<<<NB_VCT + NTOK, 256>>>(
        kvC, vCT_hi, vCT_lo, qCR, krn, freqs,
        qf_hi, qf_lo, kf_hi, kf_lo, 1.0f / sqrtf((float)D_QK));

    // 6) scores = q k^T (causal; upper tiles zero-fill w)
    {
        LL soQK = (LL)SEQ * N_HEADS * D_QK, siQK = D_QK;
        LL soW  = (LL)N_HEADS * SEQ * SEQ,  siW  = (LL)SEQ * SEQ;
        attn128<true,false,1><<<dim3(SEQ/128, SEQ/128, BSZ*N_HEADS), 256, A128_SMEM>>>(
            qf_hi, qf_lo, kf_hi, kf_lo, w, nullptr, nullptr,
            D_QK, N_HEADS*D_QK, N_HEADS*D_QK, SEQ,
            soQK, siQK, soQK, siQK, soW, siW, N_HEADS);
    }

    // 7) softmax
    softmax_kernel<<<(LL)BSZ*N_HEADS*SEQ, 256>>>(w, w_hi, w_lo);

    // 8) PV
    {
        LL soW = (LL)N_HEADS * SEQ * SEQ, siW = (LL)SEQ * SEQ;
        LL soB = 2048;
        LL siB = (LL)D_H * NTOK;
        LL soC = (LL)SEQ * 2048, siC = D_H;
        attn128<false,true,2><<<dim3(D_H/128, SEQ/128, BSZ*N_HEADS), 256, A128_SMEM>>>(
            w_hi, w_lo, vCT_hi, vCT_lo, nullptr, attn_hi, attn_lo,
            SEQ, SEQ, NTOK, 2048,
            soW, siW, soB, siB, soC, siC, N_HEADS);
    }

    // 9) h_out = attn @ Wo + bo
    gemm512f<<<dim3(2048/128, NTOK/256), 512, G512_SMEM>>>(
        attn_hi, attn_lo, WoT_hi, WoT_lo, bo, out_h, 2048, 2048, 2048, 2048);
}

// round 16
// speedup vs baseline: 1.0657x; 1.0084x over previous
#include <cuda_runtime.h>
#include <cuda_bf16.h>
#include <math.h>
#include <stdint.h>

#define D_MODEL 2048
#define N_HEADS 16
#define D_CQ    1536
#define D_C     512
#define D_H     128
#define D_R     64
#define BSZ     4
#define SEQ     2048
#define NTOK    (BSZ*SEQ)
#define D_QK    (D_H + D_R)
#define LL long long

#define SW128(o) ((o) ^ (((o) >> 3) & 0x70))
#define SW64(o)  ((o) ^ (((o) >> 2) & 0x30))

#define N1 2176   // merged first-GEMM N: Wqd(1536) | Wkv(512) | Wkr(64) | pad(64)

typedef __nv_bfloat16 bf16;

// ---------------- scratch ----------------
__device__ float g_tmp12[(LL)NTOK * N1];
__device__ float g_vC  [(LL)NTOK * 2048];
__device__ float g_krn [(LL)NTOK * D_R];
__device__ bf16 g_h_hi[(LL)NTOK * D_MODEL],      g_h_lo[(LL)NTOK * D_MODEL];
__device__ bf16 g_WdT_hi[(LL)N1 * D_MODEL],      g_WdT_lo[(LL)N1 * D_MODEL];
__device__ bf16 g_WqcrT_hi[(LL)3072 * D_CQ],     g_WqcrT_lo[(LL)3072 * D_CQ];
__device__ bf16 g_WkvcT_hi[(LL)4096 * D_C],      g_WkvcT_lo[(LL)4096 * D_C];
__device__ bf16 g_WoT_hi[(LL)2048 * 2048],       g_WoT_lo[(LL)2048 * 2048];
__device__ bf16 g_cQ_hi[(LL)NTOK * D_CQ],        g_cQ_lo[(LL)NTOK * D_CQ];
__device__ bf16 g_cKV_hi[(LL)NTOK * D_C],        g_cKV_lo[(LL)NTOK * D_C];
__device__ bf16 g_qf_hi[(LL)NTOK * N_HEADS*D_QK], g_qf_lo[(LL)NTOK * N_HEADS*D_QK];
__device__ bf16 g_kf_hi[(LL)NTOK * N_HEADS*D_QK], g_kf_lo[(LL)NTOK * N_HEADS*D_QK];
__device__ bf16 g_vCT_hi[(LL)2048 * NTOK],       g_vCT_lo[(LL)2048 * NTOK];
__device__ bf16 g_w_hi[(LL)BSZ*N_HEADS*SEQ*SEQ], g_w_lo[(LL)BSZ*N_HEADS*SEQ*SEQ];
__device__ bf16 g_attn_hi[(LL)NTOK * 2048],      g_attn_lo[(LL)NTOK * 2048];
__device__ float g_bias1[N1];
__device__ float g_bias2[3072];
__device__ float g_bias3[4096];

// ---------------- helpers ----------------
__device__ __forceinline__ uint32_t smem_u32(const void* p) {
    uint32_t a;
    asm("{ .reg .u64 t; cvta.to.shared.u64 t, %1; cvt.u32.u64 %0, t; }" : "=r"(a) : "l"(p));
    return a;
}
#define CP16(d, s) asm volatile("cp.async.cg.shared.global [%0], [%1], 16;" :: "r"(d), "l"(s))
#define CP_COMMIT() asm volatile("cp.async.commit_group;" ::: "memory")
#define CP_WAIT1() asm volatile("cp.async.wait_group 1;" ::: "memory")
#define CP_WAIT0() asm volatile("cp.async.wait_group 0;" ::: "memory")

__device__ __forceinline__ void ldsm_x4(uint32_t addr, uint32_t& r0, uint32_t& r1,
                                        uint32_t& r2, uint32_t& r3) {
    asm volatile("ldmatrix.sync.aligned.m8n8.x4.shared.b16 {%0,%1,%2,%3}, [%4];"
                 : "=r"(r0), "=r"(r1), "=r"(r2), "=r"(r3) : "r"(addr));
}
__device__ __forceinline__ void mma_bf16(float* c, const uint32_t* a,
                                         uint32_t b0, uint32_t b1) {
    asm volatile(
        "mma.sync.aligned.m16n8k16.row.col.f32.bf16.bf16.f32 "
        "{%0,%1,%2,%3}, {%4,%5,%6,%7}, {%8,%9}, {%0,%1,%2,%3};"
        : "+f"(c[0]), "+f"(c[1]), "+f"(c[2]), "+f"(c[3])
        : "r"(a[0]), "r"(a[1]), "r"(a[2]), "r"(a[3]), "r"(b0), "r"(b1));
}
__device__ __forceinline__ void splitw(float v, bf16& hi, bf16& lo) {
    hi = __float2bfloat16(v);
    lo = __float2bfloat16(v - __bfloat162float(hi));
}
__device__ __forceinline__ void split2pack(float f0, float f1, uint32_t& hp, uint32_t& lp) {
    bf16 h0, l0, h1, l1;
    splitw(f0, h0, l0); splitw(f1, h1, l1);
    hp = ((uint32_t)__bfloat16_as_ushort(h1) << 16) | __bfloat16_as_ushort(h0);
    lp = ((uint32_t)__bfloat16_as_ushort(l1) << 16) | __bfloat16_as_ushort(l0);
}

// ============ gemm512 body: 256x128 tile, 512 threads, BK=64, 2-stage ============
// EPI 0: fp32 + bias -> Cb
// EPI 3: q epilogue: bias, (RoPE for col>=2048), *scale, split -> qf layout
// EPI 4: kv epilogue: col<2048 -> kf splits (offset 64); col>=2048 -> fp32 vC
template<int EPI>
__device__ __forceinline__
void gemm512_body(const bf16* __restrict__ Ah_b, const bf16* __restrict__ Al_b,
                  const bf16* __restrict__ Bh_b, const bf16* __restrict__ Bl_b,
                  const float* __restrict__ bias, float* __restrict__ Cb,
                  bf16* __restrict__ Fh, bf16* __restrict__ Fl,
                  float* __restrict__ vC, const float* __restrict__ freqs, float scale,
                  int m0, int n0, int K, int lda, int ldb, int ldc)
{
    int KT = K >> 6;

    extern __shared__ char sm[];
    uint32_t sb = smem_u32(sm);

    int tid = threadIdx.x;
    int wid = tid >> 5, lane = tid & 31;
    int wm = (wid & 7) << 5;
    int wn = (wid >> 3) << 6;
    int g = lane >> 3, r = lane & 7;
    int aro = ((g & 1) << 3) + r, aco = (g >> 1) << 4;
    int bro = ((g >> 1) << 3) + r, bco = (g & 1) << 4;

    float acc[2][8][4];
    #pragma unroll
    for (int i = 0; i < 2; i++)
        #pragma unroll
        for (int j = 0; j < 8; j++)
            #pragma unroll
            for (int t = 0; t < 4; t++) acc[i][j][t] = 0.0f;

    #define LOAD_STG(s, k0) do {                                               \
        uint32_t st = sb + (uint32_t)(s) * 98304u;                             \
        _Pragma("unroll")                                                      \
        for (int i = 0; i < 4; i++) {                                          \
            int idx = tid + (i << 9);                                          \
            int row = idx >> 3, c = idx & 7;                                   \
            uint32_t d = st + SW128((uint32_t)((row << 7) + (c << 4)));        \
            LL go = (LL)(m0 + row) * lda + (k0) + (c << 3);                    \
            CP16(d,          Ah_b + go);                                       \
            CP16(d + 32768u, Al_b + go);                                       \
        }                                                                      \
        _Pragma("unroll")                                                      \
        for (int i = 0; i < 2; i++) {                                          \
            int idx = tid + (i << 9);                                          \
            int row = idx >> 3, c = idx & 7;                                   \
            uint32_t d = st + 65536u + SW128((uint32_t)((row << 7) + (c << 4)));\
            LL go = (LL)(n0 + row) * ldb + (k0) + (c << 3);                    \
            CP16(d,          Bh_b + go);                                       \
            CP16(d + 16384u, Bl_b + go);                                       \
        }                                                                      \
    } while (0)

    LOAD_STG(0, 0);
    CP_COMMIT();

    for (int kt = 0; kt < KT; kt++) {
        CP_WAIT0();
        __syncthreads();
        if (kt + 1 < KT) {
            LOAD_STG((kt + 1) & 1, (kt + 1) << 6);
            CP_COMMIT();
        }

        uint32_t aB = sb + (uint32_t)(kt & 1) * 98304u;
        uint32_t bB = aB + 65536u;

        #pragma unroll
        for (int ks = 0; ks < 4; ks++) {
            int kb = ks << 5;
            uint32_t ah[2][4], al[2][4];
            #pragma unroll
            for (int mf = 0; mf < 2; mf++) {
                uint32_t off = SW128((uint32_t)((wm + (mf << 4) + aro) * 128 + kb + aco));
                ldsm_x4(aB + off,          ah[mf][0], ah[mf][1], ah[mf][2], ah[mf][3]);
                ldsm_x4(aB + 32768u + off, al[mf][0], al[mf][1], al[mf][2], al[mf][3]);
            }
            #pragma unroll
            for (int ng = 0; ng < 4; ng++) {
                uint32_t off = SW128((uint32_t)((wn + (ng << 4) + bro) * 128 + kb + bco));
                uint32_t bh0, bh1, bh2, bh3, bl0, bl1, bl2, bl3;
                ldsm_x4(bB + off,          bh0, bh1, bh2, bh3);
                ldsm_x4(bB + 16384u + off, bl0, bl1, bl2, bl3);
                #pragma unroll
                for (int mf = 0; mf < 2; mf++) {
                    float* c0 = acc[mf][(ng << 1)];
                    float* c1 = acc[mf][(ng << 1) + 1];
                    mma_bf16(c0, ah[mf], bh0, bh1);
                    mma_bf16(c1, ah[mf], bh2, bh3);
                    mma_bf16(c0, ah[mf], bl0, bl1);
                    mma_bf16(c1, ah[mf], bl2, bl3);
                    mma_bf16(c0, al[mf], bh0, bh1);
                    mma_bf16(c1, al[mf], bh2, bh3);
                }
            }
        }
    }

    #pragma unroll
    for (int mf = 0; mf < 2; mf++) {
        int row0 = m0 + wm + (mf << 4) + (lane >> 2);
        #pragma unroll
        for (int nf = 0; nf < 8; nf++) {
            int col = n0 + wn + (nf << 3) + ((lane & 3) << 1);
            float* a = acc[mf][nf];
            float bx = bias[col], by = bias[col + 1];
            if (EPI == 0) {
                *(float2*)(Cb + (LL)row0 * ldc + col)       = make_float2(a[0] + bx, a[1] + by);
                *(float2*)(Cb + (LL)(row0 + 8) * ldc + col) = make_float2(a[2] + bx, a[3] + by);
            } else if (EPI == 3) {
                #pragma unroll
                for (int rr = 0; rr < 2; rr++) {
                    int row = row0 + rr * 8;
                    float v0 = a[rr*2] + bx, v1 = a[rr*2 + 1] + by;
                    LL qfb = (LL)row * 3072;
                    uint32_t hp, lp;
                    if (col < 2048) {
                        int hh = col >> 7, d = col & 127;
                        split2pack(v0 * scale, v1 * scale, hp, lp);
                        *(uint32_t*)(Fh + qfb + hh*D_QK + d) = hp;
                        *(uint32_t*)(Fl + qfb + hh*D_QK + d) = lp;
                    } else {
                        int j = col - 2048;
                        int hh = j >> 6, d = j & 63;
                        int s = row & (SEQ - 1);
                        float c  = freqs[s*D_R + d];
                        float sn = freqs[s*D_R + d + 1];
                        float r0 = (v0*c - v1*sn) * scale;
                        float r1 = (v0*sn + v1*c) * scale;
                        split2pack(r0, r1, hp, lp);
                        *(uint32_t*)(Fh + qfb + hh*D_QK + D_H + d) = hp;
                        *(uint32_t*)(Fl + qfb + hh*D_QK + D_H + d) = lp;
                    }
                }
            } else {  // EPI == 4
                #pragma unroll
                for (int rr = 0; rr < 2; rr++) {
                    int row = row0 + rr * 8;
                    float v0 = a[rr*2] + bx, v1 = a[rr*2 + 1] + by;
                    if (col < 2048) {
                        int hh = col >> 7, d = col & 127;
                        LL kfb = (LL)row * 3072;
                        uint32_t hp, lp;
                        split2pack(v0, v1, hp, lp);
                        *(uint32_t*)(Fh + kfb + hh*D_QK + D_R + d) = hp;
                        *(uint32_t*)(Fl + kfb + hh*D_QK + D_R + d) = lp;
                    } else {
                        *(float2*)(vC + (LL)row * 2048 + (col - 2048)) = make_float2(v0, v1);
                    }
                }
            }
        }
    }
}

__global__ __launch_bounds__(512, 1)
void gemm512f(const bf16* __restrict__ Ahi, const bf16* __restrict__ Alo,
              const bf16* __restrict__ Bhi, const bf16* __restrict__ Blo,
              const float* __restrict__ bias, float* __restrict__ C,
              int K, int lda, int ldb, int ldc)
{
    gemm512_body<0>(Ahi, Alo, Bhi, Blo, bias, C,
                    nullptr, nullptr, nullptr, nullptr, 0.0f,
                    blockIdx.y * 256, blockIdx.x * 128, K, lda, ldb, ldc);
}

// dual projection GEMM with fused pack epilogues
__global__ __launch_bounds__(512, 1)
void gemm512qkv(const bf16* cQh, const bf16* cQl, const bf16* Wqh, const bf16* Wql,
                const float* b2, bf16* qfh, bf16* qfl, int NX1,
                const bf16* cKVh, const bf16* cKVl, const bf16* Wkh, const bf16* Wkl,
                const float* b3, bf16* kfh, bf16* kfl, float* vC,
                const float* freqs, float scale)
{
    int xc = blockIdx.x;
    if (xc < NX1) {
        gemm512_body<3>(cQh, cQl, Wqh, Wql, b2, nullptr,
                        qfh, qfl, nullptr, freqs, scale,
                        blockIdx.y * 256, xc * 128, D_CQ, D_CQ, D_CQ, 0);
    } else {
        gemm512_body<4>(cKVh, cKVl, Wkh, Wkl, b3, nullptr,
                        kfh, kfl, vC, nullptr, 0.0f,
                        blockIdx.y * 256, (xc - NX1) * 128, D_C, D_C, D_C, 0);
    }
}

// ============ attn128: bf16x3, 128x128, BK=32, 3-stage, 2 CTAs/SM ============
template<bool CAUSAL, bool KCLIP, int EPI>   // EPI: 1=fp32, 2=bf16 splits
__global__ __launch_bounds__(256, 2)
void attn128(const bf16* __restrict__ Ahi, const bf16* __restrict__ Alo,
             const bf16* __restrict__ Bhi, const bf16* __restrict__ Blo,
             float* __restrict__ C, bf16* __restrict__ Chi, bf16* __restrict__ Clo,
             int K, int lda, int ldb, int ldc,
             LL soA, LL siA, LL soB, LL siB, LL soC, LL siC, int IC)
{
    int m0 = blockIdx.y * 128;
    int n0 = blockIdx.x * 128;
    int z = blockIdx.z;
    LL zo = z / IC, zi = z % IC;
    int tid = threadIdx.x;

    if (CAUSAL && n0 > m0) {
        float* Wb = C + zo*soC + zi*siC;
        float4 zz = make_float4(0.f, 0.f, 0.f, 0.f);
        #pragma unroll
        for (int i = 0; i < 16; i++) {
            int idx = tid + (i << 8);
            int row = idx >> 5, c4 = (idx & 31) << 2;
            *(float4*)(Wb + (LL)(m0 + row) * ldc + n0 + c4) = zz;
        }
        return;
    }

    const bf16* Ah_b = Ahi + zo*soA + zi*siA;
    const bf16* Al_b = Alo + zo*soA + zi*siA;
    const bf16* Bh_b = Bhi + zo*soB + zi*siB;
    const bf16* Bl_b = Blo + zo*soB + zi*siB;

    int Keff = KCLIP ? (m0 + 128 < K ? m0 + 128 : K) : K;
    int KT = Keff >> 5;

    extern __shared__ char sm[];
    uint32_t sb = smem_u32(sm);

    int wid = tid >> 5, lane = tid & 31;
    int wm = (wid & 3) << 5;
    int wn = (wid >> 2) << 6;
    int g = lane >> 3, r = lane & 7;
    int aro = ((g & 1) << 3) + r, aco = (g >> 1) << 4;
    int bro = ((g >> 1) << 3) + r, bco = (g & 1) << 4;

    float acc[2][8][4];
    #pragma unroll
    for (int i = 0; i < 2; i++)
        #pragma unroll
        for (int j = 0; j < 8; j++)
            #pragma unroll
            for (int t = 0; t < 4; t++) acc[i][j][t] = 0.0f;

    #define SLOAD(s, k0) do {                                                  \
        uint32_t st = sb + (uint32_t)(s) * 32768u;                             \
        _Pragma("unroll")                                                      \
        for (int i = 0; i < 2; i++) {                                          \
            int idx = tid + (i << 8);                                          \
            int row = idx >> 2, c = (idx & 3) << 4;                            \
            uint32_t sw = SW64((uint32_t)((row << 6) + c));                    \
            LL goA = (LL)(m0 + row) * lda + (k0) + ((idx & 3) << 3);           \
            LL goB = (LL)(n0 + row) * ldb + (k0) + ((idx & 3) << 3);           \
            CP16(st + sw,           Ah_b + goA);                               \
            CP16(st + 8192u  + sw,  Al_b + goA);                               \
            CP16(st + 16384u + sw,  Bh_b + goB);                               \
            CP16(st + 24576u + sw,  Bl_b + goB);                               \
        }                                                                      \
    } while (0)

    SLOAD(0, 0);  CP_COMMIT();
    SLOAD(1, 32); CP_COMMIT();

    int cs = 0, ls = 2;
    for (int kt = 0; kt < KT; kt++) {
        CP_WAIT1();
        __syncthreads();
        if (kt + 2 < KT) {
            SLOAD(ls, (kt + 2) << 5);
        }
        CP_COMMIT();
        ls++; if (ls == 3) ls = 0;

        uint32_t aB = sb + (uint32_t)cs * 32768u;
        uint32_t bB = aB + 16384u;

        #pragma unroll
        for (int ks = 0; ks < 2; ks++) {
            int kb = ks << 5;
            uint32_t ah[2][4], al[2][4];
            #pragma unroll
            for (int mf = 0; mf < 2; mf++) {
                uint32_t off = SW64((uint32_t)((wm + (mf << 4) + aro) * 64 + kb + aco));
                ldsm_x4(aB + off,         ah[mf][0], ah[mf][1], ah[mf][2], ah[mf][3]);
                ldsm_x4(aB + 8192u + off, al[mf][0], al[mf][1], al[mf][2], al[mf][3]);
            }
            #pragma unroll
            for (int ng = 0; ng < 4; ng++) {
                uint32_t off = SW64((uint32_t)((wn + (ng << 4) + bro) * 64 + kb + bco));
                uint32_t bh0, bh1, bh2, bh3, bl0, bl1, bl2, bl3;
                ldsm_x4(bB + off,         bh0, bh1, bh2, bh3);
                ldsm_x4(bB + 8192u + off, bl0, bl1, bl2, bl3);
                #pragma unroll
                for (int mf = 0; mf < 2; mf++) {
                    float* c0 = acc[mf][(ng << 1)];
                    float* c1 = acc[mf][(ng << 1) + 1];
                    mma_bf16(c0, ah[mf], bh0, bh1);
                    mma_bf16(c1, ah[mf], bh2, bh3);
                    mma_bf16(c0, ah[mf], bl0, bl1);
                    mma_bf16(c1, ah[mf], bl2, bl3);
                    mma_bf16(c0, al[mf], bh0, bh1);
                    mma_bf16(c1, al[mf], bh2, bh3);
                }
            }
        }
        cs++; if (cs == 3) cs = 0;
    }

    #pragma unroll
    for (int mf = 0; mf < 2; mf++) {
        int row = m0 + wm + (mf << 4) + (lane >> 2);
        #pragma unroll
        for (int nf = 0; nf < 8; nf++) {
            int col = n0 + wn + (nf << 3) + ((lane & 3) << 1);
            float* a = acc[mf][nf];
            if (EPI == 1) {
                float* Cb = C + zo*soC + zi*siC;
                *(float2*)(Cb + (LL)row * ldc + col)       = make_float2(a[0], a[1]);
                *(float2*)(Cb + (LL)(row + 8) * ldc + col) = make_float2(a[2], a[3]);
            } else {
                bf16* Hb = Chi + zo*soC + zi*siC;
                bf16* Lb = Clo + zo*soC + zi*siC;
                uint32_t hp, lp;
                split2pack(a[0], a[1], hp, lp);
                *(uint32_t*)(Hb + (LL)row * ldc + col) = hp;
                *(uint32_t*)(Lb + (LL)row * ldc + col) = lp;
                split2pack(a[2], a[3], hp, lp);
                *(uint32_t*)(Hb + (LL)(row + 8) * ldc + col) = hp;
                *(uint32_t*)(Lb + (LL)(row + 8) * ldc + col) = lp;
            }
        }
    }
}

// ---------------- fat-kernel device bodies ----------------
__device__ __forceinline__
void split_rm_body(const float* __restrict__ x, bf16* __restrict__ hi,
                   bf16* __restrict__ lo, int blk)
{
    LL base = ((LL)blk * 256 + threadIdx.x) * 4;
    float4 v = *(const float4*)(x + base);
    bf16 h[4], l[4];
    splitw(v.x, h[0], l[0]); splitw(v.y, h[1], l[1]);
    splitw(v.z, h[2], l[2]); splitw(v.w, h[3], l[3]);
    *(uint2*)(hi + base) = *(uint2*)h;
    *(uint2*)(lo + base) = *(uint2*)l;
}

__device__ __forceinline__
void split_tr_body(const float* __restrict__ x, int ldx,
                   bf16* __restrict__ hi, bf16* __restrict__ lo,
                   int R, int bx, int by)
{
    __shared__ float s[32][33];
    int tx = threadIdx.x & 31, ty = threadIdx.x >> 5;
    int r0 = by * 32, c0 = bx * 32;
    #pragma unroll
    for (int j = 0; j < 4; j++)
        s[ty + 8*j][tx] = x[(LL)(r0 + ty + 8*j) * ldx + c0 + tx];
    __syncthreads();
    #pragma unroll
    for (int j = 0; j < 4; j++) {
        float v = s[tx][ty + 8*j];
        bf16 h, l; splitw(v, h, l);
        LL o = (LL)(c0 + ty + 8*j) * R + r0 + tx;
        hi[o] = h; lo[o] = l;
    }
    __syncthreads();
}

__device__ __forceinline__
void zfill_body(bf16* __restrict__ p, int blk)
{
    LL i = ((LL)blk * 256 + threadIdx.x) * 2;
    *(uint32_t*)(p + i) = 0u;
}

__device__ __forceinline__
void biascat_body(const float* bqd, const float* bkv, const float* bkr,
                  const float* bqc, const float* bqr,
                  const float* bkc, const float* bvc,
                  float* b1, float* b2, float* b3, int blk)
{
    int i = blk * 256 + threadIdx.x;
    if (i < N1) {
        float v = 0.0f;
        if (i < 1536) v = bqd[i];
        else if (i < 2048) v = bkv[i - 1536];
        else if (i < 2112) v = bkr[i - 2048];
        b1[i] = v;
    }
    if (i < 2048) b2[i] = bqc[i]; else if (i < 3072) b2[i] = bqr[i - 2048];
    if (i < 2048) b3[i] = bkc[i]; else if (i < 4096) b3[i] = bvc[i - 2048];
}

#define NB_RM   16384
#define NB_WQD  (48*64)
#define NB_WKV  (16*64)
#define NB_WKR  (2*64)
#define NB_ZF   256
#define NB_BIAS 16
#define NB_WQC  (64*48)
#define NB_WQR  (32*48)
#define NB_WKC  (64*16)
#define NB_WVC  (64*16)
#define NB_WO   (64*64)
#define PREP_TOTAL (NB_RM+NB_WQD+NB_WKV+NB_WKR+2*NB_ZF+NB_BIAS+NB_WQC+NB_WQR+NB_WKC+NB_WVC+NB_WO)

__global__ __launch_bounds__(256)
void prep_all(const float* h, const float* Wqd, const float* Wkv, const float* Wkr,
              const float* Wqc, const float* Wqr, const float* Wkc, const float* Wvc,
              const float* Wo,
              const float* bqd, const float* bkv, const float* bkr,
              const float* bqc, const float* bqr, const float* bkc, const float* bvc,
              bf16* h_hi, bf16* h_lo, bf16* WdT_hi, bf16* WdT_lo,
              bf16* WqcrT_hi, bf16* WqcrT_lo, bf16* WkvcT_hi, bf16* WkvcT_lo,
              bf16* WoT_hi, bf16* WoT_lo,
              float* b1, float* b2, float* b3)
{
    int b = blockIdx.x;
    if (b < NB_RM) { split_rm_body(h, h_hi, h_lo, b); return; }
    b -= NB_RM;
    if (b < NB_WQD) { split_tr_body(Wqd, D_CQ, WdT_hi, WdT_lo, D_MODEL, b % 48, b / 48); return; }
    b -= NB_WQD;
    if (b < NB_WKV) {
        split_tr_body(Wkv, D_C, WdT_hi + (LL)D_CQ*D_MODEL, WdT_lo + (LL)D_CQ*D_MODEL,
                      D_MODEL, b % 16, b / 16);
        return;
    }
    b -= NB_WKV;
    if (b < NB_WKR) {
        split_tr_body(Wkr, D_R, WdT_hi + (LL)2048*D_MODEL, WdT_lo + (LL)2048*D_MODEL,
                      D_MODEL, b % 2, b / 2);
        return;
    }
    b -= NB_WKR;
    if (b < NB_ZF) { zfill_body(WdT_hi + (LL)2112*D_MODEL, b); return; }
    b -= NB_ZF;
    if (b < NB_ZF) { zfill_body(WdT_lo + (LL)2112*D_MODEL, b); return; }
    b -= NB_ZF;
    if (b < NB_BIAS) { biascat_body(bqd, bkv, bkr, bqc, bqr, bkc, bvc, b1, b2, b3, b); return; }
    b -= NB_BIAS;
    if (b < NB_WQC) { split_tr_body(Wqc, 2048, WqcrT_hi, WqcrT_lo, D_CQ, b % 64, b / 64); return; }
    b -= NB_WQC;
    if (b < NB_WQR) {
        split_tr_body(Wqr, 1024, WqcrT_hi + (LL)2048*D_CQ, WqcrT_lo + (LL)2048*D_CQ,
                      D_CQ, b % 32, b / 32);
        return;
    }
    b -= NB_WQR;
    if (b < NB_WKC) { split_tr_body(Wkc, 2048, WkvcT_hi, WkvcT_lo, D_C, b % 64, b / 64); return; }
    b -= NB_WKC;
    if (b < NB_WVC) {
        split_tr_body(Wvc, 2048, WkvcT_hi + (LL)2048*D_C, WkvcT_lo + (LL)2048*D_C,
                      D_C, b % 64, b / 64);
        return;
    }
    b -= NB_WVC;
    split_tr_body(Wo, 2048, WoT_hi, WoT_lo, 2048, b % 64, b / 64);
}

// ---------------- fused rmsnorm over all three slices of tmp12 ----------------
__global__ __launch_bounds__(256)
void rmsnorm_all(const float* __restrict__ x,
                 const float* __restrict__ gq, const float* __restrict__ gkv,
                 const float* __restrict__ gkr,
                 bf16* __restrict__ cQh, bf16* __restrict__ cQl,
                 bf16* __restrict__ cKVh, bf16* __restrict__ cKVl,
                 float* __restrict__ krn)
{
    LL xb = (LL)blockIdx.x * N1;
    int tid = threadIdx.x;
    __shared__ float red[256];

    float s = 0.0f;
    #pragma unroll
    for (int i = 0; i < 6; i++) { float v = x[xb + tid + (i << 8)]; s += v * v; }
    red[tid] = s; __syncthreads();
    for (int st = 128; st > 0; st >>= 1) {
        if (tid < st) red[tid] += red[tid + st];
        __syncthreads();
    }
    float rs = rsqrtf(red[0] / (float)D_CQ + 1e-6f);
    LL yb = (LL)blockIdx.x * D_CQ;
    #pragma unroll
    for (int i = 0; i < 6; i++) {
        int idx = tid + (i << 8);
        float v = x[xb + idx] * rs * gq[idx];
        bf16 h, l; splitw(v, h, l);
        cQh[yb + idx] = h; cQl[yb + idx] = l;
    }
    __syncthreads();

    s = 0.0f;
    #pragma unroll
    for (int i = 0; i < 2; i++) { float v = x[xb + 1536 + tid + (i << 8)]; s += v * v; }
    red[tid] = s; __syncthreads();
    for (int st = 128; st > 0; st >>= 1) {
        if (tid < st) red[tid] += red[tid + st];
        __syncthreads();
    }
    rs = rsqrtf(red[0] / (float)D_C + 1e-6f);
    yb = (LL)blockIdx.x * D_C;
    #pragma unroll
    for (int i = 0; i < 2; i++) {
        int idx = tid + (i << 8);
        float v = x[xb + 1536 + idx] * rs * gkv[idx];
        bf16 h, l; splitw(v, h, l);
        cKVh[yb + idx] = h; cKVl[yb + idx] = l;
    }
    __syncthreads();

    float v3 = (tid < D_R) ? x[xb + 2048 + tid] : 0.0f;
    red[tid] = v3 * v3; __syncthreads();
    for (int st = 128; st > 0; st >>= 1) {
        if (tid < st) red[tid] += red[tid + st];
        __syncthreads();
    }
    rs = rsqrtf(red[0] / (float)D_R + 1e-6f);
    if (tid < D_R)
        krn[(LL)blockIdx.x * D_R + tid] = v3 * rs * gkr[tid];
}

// ---------------- kR broadcast body (RoPE on krn -> kf heads) ----------------
__device__ __forceinline__
void pack_kr_body(const float* __restrict__ krn, const float* __restrict__ freqs,
                  bf16* __restrict__ kfh, bf16* __restrict__ kfl, int bs)
{
    int s  = bs & (SEQ - 1);
    LL kfb = (LL)bs * 3072;
    int tid = threadIdx.x;

    __shared__ uint32_t krh[32], krl[32];
    if (tid < 32) {
        int i = tid;
        float a = krn[(LL)bs*D_R + 2*i];
        float b = krn[(LL)bs*D_R + 2*i + 1];
        float c  = freqs[(LL)s*D_R + 2*i];
        float sn = freqs[(LL)s*D_R + 2*i + 1];
        float r0 = a*c - b*sn;
        float r1 = a*sn + b*c;
        uint32_t hp, lp;
        split2pack(r0, r1, hp, lp);
        krh[i] = hp; krl[i] = lp;
    }
    __syncthreads();

    // 16 heads x 32 uint32 pairs = 512 stores x2
    #pragma unroll
    for (int it = 0; it < 2; it++) {
        int idx = tid + (it << 8);
        int hh = idx >> 5, p = idx & 31;
        LL o = kfb + hh*D_QK + (p << 1);
        *(uint32_t*)(kfh + o) = krh[p];
        *(uint32_t*)(kfl + o) = krl[p];
    }
}

// post_all: vCT split (16384 blocks) + kR broadcast (8192 blocks)
#define NB_VCT (64*256)
__global__ __launch_bounds__(256)
void post_all(const float* vC, bf16* vCT_hi, bf16* vCT_lo,
              const float* krn, const float* freqs,
              bf16* kfh, bf16* kfl)
{
    int b = blockIdx.x;
    if (b < NB_VCT) {
        split_tr_body(vC, 2048, vCT_hi, vCT_lo, NTOK, b % 64, b / 64);
        return;
    }
    b -= NB_VCT;
    pack_kr_body(krn, freqs, kfh, kfl, b);
}

// ---------------- causal softmax + bf16 split emission (k < kLim only) ----------------
__global__ __launch_bounds__(256)
void softmax_kernel(float* __restrict__ w, bf16* __restrict__ wh, bf16* __restrict__ wl)
{
    LL row = blockIdx.x;
    int q = (int)(row & (SEQ - 1));
    float* base = w + row * (LL)SEQ;
    bf16* bh = wh + row * (LL)SEQ;
    bf16* bl = wl + row * (LL)SEQ;
    int tid = threadIdx.x;

    float vals[8];
    float mx = -INFINITY;
    #pragma unroll
    for (int it = 0; it < 8; it++) {
        int k = tid + it * 256;
        float v = -INFINITY;
        if (k <= q) v = base[k];
        vals[it] = v;
        mx = fmaxf(mx, v);
    }
    __shared__ float red[256];
    red[tid] = mx; __syncthreads();
    for (int st = 128; st > 0; st >>= 1) {
        if (tid < st) red[tid] = fmaxf(red[tid], red[tid + st]);
        __syncthreads();
    }
    mx = red[0]; __syncthreads();

    float sum = 0.0f;
    #pragma unroll
    for (int it = 0; it < 8; it++) {
        float e = (vals[it] == -INFINITY) ? 0.0f : __expf(vals[it] - mx);
        vals[it] = e;
        sum += e;
    }
    red[tid] = sum; __syncthreads();
    for (int st = 128; st > 0; st >>= 1) {
        if (tid < st) red[tid] += red[tid + st];
        __syncthreads();
    }
    float inv = 1.0f / red[0];

    int kLim = ((q >> 7) + 1) << 7;
    #pragma unroll
    for (int it = 0; it < 8; it++) {
        int k = tid + it * 256;
        if (k < kLim) {
            float p = vals[it] * inv;
            base[k] = p;
            bf16 h, l; splitw(p, h, l);
            bh[k] = h; bl[k] = l;
        }
    }
}

// ---------------- host ----------------
#define SYMF(name) ({ void* p_; cudaGetSymbolAddress(&p_, name); (float*)p_; })
#define SYMB(name) ({ void* p_; cudaGetSymbolAddress(&p_, name); (bf16*)p_; })

#define G512_SMEM  196608
#define A128_SMEM  98304

extern "C" void kernel_launch(void* const* d_in, const int* in_sizes, int n_in,
                              void* d_out, int out_size)
{
    (void)in_sizes; (void)n_in; (void)out_size;
    const float* h       = (const float*)d_in[0];
    const float* freqs   = (const float*)d_in[1];
    const float* Wq_down = (const float*)d_in[3];
    const float* bq_down = (const float*)d_in[4];
    const float* gq_norm = (const float*)d_in[5];
    const float* Wqc     = (const float*)d_in[6];
    const float* bqc     = (const float*)d_in[7];
    const float* Wqr     = (const float*)d_in[8];
    const float* bqr     = (const float*)d_in[9];
    const float* Wkr     = (const float*)d_in[10];
    const float* bkr     = (const float*)d_in[11];
    const float* gkr     = (const float*)d_in[12];
    const float* Wkv     = (const float*)d_in[13];
    const float* bkv     = (const float*)d_in[14];
    const float* gkv     = (const float*)d_in[15];
    const float* Wkc     = (const float*)d_in[16];
    const float* bkc     = (const float*)d_in[17];
    const float* Wvc     = (const float*)d_in[18];
    const float* bvc     = (const float*)d_in[19];
    const float* Wo      = (const float*)d_in[20];
    const float* bo      = (const float*)d_in[21];

    float* out_h = (float*)d_out;
    float* w     = out_h + (LL)NTOK * D_MODEL;

    float* tmp12 = SYMF(g_tmp12);
    float* vC = SYMF(g_vC);
    float* krn = SYMF(g_krn);
    float* b1 = SYMF(g_bias1); float* b2 = SYMF(g_bias2); float* b3 = SYMF(g_bias3);

    bf16 *h_hi = SYMB(g_h_hi), *h_lo = SYMB(g_h_lo);
    bf16 *WdT_hi = SYMB(g_WdT_hi), *WdT_lo = SYMB(g_WdT_lo);
    bf16 *WqcrT_hi = SYMB(g_WqcrT_hi), *WqcrT_lo = SYMB(g_WqcrT_lo);
    bf16 *WkvcT_hi = SYMB(g_WkvcT_hi), *WkvcT_lo = SYMB(g_WkvcT_lo);
    bf16 *WoT_hi  = SYMB(g_WoT_hi),  *WoT_lo  = SYMB(g_WoT_lo);
    bf16 *cQ_hi = SYMB(g_cQ_hi), *cQ_lo = SYMB(g_cQ_lo);
    bf16 *cKV_hi = SYMB(g_cKV_hi), *cKV_lo = SYMB(g_cKV_lo);
    bf16 *qf_hi = SYMB(g_qf_hi), *qf_lo = SYMB(g_qf_lo);
    bf16 *kf_hi = SYMB(g_kf_hi), *kf_lo = SYMB(g_kf_lo);
    bf16 *vCT_hi = SYMB(g_vCT_hi), *vCT_lo = SYMB(g_vCT_lo);
    bf16 *w_hi = SYMB(g_w_hi), *w_lo = SYMB(g_w_lo);
    bf16 *attn_hi = SYMB(g_attn_hi), *attn_lo = SYMB(g_attn_lo);

    cudaFuncSetAttribute((const void*)gemm512f,   cudaFuncAttributeMaxDynamicSharedMemorySize, G512_SMEM);
    cudaFuncSetAttribute((const void*)gemm512qkv, cudaFuncAttributeMaxDynamicSharedMemorySize, G512_SMEM);
    cudaFuncSetAttribute((const void*)attn128<true,false,1>, cudaFuncAttributeMaxDynamicSharedMemorySize, A128_SMEM);
    cudaFuncSetAttribute((const void*)attn128<false,true,2>, cudaFuncAttributeMaxDynamicSharedMemorySize, A128_SMEM);

    // 1) all input-derived prep in ONE launch
    prep_all<<<PREP_TOTAL, 256>>>(
        h, Wq_down, Wkv, Wkr, Wqc, Wqr, Wkc, Wvc, Wo,
        bq_down, bkv, bkr, bqc, bqr, bkc, bvc,
        h_hi, h_lo, WdT_hi, WdT_lo, WqcrT_hi, WqcrT_lo, WkvcT_hi, WkvcT_lo,
        WoT_hi, WoT_lo, b1, b2, b3);

    // 2) merged first GEMM: tmp12 = h @ [Wq_down | Wkv | Wkr | 0] + bias
    gemm512f<<<dim3(N1/128, NTOK/256), 512, G512_SMEM>>>(
        h_hi, h_lo, WdT_hi, WdT_lo, b1, tmp12, D_MODEL, D_MODEL, D_MODEL, N1);

    // 3) fused norms
    rmsnorm_all<<<NTOK, 256>>>(tmp12, gq_norm, gkv, gkr,
                               cQ_hi, cQ_lo, cKV_hi, cKV_lo, krn);

    // 4) dual projection with FUSED pack epilogues: qf (RoPE+scale) and kf/vC
    gemm512qkv<<<dim3(3072/128 + 4096/128, NTOK/256), 512, G512_SMEM>>>(
        cQ_hi, cQ_lo, WqcrT_hi, WqcrT_lo, b2, qf_hi, qf_lo, 3072/128,
        cKV_hi, cKV_lo, WkvcT_hi, WkvcT_lo, b3, kf_hi, kf_lo, vC,
        freqs, 1.0f / sqrtf((float)D_QK));

    // 5) vCT split + kR broadcast in ONE launch
    post_all<<<NB_VCT + NTOK, 256>>>(vC, vCT_hi, vCT_lo, krn, freqs, kf_hi, kf_lo);

    // 6) scores = q k^T (causal; upper tiles zero-fill w)
    {
        LL soQK = (LL)SEQ * N_HEADS * D_QK, siQK = D_QK;
        LL soW  = (LL)N_HEADS * SEQ * SEQ,  siW  = (LL)SEQ * SEQ;
        attn128<true,false,1><<<dim3(SEQ/128, SEQ/128, BSZ*N_HEADS), 256, A128_SMEM>>>(
            qf_hi, qf_lo, kf_hi, kf_lo, w, nullptr, nullptr,
            D_QK, N_HEADS*D_QK, N_HEADS*D_QK, SEQ,
            soQK, siQK, soQK, siQK, soW, siW, N_HEADS);
    }

    // 7) softmax
    softmax_kernel<<<(LL)BSZ*N_HEADS*SEQ, 256>>>(w, w_hi, w_lo);

    // 8) PV
    {
        LL soW = (LL)N_HEADS * SEQ * SEQ, siW = (LL)SEQ * SEQ;
        LL soB = 2048;
        LL siB = (LL)D_H * NTOK;
        LL soC = (LL)SEQ * 2048, siC = D_H;
        attn128<false,true,2><<<dim3(D_H/128, SEQ/128, BSZ*N_HEADS), 256, A128_SMEM>>>(
            w_hi, w_lo, vCT_hi, vCT_lo, nullptr, attn_hi, attn_lo,
            SEQ, SEQ, NTOK, 2048,
            soW, siW, soB, siB, soC, siC, N_HEADS);
    }

    // 9) h_out = attn @ Wo + bo
    gemm512f<<<dim3(2048/128, NTOK/256), 512, G512_SMEM>>>(
        attn_hi, attn_lo, WoT_hi, WoT_lo, bo, out_h, 2048, 2048, 2048, 2048);
}

// round 17
// speedup vs baseline: 1.0757x; 1.0094x over previous
#include <cuda_runtime.h>
#include <cuda_bf16.h>
#include <math.h>
#include <stdint.h>

#define D_MODEL 2048
#define N_HEADS 16
#define D_CQ    1536
#define D_C     512
#define D_H     128
#define D_R     64
#define BSZ     4
#define SEQ     2048
#define NTOK    (BSZ*SEQ)
#define D_QK    (D_H + D_R)
#define LL long long

#define SW128(o) ((o) ^ (((o) >> 3) & 0x70))
#define SW64(o)  ((o) ^ (((o) >> 2) & 0x30))

#define N1 2176   // merged first-GEMM N: Wqd(1536) | Wkv(512) | Wkr(64) | pad(64)

typedef __nv_bfloat16 bf16;

// ---------------- scratch ----------------
__device__ float g_tmp12[(LL)NTOK * N1];
__device__ float g_vC  [(LL)NTOK * 2048];
__device__ float g_krn [(LL)NTOK * D_R];
__device__ bf16 g_h_hi[(LL)NTOK * D_MODEL],      g_h_lo[(LL)NTOK * D_MODEL];
__device__ bf16 g_WdT_hi[(LL)N1 * D_MODEL],      g_WdT_lo[(LL)N1 * D_MODEL];
__device__ bf16 g_WqcrT_hi[(LL)3072 * D_CQ],     g_WqcrT_lo[(LL)3072 * D_CQ];
__device__ bf16 g_WkvcT_hi[(LL)4096 * D_C],      g_WkvcT_lo[(LL)4096 * D_C];
__device__ bf16 g_WoT_hi[(LL)2048 * 2048],       g_WoT_lo[(LL)2048 * 2048];
__device__ bf16 g_cQ_hi[(LL)NTOK * D_CQ],        g_cQ_lo[(LL)NTOK * D_CQ];
__device__ bf16 g_cKV_hi[(LL)NTOK * D_C],        g_cKV_lo[(LL)NTOK * D_C];
__device__ bf16 g_qf_hi[(LL)NTOK * N_HEADS*D_QK], g_qf_lo[(LL)NTOK * N_HEADS*D_QK];
__device__ bf16 g_kf_hi[(LL)NTOK * N_HEADS*D_QK], g_kf_lo[(LL)NTOK * N_HEADS*D_QK];
__device__ bf16 g_vCT_hi[(LL)2048 * NTOK],       g_vCT_lo[(LL)2048 * NTOK];
__device__ bf16 g_w_hi[(LL)BSZ*N_HEADS*SEQ*SEQ], g_w_lo[(LL)BSZ*N_HEADS*SEQ*SEQ];
__device__ bf16 g_attn_hi[(LL)NTOK * 2048],      g_attn_lo[(LL)NTOK * 2048];
__device__ float g_bias1[N1];
__device__ float g_bias2[3072];
__device__ float g_bias3[4096];

// ---------------- helpers ----------------
__device__ __forceinline__ uint32_t smem_u32(const void* p) {
    uint32_t a;
    asm("{ .reg .u64 t; cvta.to.shared.u64 t, %1; cvt.u32.u64 %0, t; }" : "=r"(a) : "l"(p));
    return a;
}
#define CP16(d, s) asm volatile("cp.async.cg.shared.global [%0], [%1], 16;" :: "r"(d), "l"(s))
#define CP_COMMIT() asm volatile("cp.async.commit_group;" ::: "memory")
#define CP_WAIT1() asm volatile("cp.async.wait_group 1;" ::: "memory")
#define CP_WAIT0() asm volatile("cp.async.wait_group 0;" ::: "memory")

__device__ __forceinline__ void ldsm_x4(uint32_t addr, uint32_t& r0, uint32_t& r1,
                                        uint32_t& r2, uint32_t& r3) {
    asm volatile("ldmatrix.sync.aligned.m8n8.x4.shared.b16 {%0,%1,%2,%3}, [%4];"
                 : "=r"(r0), "=r"(r1), "=r"(r2), "=r"(r3) : "r"(addr));
}
__device__ __forceinline__ void mma_bf16(float* c, const uint32_t* a,
                                         uint32_t b0, uint32_t b1) {
    asm volatile(
        "mma.sync.aligned.m16n8k16.row.col.f32.bf16.bf16.f32 "
        "{%0,%1,%2,%3}, {%4,%5,%6,%7}, {%8,%9}, {%0,%1,%2,%3};"
        : "+f"(c[0]), "+f"(c[1]), "+f"(c[2]), "+f"(c[3])
        : "r"(a[0]), "r"(a[1]), "r"(a[2]), "r"(a[3]), "r"(b0), "r"(b1));
}
__device__ __forceinline__ void splitw(float v, bf16& hi, bf16& lo) {
    hi = __float2bfloat16(v);
    lo = __float2bfloat16(v - __bfloat162float(hi));
}
__device__ __forceinline__ void split2pack(float f0, float f1, uint32_t& hp, uint32_t& lp) {
    bf16 h0, l0, h1, l1;
    splitw(f0, h0, l0); splitw(f1, h1, l1);
    hp = ((uint32_t)__bfloat16_as_ushort(h1) << 16) | __bfloat16_as_ushort(h0);
    lp = ((uint32_t)__bfloat16_as_ushort(l1) << 16) | __bfloat16_as_ushort(l0);
}

// ============ gemm512 body: 256x128 tile, 512 threads, BK=64, 2-stage ============
// EPI 0: fp32 + bias -> Cb
// EPI 3: q epilogue: bias, (RoPE for col>=2048), *scale, split -> qf layout
// EPI 4: kv epilogue: col<2048 -> kf splits (offset 64); col>=2048 -> fp32 vC
template<int EPI>
__device__ __forceinline__
void gemm512_body(const bf16* __restrict__ Ah_b, const bf16* __restrict__ Al_b,
                  const bf16* __restrict__ Bh_b, const bf16* __restrict__ Bl_b,
                  const float* __restrict__ bias, float* __restrict__ Cb,
                  bf16* __restrict__ Fh, bf16* __restrict__ Fl,
                  float* __restrict__ vC, const float* __restrict__ freqs, float scale,
                  int m0, int n0, int K, int lda, int ldb, int ldc)
{
    int KT = K >> 6;

    extern __shared__ char sm[];
    uint32_t sb = smem_u32(sm);

    int tid = threadIdx.x;
    int wid = tid >> 5, lane = tid & 31;
    int wm = (wid & 7) << 5;
    int wn = (wid >> 3) << 6;
    int g = lane >> 3, r = lane & 7;
    int aro = ((g & 1) << 3) + r, aco = (g >> 1) << 4;
    int bro = ((g >> 1) << 3) + r, bco = (g & 1) << 4;

    float acc[2][8][4];
    #pragma unroll
    for (int i = 0; i < 2; i++)
        #pragma unroll
        for (int j = 0; j < 8; j++)
            #pragma unroll
            for (int t = 0; t < 4; t++) acc[i][j][t] = 0.0f;

    #define LOAD_STG(s, k0) do {                                               \
        uint32_t st = sb + (uint32_t)(s) * 98304u;                             \
        _Pragma("unroll")                                                      \
        for (int i = 0; i < 4; i++) {                                          \
            int idx = tid + (i << 9);                                          \
            int row = idx >> 3, c = idx & 7;                                   \
            uint32_t d = st + SW128((uint32_t)((row << 7) + (c << 4)));        \
            LL go = (LL)(m0 + row) * lda + (k0) + (c << 3);                    \
            CP16(d,          Ah_b + go);                                       \
            CP16(d + 32768u, Al_b + go);                                       \
        }                                                                      \
        _Pragma("unroll")                                                      \
        for (int i = 0; i < 2; i++) {                                          \
            int idx = tid + (i << 9);                                          \
            int row = idx >> 3, c = idx & 7;                                   \
            uint32_t d = st + 65536u + SW128((uint32_t)((row << 7) + (c << 4)));\
            LL go = (LL)(n0 + row) * ldb + (k0) + (c << 3);                    \
            CP16(d,          Bh_b + go);                                       \
            CP16(d + 16384u, Bl_b + go);                                       \
        }                                                                      \
    } while (0)

    LOAD_STG(0, 0);
    CP_COMMIT();

    for (int kt = 0; kt < KT; kt++) {
        CP_WAIT0();
        __syncthreads();
        if (kt + 1 < KT) {
            LOAD_STG((kt + 1) & 1, (kt + 1) << 6);
            CP_COMMIT();
        }

        uint32_t aB = sb + (uint32_t)(kt & 1) * 98304u;
        uint32_t bB = aB + 65536u;

        #pragma unroll
        for (int ks = 0; ks < 4; ks++) {
            int kb = ks << 5;
            uint32_t ah[2][4], al[2][4];
            #pragma unroll
            for (int mf = 0; mf < 2; mf++) {
                uint32_t off = SW128((uint32_t)((wm + (mf << 4) + aro) * 128 + kb + aco));
                ldsm_x4(aB + off,          ah[mf][0], ah[mf][1], ah[mf][2], ah[mf][3]);
                ldsm_x4(aB + 32768u + off, al[mf][0], al[mf][1], al[mf][2], al[mf][3]);
            }
            #pragma unroll
            for (int ng = 0; ng < 4; ng++) {
                uint32_t off = SW128((uint32_t)((wn + (ng << 4) + bro) * 128 + kb + bco));
                uint32_t bh0, bh1, bh2, bh3, bl0, bl1, bl2, bl3;
                ldsm_x4(bB + off,          bh0, bh1, bh2, bh3);
                ldsm_x4(bB + 16384u + off, bl0, bl1, bl2, bl3);
                #pragma unroll
                for (int mf = 0; mf < 2; mf++) {
                    float* c0 = acc[mf][(ng << 1)];
                    float* c1 = acc[mf][(ng << 1) + 1];
                    mma_bf16(c0, ah[mf], bh0, bh1);
                    mma_bf16(c1, ah[mf], bh2, bh3);
                    mma_bf16(c0, ah[mf], bl0, bl1);
                    mma_bf16(c1, ah[mf], bl2, bl3);
                    mma_bf16(c0, al[mf], bh0, bh1);
                    mma_bf16(c1, al[mf], bh2, bh3);
                }
            }
        }
    }

    #pragma unroll
    for (int mf = 0; mf < 2; mf++) {
        int row0 = m0 + wm + (mf << 4) + (lane >> 2);
        #pragma unroll
        for (int nf = 0; nf < 8; nf++) {
            int col = n0 + wn + (nf << 3) + ((lane & 3) << 1);
            float* a = acc[mf][nf];
            float bx = bias[col], by = bias[col + 1];
            if (EPI == 0) {
                *(float2*)(Cb + (LL)row0 * ldc + col)       = make_float2(a[0] + bx, a[1] + by);
                *(float2*)(Cb + (LL)(row0 + 8) * ldc + col) = make_float2(a[2] + bx, a[3] + by);
            } else if (EPI == 3) {
                #pragma unroll
                for (int rr = 0; rr < 2; rr++) {
                    int row = row0 + rr * 8;
                    float v0 = a[rr*2] + bx, v1 = a[rr*2 + 1] + by;
                    LL qfb = (LL)row * 3072;
                    uint32_t hp, lp;
                    if (col < 2048) {
                        int hh = col >> 7, d = col & 127;
                        split2pack(v0 * scale, v1 * scale, hp, lp);
                        *(uint32_t*)(Fh + qfb + hh*D_QK + d) = hp;
                        *(uint32_t*)(Fl + qfb + hh*D_QK + d) = lp;
                    } else {
                        int j = col - 2048;
                        int hh = j >> 6, d = j & 63;
                        int s = row & (SEQ - 1);
                        float c  = freqs[s*D_R + d];
                        float sn = freqs[s*D_R + d + 1];
                        float r0 = (v0*c - v1*sn) * scale;
                        float r1 = (v0*sn + v1*c) * scale;
                        split2pack(r0, r1, hp, lp);
                        *(uint32_t*)(Fh + qfb + hh*D_QK + D_H + d) = hp;
                        *(uint32_t*)(Fl + qfb + hh*D_QK + D_H + d) = lp;
                    }
                }
            } else {  // EPI == 4
                #pragma unroll
                for (int rr = 0; rr < 2; rr++) {
                    int row = row0 + rr * 8;
                    float v0 = a[rr*2] + bx, v1 = a[rr*2 + 1] + by;
                    if (col < 2048) {
                        int hh = col >> 7, d = col & 127;
                        LL kfb = (LL)row * 3072;
                        uint32_t hp, lp;
                        split2pack(v0, v1, hp, lp);
                        *(uint32_t*)(Fh + kfb + hh*D_QK + D_R + d) = hp;
                        *(uint32_t*)(Fl + kfb + hh*D_QK + D_R + d) = lp;
                    } else {
                        *(float2*)(vC + (LL)row * 2048 + (col - 2048)) = make_float2(v0, v1);
                    }
                }
            }
        }
    }
}

__global__ __launch_bounds__(512, 1)
void gemm512f(const bf16* __restrict__ Ahi, const bf16* __restrict__ Alo,
              const bf16* __restrict__ Bhi, const bf16* __restrict__ Blo,
              const float* __restrict__ bias, float* __restrict__ C,
              int K, int lda, int ldb, int ldc)
{
    gemm512_body<0>(Ahi, Alo, Bhi, Blo, bias, C,
                    nullptr, nullptr, nullptr, nullptr, 0.0f,
                    blockIdx.y * 256, blockIdx.x * 128, K, lda, ldb, ldc);
}

__global__ __launch_bounds__(512, 1)
void gemm512qkv(const bf16* cQh, const bf16* cQl, const bf16* Wqh, const bf16* Wql,
                const float* b2, bf16* qfh, bf16* qfl, int NX1,
                const bf16* cKVh, const bf16* cKVl, const bf16* Wkh, const bf16* Wkl,
                const float* b3, bf16* kfh, bf16* kfl, float* vC,
                const float* freqs, float scale)
{
    int xc = blockIdx.x;
    if (xc < NX1) {
        gemm512_body<3>(cQh, cQl, Wqh, Wql, b2, nullptr,
                        qfh, qfl, nullptr, freqs, scale,
                        blockIdx.y * 256, xc * 128, D_CQ, D_CQ, D_CQ, 0);
    } else {
        gemm512_body<4>(cKVh, cKVl, Wkh, Wkl, b3, nullptr,
                        kfh, kfl, vC, nullptr, 0.0f,
                        blockIdx.y * 256, (xc - NX1) * 128, D_C, D_C, D_C, 0);
    }
}

// ============ attn128: bf16x3, 128x128, BK=32, 3-stage, 2 CTAs/SM ============
template<bool CAUSAL, bool KCLIP, int EPI>   // EPI: 1=fp32, 2=bf16 splits
__global__ __launch_bounds__(256, 2)
void attn128(const bf16* __restrict__ Ahi, const bf16* __restrict__ Alo,
             const bf16* __restrict__ Bhi, const bf16* __restrict__ Blo,
             float* __restrict__ C, bf16* __restrict__ Chi, bf16* __restrict__ Clo,
             int K, int lda, int ldb, int ldc,
             LL soA, LL siA, LL soB, LL siB, LL soC, LL siC, int IC)
{
    // KCLIP (PV): issue longest-K tiles first to pack the wave tail
    int my = KCLIP ? (gridDim.y - 1 - blockIdx.y) : blockIdx.y;
    int m0 = my * 128;
    int n0 = blockIdx.x * 128;
    int z = blockIdx.z;
    LL zo = z / IC, zi = z % IC;
    int tid = threadIdx.x;

    if (CAUSAL && n0 > m0) {
        float* Wb = C + zo*soC + zi*siC;
        float4 zz = make_float4(0.f, 0.f, 0.f, 0.f);
        #pragma unroll
        for (int i = 0; i < 16; i++) {
            int idx = tid + (i << 8);
            int row = idx >> 5, c4 = (idx & 31) << 2;
            *(float4*)(Wb + (LL)(m0 + row) * ldc + n0 + c4) = zz;
        }
        return;
    }

    const bf16* Ah_b = Ahi + zo*soA + zi*siA;
    const bf16* Al_b = Alo + zo*soA + zi*siA;
    const bf16* Bh_b = Bhi + zo*soB + zi*siB;
    const bf16* Bl_b = Blo + zo*soB + zi*siB;

    int Keff = KCLIP ? (m0 + 128 < K ? m0 + 128 : K) : K;
    int KT = Keff >> 5;

    extern __shared__ char sm[];
    uint32_t sb = smem_u32(sm);

    int wid = tid >> 5, lane = tid & 31;
    int wm = (wid & 3) << 5;
    int wn = (wid >> 2) << 6;
    int g = lane >> 3, r = lane & 7;
    int aro = ((g & 1) << 3) + r, aco = (g >> 1) << 4;
    int bro = ((g >> 1) << 3) + r, bco = (g & 1) << 4;

    float acc[2][8][4];
    #pragma unroll
    for (int i = 0; i < 2; i++)
        #pragma unroll
        for (int j = 0; j < 8; j++)
            #pragma unroll
            for (int t = 0; t < 4; t++) acc[i][j][t] = 0.0f;

    #define SLOAD(s, k0) do {                                                  \
        uint32_t st = sb + (uint32_t)(s) * 32768u;                             \
        _Pragma("unroll")                                                      \
        for (int i = 0; i < 2; i++) {                                          \
            int idx = tid + (i << 8);                                          \
            int row = idx >> 2, c = (idx & 3) << 4;                            \
            uint32_t sw = SW64((uint32_t)((row << 6) + c));                    \
            LL goA = (LL)(m0 + row) * lda + (k0) + ((idx & 3) << 3);           \
            LL goB = (LL)(n0 + row) * ldb + (k0) + ((idx & 3) << 3);           \
            CP16(st + sw,           Ah_b + goA);                               \
            CP16(st + 8192u  + sw,  Al_b + goA);                               \
            CP16(st + 16384u + sw,  Bh_b + goB);                               \
            CP16(st + 24576u + sw,  Bl_b + goB);                               \
        }                                                                      \
    } while (0)

    SLOAD(0, 0);  CP_COMMIT();
    SLOAD(1, 32); CP_COMMIT();

    int cs = 0, ls = 2;
    for (int kt = 0; kt < KT; kt++) {
        CP_WAIT1();
        __syncthreads();
        if (kt + 2 < KT) {
            SLOAD(ls, (kt + 2) << 5);
        }
        CP_COMMIT();
        ls++; if (ls == 3) ls = 0;

        uint32_t aB = sb + (uint32_t)cs * 32768u;
        uint32_t bB = aB + 16384u;

        #pragma unroll
        for (int ks = 0; ks < 2; ks++) {
            int kb = ks << 5;
            uint32_t ah[2][4], al[2][4];
            #pragma unroll
            for (int mf = 0; mf < 2; mf++) {
                uint32_t off = SW64((uint32_t)((wm + (mf << 4) + aro) * 64 + kb + aco));
                ldsm_x4(aB + off,         ah[mf][0], ah[mf][1], ah[mf][2], ah[mf][3]);
                ldsm_x4(aB + 8192u + off, al[mf][0], al[mf][1], al[mf][2], al[mf][3]);
            }
            #pragma unroll
            for (int ng = 0; ng < 4; ng++) {
                uint32_t off = SW64((uint32_t)((wn + (ng << 4) + bro) * 64 + kb + bco));
                uint32_t bh0, bh1, bh2, bh3, bl0, bl1, bl2, bl3;
                ldsm_x4(bB + off,         bh0, bh1, bh2, bh3);
                ldsm_x4(bB + 8192u + off, bl0, bl1, bl2, bl3);
                #pragma unroll
                for (int mf = 0; mf < 2; mf++) {
                    float* c0 = acc[mf][(ng << 1)];
                    float* c1 = acc[mf][(ng << 1) + 1];
                    mma_bf16(c0, ah[mf], bh0, bh1);
                    mma_bf16(c1, ah[mf], bh2, bh3);
                    mma_bf16(c0, ah[mf], bl0, bl1);
                    mma_bf16(c1, ah[mf], bl2, bl3);
                    mma_bf16(c0, al[mf], bh0, bh1);
                    mma_bf16(c1, al[mf], bh2, bh3);
                }
            }
        }
        cs++; if (cs == 3) cs = 0;
    }

    #pragma unroll
    for (int mf = 0; mf < 2; mf++) {
        int row = m0 + wm + (mf << 4) + (lane >> 2);
        #pragma unroll
        for (int nf = 0; nf < 8; nf++) {
            int col = n0 + wn + (nf << 3) + ((lane & 3) << 1);
            float* a = acc[mf][nf];
            if (EPI == 1) {
                float* Cb = C + zo*soC + zi*siC;
                *(float2*)(Cb + (LL)row * ldc + col)       = make_float2(a[0], a[1]);
                *(float2*)(Cb + (LL)(row + 8) * ldc + col) = make_float2(a[2], a[3]);
            } else {
                bf16* Hb = Chi + zo*soC + zi*siC;
                bf16* Lb = Clo + zo*soC + zi*siC;
                uint32_t hp, lp;
                split2pack(a[0], a[1], hp, lp);
                *(uint32_t*)(Hb + (LL)row * ldc + col) = hp;
                *(uint32_t*)(Lb + (LL)row * ldc + col) = lp;
                split2pack(a[2], a[3], hp, lp);
                *(uint32_t*)(Hb + (LL)(row + 8) * ldc + col) = hp;
                *(uint32_t*)(Lb + (LL)(row + 8) * ldc + col) = lp;
            }
        }
    }
}

// ---------------- fat-kernel device bodies ----------------
__device__ __forceinline__
void split_rm_body(const float* __restrict__ x, bf16* __restrict__ hi,
                   bf16* __restrict__ lo, int blk)
{
    LL base = ((LL)blk * 256 + threadIdx.x) * 4;
    float4 v = *(const float4*)(x + base);
    bf16 h[4], l[4];
    splitw(v.x, h[0], l[0]); splitw(v.y, h[1], l[1]);
    splitw(v.z, h[2], l[2]); splitw(v.w, h[3], l[3]);
    *(uint2*)(hi + base) = *(uint2*)h;
    *(uint2*)(lo + base) = *(uint2*)l;
}

// 64-row x 32-col transpose-split tile with packed uint32 stores (full 128B/warp).
// x [R rows][ldx cols] fp32, tile at (r0=by*64, c0=bx*32) -> out[C][R] bf16 hi/lo.
__device__ __forceinline__
void split_tr64_body(const float* __restrict__ x, int ldx,
                     bf16* __restrict__ hi, bf16* __restrict__ lo,
                     int R, int bx, int by)
{
    __shared__ float s[64][33];
    int tid = threadIdx.x;
    int r0 = by * 64, c0 = bx * 32;
    #pragma unroll
    for (int i = 0; i < 8; i++) {
        int idx = tid + (i << 8);
        int row = idx >> 5, col = idx & 31;
        s[row][col] = x[(LL)(r0 + row) * ldx + c0 + col];
    }
    __syncthreads();
    #pragma unroll
    for (int i = 0; i < 4; i++) {
        int idx = tid + (i << 8);
        int n = idx >> 5, p = idx & 31;   // n: output row (col of x), p: pair of r
        float v0 = s[2*p][n], v1 = s[2*p + 1][n];
        uint32_t hp, lp;
        split2pack(v0, v1, hp, lp);
        LL o = (LL)(c0 + n) * R + r0 + 2*p;
        *(uint32_t*)(hi + o) = hp;
        *(uint32_t*)(lo + o) = lp;
    }
    __syncthreads();
}

__device__ __forceinline__
void zfill_body(bf16* __restrict__ p, int blk)
{
    LL i = ((LL)blk * 256 + threadIdx.x) * 2;
    *(uint32_t*)(p + i) = 0u;
}

__device__ __forceinline__
void biascat_body(const float* bqd, const float* bkv, const float* bkr,
                  const float* bqc, const float* bqr,
                  const float* bkc, const float* bvc,
                  float* b1, float* b2, float* b3, int blk)
{
    int i = blk * 256 + threadIdx.x;
    if (i < N1) {
        float v = 0.0f;
        if (i < 1536) v = bqd[i];
        else if (i < 2048) v = bkv[i - 1536];
        else if (i < 2112) v = bkr[i - 2048];
        b1[i] = v;
    }
    if (i < 2048) b2[i] = bqc[i]; else if (i < 3072) b2[i] = bqr[i - 2048];
    if (i < 2048) b3[i] = bkc[i]; else if (i < 4096) b3[i] = bvc[i - 2048];
}

// block counts (64-row split_tr tiles: r-tiles = rows/64, c-tiles = cols/32)
#define NB_RM   16384
#define NB_WQD  (48*32)   // 1536: Wqd [2048][1536]
#define NB_WKV  (16*32)   // 512
#define NB_WKR  (2*32)    // 64
#define NB_ZF   256
#define NB_BIAS 16
#define NB_WQC  (64*24)   // 1536: Wqc [1536][2048]
#define NB_WQR  (32*24)   // 768
#define NB_WKC  (64*8)    // 512: Wkc [512][2048]
#define NB_WVC  (64*8)    // 512
#define NB_WO   (64*32)   // 2048
#define PREP_TOTAL (NB_RM+NB_WQD+NB_WKV+NB_WKR+2*NB_ZF+NB_BIAS+NB_WQC+NB_WQR+NB_WKC+NB_WVC+NB_WO)

__global__ __launch_bounds__(256)
void prep_all(const float* h, const float* Wqd, const float* Wkv, const float* Wkr,
              const float* Wqc, const float* Wqr, const float* Wkc, const float* Wvc,
              const float* Wo,
              const float* bqd, const float* bkv, const float* bkr,
              const float* bqc, const float* bqr, const float* bkc, const float* bvc,
              bf16* h_hi, bf16* h_lo, bf16* WdT_hi, bf16* WdT_lo,
              bf16* WqcrT_hi, bf16* WqcrT_lo, bf16* WkvcT_hi, bf16* WkvcT_lo,
              bf16* WoT_hi, bf16* WoT_lo,
              float* b1, float* b2, float* b3)
{
    int b = blockIdx.x;
    if (b < NB_RM) { split_rm_body(h, h_hi, h_lo, b); return; }
    b -= NB_RM;
    if (b < NB_WQD) { split_tr64_body(Wqd, D_CQ, WdT_hi, WdT_lo, D_MODEL, b % 48, b / 48); return; }
    b -= NB_WQD;
    if (b < NB_WKV) {
        split_tr64_body(Wkv, D_C, WdT_hi + (LL)D_CQ*D_MODEL, WdT_lo + (LL)D_CQ*D_MODEL,
                        D_MODEL, b % 16, b / 16);
        return;
    }
    b -= NB_WKV;
    if (b < NB_WKR) {
        split_tr64_body(Wkr, D_R, WdT_hi + (LL)2048*D_MODEL, WdT_lo + (LL)2048*D_MODEL,
                        D_MODEL, b % 2, b / 2);
        return;
    }
    b -= NB_WKR;
    if (b < NB_ZF) { zfill_body(WdT_hi + (LL)2112*D_MODEL, b); return; }
    b -= NB_ZF;
    if (b < NB_ZF) { zfill_body(WdT_lo + (LL)2112*D_MODEL, b); return; }
    b -= NB_ZF;
    if (b < NB_BIAS) { biascat_body(bqd, bkv, bkr, bqc, bqr, bkc, bvc, b1, b2, b3, b); return; }
    b -= NB_BIAS;
    if (b < NB_WQC) { split_tr64_body(Wqc, 2048, WqcrT_hi, WqcrT_lo, D_CQ, b % 64, b / 64); return; }
    b -= NB_WQC;
    if (b < NB_WQR) {
        split_tr64_body(Wqr, 1024, WqcrT_hi + (LL)2048*D_CQ, WqcrT_lo + (LL)2048*D_CQ,
                        D_CQ, b % 32, b / 32);
        return;
    }
    b -= NB_WQR;
    if (b < NB_WKC) { split_tr64_body(Wkc, 2048, WkvcT_hi, WkvcT_lo, D_C, b % 64, b / 64); return; }
    b -= NB_WKC;
    if (b < NB_WVC) {
        split_tr64_body(Wvc, 2048, WkvcT_hi + (LL)2048*D_C, WkvcT_lo + (LL)2048*D_C,
                        D_C, b % 64, b / 64);
        return;
    }
    b -= NB_WVC;
    split_tr64_body(Wo, 2048, WoT_hi, WoT_lo, 2048, b % 64, b / 64);
}

// ---------------- fused rmsnorm over all three slices of tmp12 ----------------
__global__ __launch_bounds__(256)
void rmsnorm_all(const float* __restrict__ x,
                 const float* __restrict__ gq, const float* __restrict__ gkv,
                 const float* __restrict__ gkr,
                 bf16* __restrict__ cQh, bf16* __restrict__ cQl,
                 bf16* __restrict__ cKVh, bf16* __restrict__ cKVl,
                 float* __restrict__ krn)
{
    LL xb = (LL)blockIdx.x * N1;
    int tid = threadIdx.x;
    __shared__ float red[256];

    float s = 0.0f;
    #pragma unroll
    for (int i = 0; i < 6; i++) { float v = x[xb + tid + (i << 8)]; s += v * v; }
    red[tid] = s; __syncthreads();
    for (int st = 128; st > 0; st >>= 1) {
        if (tid < st) red[tid] += red[tid + st];
        __syncthreads();
    }
    float rs = rsqrtf(red[0] / (float)D_CQ + 1e-6f);
    LL yb = (LL)blockIdx.x * D_CQ;
    #pragma unroll
    for (int i = 0; i < 6; i++) {
        int idx = tid + (i << 8);
        float v = x[xb + idx] * rs * gq[idx];
        bf16 h, l; splitw(v, h, l);
        cQh[yb + idx] = h; cQl[yb + idx] = l;
    }
    __syncthreads();

    s = 0.0f;
    #pragma unroll
    for (int i = 0; i < 2; i++) { float v = x[xb + 1536 + tid + (i << 8)]; s += v * v; }
    red[tid] = s; __syncthreads();
    for (int st = 128; st > 0; st >>= 1) {
        if (tid < st) red[tid] += red[tid + st];
        __syncthreads();
    }
    rs = rsqrtf(red[0] / (float)D_C + 1e-6f);
    yb = (LL)blockIdx.x * D_C;
    #pragma unroll
    for (int i = 0; i < 2; i++) {
        int idx = tid + (i << 8);
        float v = x[xb + 1536 + idx] * rs * gkv[idx];
        bf16 h, l; splitw(v, h, l);
        cKVh[yb + idx] = h; cKVl[yb + idx] = l;
    }
    __syncthreads();

    float v3 = (tid < D_R) ? x[xb + 2048 + tid] : 0.0f;
    red[tid] = v3 * v3; __syncthreads();
    for (int st = 128; st > 0; st >>= 1) {
        if (tid < st) red[tid] += red[tid + st];
        __syncthreads();
    }
    rs = rsqrtf(red[0] / (float)D_R + 1e-6f);
    if (tid < D_R)
        krn[(LL)blockIdx.x * D_R + tid] = v3 * rs * gkr[tid];
}

// ---------------- kR broadcast body (RoPE on krn -> kf heads) ----------------
__device__ __forceinline__
void pack_kr_body(const float* __restrict__ krn, const float* __restrict__ freqs,
                  bf16* __restrict__ kfh, bf16* __restrict__ kfl, int bs)
{
    int s  = bs & (SEQ - 1);
    LL kfb = (LL)bs * 3072;
    int tid = threadIdx.x;

    __shared__ uint32_t krh[32], krl[32];
    if (tid < 32) {
        int i = tid;
        float a = krn[(LL)bs*D_R + 2*i];
        float b = krn[(LL)bs*D_R + 2*i + 1];
        float c  = freqs[(LL)s*D_R + 2*i];
        float sn = freqs[(LL)s*D_R + 2*i + 1];
        float r0 = a*c - b*sn;
        float r1 = a*sn + b*c;
        uint32_t hp, lp;
        split2pack(r0, r1, hp, lp);
        krh[i] = hp; krl[i] = lp;
    }
    __syncthreads();

    #pragma unroll
    for (int it = 0; it < 2; it++) {
        int idx = tid + (it << 8);
        int hh = idx >> 5, p = idx & 31;
        LL o = kfb + hh*D_QK + (p << 1);
        *(uint32_t*)(kfh + o) = krh[p];
        *(uint32_t*)(kfl + o) = krl[p];
    }
}

// post_all: vCT split (64 c-tiles x 128 r-tiles = 8192 blocks) + kR broadcast (8192)
#define NB_VCT (64*128)
__global__ __launch_bounds__(256)
void post_all(const float* vC, bf16* vCT_hi, bf16* vCT_lo,
              const float* krn, const float* freqs,
              bf16* kfh, bf16* kfl)
{
    int b = blockIdx.x;
    if (b < NB_VCT) {
        split_tr64_body(vC, 2048, vCT_hi, vCT_lo, NTOK, b % 64, b / 64);
        return;
    }
    b -= NB_VCT;
    pack_kr_body(krn, freqs, kfh, kfl, b);
}

// ---------------- causal softmax + bf16 split emission (k < kLim only) ----------------
__global__ __launch_bounds__(256)
void softmax_kernel(float* __restrict__ w, bf16* __restrict__ wh, bf16* __restrict__ wl)
{
    LL row = blockIdx.x;
    int q = (int)(row & (SEQ - 1));
    float* base = w + row * (LL)SEQ;
    bf16* bh = wh + row * (LL)SEQ;
    bf16* bl = wl + row * (LL)SEQ;
    int tid = threadIdx.x;

    float vals[8];
    float mx = -INFINITY;
    #pragma unroll
    for (int it = 0; it < 8; it++) {
        int k = tid + it * 256;
        float v = -INFINITY;
        if (k <= q) v = base[k];
        vals[it] = v;
        mx = fmaxf(mx, v);
    }
    __shared__ float red[256];
    red[tid] = mx; __syncthreads();
    for (int st = 128; st > 0; st >>= 1) {
        if (tid < st) red[tid] = fmaxf(red[tid], red[tid + st]);
        __syncthreads();
    }
    mx = red[0]; __syncthreads();

    float sum = 0.0f;
    #pragma unroll
    for (int it = 0; it < 8; it++) {
        float e = (vals[it] == -INFINITY) ? 0.0f : __expf(vals[it] - mx);
        vals[it] = e;
        sum += e;
    }
    red[tid] = sum; __syncthreads();
    for (int st = 128; st > 0; st >>= 1) {
        if (tid < st) red[tid] += red[tid + st];
        __syncthreads();
    }
    float inv = 1.0f / red[0];

    int kLim = ((q >> 7) + 1) << 7;
    #pragma unroll
    for (int it = 0; it < 8; it++) {
        int k = tid + it * 256;
        if (k < kLim) {
            float p = vals[it] * inv;
            base[k] = p;
            bf16 h, l; splitw(p, h, l);
            bh[k] = h; bl[k] = l;
        }
    }
}

// ---------------- host ----------------
#define SYMF(name) ({ void* p_; cudaGetSymbolAddress(&p_, name); (float*)p_; })
#define SYMB(name) ({ void* p_; cudaGetSymbolAddress(&p_, name); (bf16*)p_; })

#define G512_SMEM  196608
#define A128_SMEM  98304

extern "C" void kernel_launch(void* const* d_in, const int* in_sizes, int n_in,
                              void* d_out, int out_size)
{
    (void)in_sizes; (void)n_in; (void)out_size;
    const float* h       = (const float*)d_in[0];
    const float* freqs   = (const float*)d_in[1];
    const float* Wq_down = (const float*)d_in[3];
    const float* bq_down = (const float*)d_in[4];
    const float* gq_norm = (const float*)d_in[5];
    const float* Wqc     = (const float*)d_in[6];
    const float* bqc     = (const float*)d_in[7];
    const float* Wqr     = (const float*)d_in[8];
    const float* bqr     = (const float*)d_in[9];
    const float* Wkr     = (const float*)d_in[10];
    const float* bkr     = (const float*)d_in[11];
    const float* gkr     = (const float*)d_in[12];
    const float* Wkv     = (const float*)d_in[13];
    const float* bkv     = (const float*)d_in[14];
    const float* gkv     = (const float*)d_in[15];
    const float* Wkc     = (const float*)d_in[16];
    const float* bkc     = (const float*)d_in[17];
    const float* Wvc     = (const float*)d_in[18];
    const float* bvc     = (const float*)d_in[19];
    const float* Wo      = (const float*)d_in[20];
    const float* bo      = (const float*)d_in[21];

    float* out_h = (float*)d_out;
    float* w     = out_h + (LL)NTOK * D_MODEL;

    float* tmp12 = SYMF(g_tmp12);
    float* vC = SYMF(g_vC);
    float* krn = SYMF(g_krn);
    float* b1 = SYMF(g_bias1); float* b2 = SYMF(g_bias2); float* b3 = SYMF(g_bias3);

    bf16 *h_hi = SYMB(g_h_hi), *h_lo = SYMB(g_h_lo);
    bf16 *WdT_hi = SYMB(g_WdT_hi), *WdT_lo = SYMB(g_WdT_lo);
    bf16 *WqcrT_hi = SYMB(g_WqcrT_hi), *WqcrT_lo = SYMB(g_WqcrT_lo);
    bf16 *WkvcT_hi = SYMB(g_WkvcT_hi), *WkvcT_lo = SYMB(g_WkvcT_lo);
    bf16 *WoT_hi  = SYMB(g_WoT_hi),  *WoT_lo  = SYMB(g_WoT_lo);
    bf16 *cQ_hi = SYMB(g_cQ_hi), *cQ_lo = SYMB(g_cQ_lo);
    bf16 *cKV_hi = SYMB(g_cKV_hi), *cKV_lo = SYMB(g_cKV_lo);
    bf16 *qf_hi = SYMB(g_qf_hi), *qf_lo = SYMB(g_qf_lo);
    bf16 *kf_hi = SYMB(g_kf_hi), *kf_lo = SYMB(g_kf_lo);
    bf16 *vCT_hi = SYMB(g_vCT_hi), *vCT_lo = SYMB(g_vCT_lo);
    bf16 *w_hi = SYMB(g_w_hi), *w_lo = SYMB(g_w_lo);
    bf16 *attn_hi = SYMB(g_attn_hi), *attn_lo = SYMB(g_attn_lo);

    cudaFuncSetAttribute((const void*)gemm512f,   cudaFuncAttributeMaxDynamicSharedMemorySize, G512_SMEM);
    cudaFuncSetAttribute((const void*)gemm512qkv, cudaFuncAttributeMaxDynamicSharedMemorySize, G512_SMEM);
    cudaFuncSetAttribute((const void*)attn128<true,false,1>, cudaFuncAttributeMaxDynamicSharedMemorySize, A128_SMEM);
    cudaFuncSetAttribute((const void*)attn128<false,true,2>, cudaFuncAttributeMaxDynamicSharedMemorySize, A128_SMEM);

    // 1) all input-derived prep in ONE launch
    prep_all<<<PREP_TOTAL, 256>>>(
        h, Wq_down, Wkv, Wkr, Wqc, Wqr, Wkc, Wvc, Wo,
        bq_down, bkv, bkr, bqc, bqr, bkc, bvc,
        h_hi, h_lo, WdT_hi, WdT_lo, WqcrT_hi, WqcrT_lo, WkvcT_hi, WkvcT_lo,
        WoT_hi, WoT_lo, b1, b2, b3);

    // 2) merged first GEMM: tmp12 = h @ [Wq_down | Wkv | Wkr | 0] + bias
    gemm512f<<<dim3(N1/128, NTOK/256), 512, G512_SMEM>>>(
        h_hi, h_lo, WdT_hi, WdT_lo, b1, tmp12, D_MODEL, D_MODEL, D_MODEL, N1);

    // 3) fused norms
    rmsnorm_all<<<NTOK, 256>>>(tmp12, gq_norm, gkv, gkr,
                               cQ_hi, cQ_lo, cKV_hi, cKV_lo, krn);

    // 4) dual projection with fused pack epilogues
    gemm512qkv<<<dim3(3072/128 + 4096/128, NTOK/256), 512, G512_SMEM>>>(
        cQ_hi, cQ_lo, WqcrT_hi, WqcrT_lo, b2, qf_hi, qf_lo, 3072/128,
        cKV_hi, cKV_lo, WkvcT_hi, WkvcT_lo, b3, kf_hi, kf_lo, vC,
        freqs, 1.0f / sqrtf((float)D_QK));

    // 5) vCT split + kR broadcast in ONE launch
    post_all<<<NB_VCT + NTOK, 256>>>(vC, vCT_hi, vCT_lo, krn, freqs, kf_hi, kf_lo);

    // 6) scores = q k^T (causal; upper tiles zero-fill w)
    {
        LL soQK = (LL)SEQ * N_HEADS * D_QK, siQK = D_QK;
        LL soW  = (LL)N_HEADS * SEQ * SEQ,  siW  = (LL)SEQ * SEQ;
        attn128<true,false,1><<<dim3(SEQ/128, SEQ/128, BSZ*N_HEADS), 256, A128_SMEM>>>(
            qf_hi, qf_lo, kf_hi, kf_lo, w, nullptr, nullptr,
            D_QK, N_HEADS*D_QK, N_HEADS*D_QK, SEQ,
            soQK, siQK, soQK, siQK, soW, siW, N_HEADS);
    }

    // 7) softmax
    softmax_kernel<<<(LL)BSZ*N_HEADS*SEQ, 256>>>(w, w_hi, w_lo);

    // 8) PV (longest-K tiles first)
    {
        LL soW = (LL)N_HEADS * SEQ * SEQ, siW = (LL)SEQ * SEQ;
        LL soB = 2048;
        LL siB = (LL)D_H * NTOK;
        LL soC = (LL)SEQ * 2048, siC = D_H;
        attn128<false,true,2><<<dim3(D_H/128, SEQ/128, BSZ*N_HEADS), 256, A128_SMEM>>>(
            w_hi, w_lo, vCT_hi, vCT_lo, nullptr, attn_hi, attn_lo,
            SEQ, SEQ, NTOK, 2048,
            soW, siW, soB, siB, soC, siC, N_HEADS);
    }

    // 9) h_out = attn @ Wo + bo
    gemm512f<<<dim3(2048/128, NTOK/256), 512, G512_SMEM>>>(
        attn_hi, attn_lo, WoT_hi, WoT_lo, bo, out_h, 2048, 2048, 2048, 2048);
}